// round 1
// baseline (speedup 1.0000x reference)
#include <cuda_runtime.h>

#define Nn 50000
#define Ee 800000
#define Et 850000
#define FD 512
#define HD 64
#define NH 4
#define HC 256   // NH*HD

// ---------------- scratch (device globals; no allocation) ----------------
__device__ float    g_x  [Nn*HD];   // current node features
__device__ float    g_h  [Nn*HC];   // per-head transformed features
__device__ float    g_als[Nn*NH];   // attention logit (src part)
__device__ float    g_ald[Nn*NH];   // attention logit (dst part)
__device__ float    g_e  [Et*NH];   // per-edge logits -> exp values
__device__ unsigned g_m  [Nn*NH];   // segment max (order-preserving uint enc)
__device__ float    g_den[Nn*NH];   // segment sum of exp
__device__ float    g_out[Nn*HC];   // aggregated per-head output

// order-preserving float<->uint encoding for atomicMax
__device__ __forceinline__ unsigned fenc(float f){
    unsigned u = __float_as_uint(f);
    return (u & 0x80000000u) ? ~u : (u | 0x80000000u);
}
__device__ __forceinline__ float fdec(unsigned u){
    return (u & 0x80000000u) ? __uint_as_float(u & 0x7FFFFFFFu)
                             : __uint_as_float(~u);
}

// ---------------- zero per-layer state ----------------
__global__ void k_zero(){
    int i = blockIdx.x*blockDim.x + threadIdx.x;
    if (i < Nn*HC) g_out[i] = 0.f;
    if (i < Nn*NH){ g_m[i] = 0u; g_den[i] = 0.f; }
}

// ---------------- x = feat @ Wt + bt  (50000x512 @ 512x64) ----------------
// 64x64 tile per block, 256 threads, K chunks of 32.
__global__ __launch_bounds__(256) void k_lin1(const float* __restrict__ A,
                                              const float* __restrict__ W,
                                              const float* __restrict__ bt){
    __shared__ float Ast[32][68];   // [k][row] transposed, padded
    __shared__ float Bs [32][64];   // [k][col]
    int t  = threadIdx.x;
    int rb = blockIdx.x*64;
    int ty = t >> 4, tx = t & 15;
    int ar = t >> 2;        // 0..63 row
    int ac = (t & 3) * 8;   // 0,8,16,24 k-offset
    int br = t >> 3;        // 0..31 k
    int bc = (t & 7) * 8;   // col offset
    float c00=0,c01=0,c02=0,c03=0, c10=0,c11=0,c12=0,c13=0;
    float c20=0,c21=0,c22=0,c23=0, c30=0,c31=0,c32=0,c33=0;

    for (int kb = 0; kb < FD; kb += 32){
        float4 a0 = {0,0,0,0}, a1 = {0,0,0,0};
        if (rb + ar < Nn){
            a0 = *(const float4*)&A[(size_t)(rb+ar)*FD + kb + ac];
            a1 = *(const float4*)&A[(size_t)(rb+ar)*FD + kb + ac + 4];
        }
        float4 b0 = *(const float4*)&W[(size_t)(kb+br)*64 + bc];
        float4 b1 = *(const float4*)&W[(size_t)(kb+br)*64 + bc + 4];
        __syncthreads();
        Ast[ac+0][ar]=a0.x; Ast[ac+1][ar]=a0.y; Ast[ac+2][ar]=a0.z; Ast[ac+3][ar]=a0.w;
        Ast[ac+4][ar]=a1.x; Ast[ac+5][ar]=a1.y; Ast[ac+6][ar]=a1.z; Ast[ac+7][ar]=a1.w;
        *(float4*)&Bs[br][bc]   = b0;
        *(float4*)&Bs[br][bc+4] = b1;
        __syncthreads();
        #pragma unroll
        for (int k = 0; k < 32; k++){
            float4 av = *(const float4*)&Ast[k][ty*4];
            float4 bv = *(const float4*)&Bs[k][tx*4];
            c00 += av.x*bv.x; c01 += av.x*bv.y; c02 += av.x*bv.z; c03 += av.x*bv.w;
            c10 += av.y*bv.x; c11 += av.y*bv.y; c12 += av.y*bv.z; c13 += av.y*bv.w;
            c20 += av.z*bv.x; c21 += av.z*bv.y; c22 += av.z*bv.z; c23 += av.z*bv.w;
            c30 += av.w*bv.x; c31 += av.w*bv.y; c32 += av.w*bv.z; c33 += av.w*bv.w;
        }
    }
    float bt0 = bt[tx*4+0], bt1 = bt[tx*4+1], bt2 = bt[tx*4+2], bt3 = bt[tx*4+3];
    int r0 = rb + ty*4;
    float rows[4][4] = {{c00,c01,c02,c03},{c10,c11,c12,c13},
                        {c20,c21,c22,c23},{c30,c31,c32,c33}};
    #pragma unroll
    for (int i = 0; i < 4; i++){
        int r = r0 + i;
        if (r < Nn){
            float* o = &g_x[(size_t)r*HD + tx*4];
            o[0] = rows[i][0] + bt0; o[1] = rows[i][1] + bt1;
            o[2] = rows[i][2] + bt2; o[3] = rows[i][3] + bt3;
        }
    }
}

// ---------------- h = x @ Wg  (50000x64 @ 64x256) ----------------
// thread j owns column j of Wg in registers; 4 rows per iteration for ILP.
__global__ __launch_bounds__(256) void k_gemm_h(const float* __restrict__ W){
    int j = threadIdx.x;            // 0..255 (output column)
    float w[64];
    #pragma unroll
    for (int k = 0; k < 64; k++) w[k] = W[k*256 + j];
    __shared__ float xs[4][64];
    for (int rb = blockIdx.x*4; rb < Nn; rb += gridDim.x*4){
        int r = rb + (j >> 6);
        float xv = (r < Nn) ? g_x[(size_t)r*HD + (j & 63)] : 0.f;
        __syncthreads();
        xs[j>>6][j&63] = xv;
        __syncthreads();
        float a0=0,a1=0,a2=0,a3=0;
        #pragma unroll
        for (int k4 = 0; k4 < 16; k4++){
            float4 x0 = *(const float4*)&xs[0][k4*4];
            float4 x1 = *(const float4*)&xs[1][k4*4];
            float4 x2 = *(const float4*)&xs[2][k4*4];
            float4 x3 = *(const float4*)&xs[3][k4*4];
            float w0 = w[k4*4], w1 = w[k4*4+1], w2 = w[k4*4+2], w3 = w[k4*4+3];
            a0 += x0.x*w0 + x0.y*w1 + x0.z*w2 + x0.w*w3;
            a1 += x1.x*w0 + x1.y*w1 + x1.z*w2 + x1.w*w3;
            a2 += x2.x*w0 + x2.y*w1 + x2.z*w2 + x2.w*w3;
            a3 += x3.x*w0 + x3.y*w1 + x3.z*w2 + x3.w*w3;
        }
        if (rb+0 < Nn) g_h[(size_t)(rb+0)*HC + j] = a0;
        if (rb+1 < Nn) g_h[(size_t)(rb+1)*HC + j] = a1;
        if (rb+2 < Nn) g_h[(size_t)(rb+2)*HC + j] = a2;
        if (rb+3 < Nn) g_h[(size_t)(rb+3)*HC + j] = a3;
    }
}

// ---------------- per-node attention logits ----------------
// warp per node: al_s[n][h] = dot(h[n][h], a_src[h]); same for dst.
__global__ __launch_bounds__(256) void k_al(const float* __restrict__ as_,
                                            const float* __restrict__ ad_){
    int n    = (blockIdx.x*blockDim.x + threadIdx.x) >> 5;
    int lane = threadIdx.x & 31;
    if (n >= Nn) return;
    const float4* hp = (const float4*)&g_h[(size_t)n*HC + lane*8];
    float4 h0 = hp[0], h1 = hp[1];
    float4 s0 = ((const float4*)as_)[lane*2], s1 = ((const float4*)as_)[lane*2+1];
    float4 d0 = ((const float4*)ad_)[lane*2], d1 = ((const float4*)ad_)[lane*2+1];
    float ps = h0.x*s0.x + h0.y*s0.y + h0.z*s0.z + h0.w*s0.w
             + h1.x*s1.x + h1.y*s1.y + h1.z*s1.z + h1.w*s1.w;
    float pd = h0.x*d0.x + h0.y*d0.y + h0.z*d0.z + h0.w*d0.w
             + h1.x*d1.x + h1.y*d1.y + h1.z*d1.z + h1.w*d1.w;
    #pragma unroll
    for (int off = 4; off; off >>= 1){
        ps += __shfl_xor_sync(0xFFFFFFFFu, ps, off);
        pd += __shfl_xor_sync(0xFFFFFFFFu, pd, off);
    }
    if ((lane & 7) == 0){
        int hh = lane >> 3;
        g_als[n*NH + hh] = ps;
        g_ald[n*NH + hh] = pd;
    }
}

// ---------------- edge pass 1: logits + segment max ----------------
__global__ __launch_bounds__(256) void k_edge1(const int* __restrict__ ei){
    int eid = blockIdx.x*blockDim.x + threadIdx.x;
    if (eid >= Et) return;
    int s, d;
    if (eid < Ee){ s = ei[eid]; d = ei[Ee + eid]; } else { s = d = eid - Ee; }
    float4 a = ((const float4*)g_als)[s];
    float4 b = ((const float4*)g_ald)[d];
    float4 e;
    e.x = a.x + b.x; e.x = e.x > 0.f ? e.x : 0.2f*e.x;
    e.y = a.y + b.y; e.y = e.y > 0.f ? e.y : 0.2f*e.y;
    e.z = a.z + b.z; e.z = e.z > 0.f ? e.z : 0.2f*e.z;
    e.w = a.w + b.w; e.w = e.w > 0.f ? e.w : 0.2f*e.w;
    ((float4*)g_e)[eid] = e;
    unsigned* mp = &g_m[d*NH];
    atomicMax(mp+0, fenc(e.x)); atomicMax(mp+1, fenc(e.y));
    atomicMax(mp+2, fenc(e.z)); atomicMax(mp+3, fenc(e.w));
}

// ---------------- edge pass 2: exp + segment sum ----------------
__global__ __launch_bounds__(256) void k_edge2(const int* __restrict__ ei){
    int eid = blockIdx.x*blockDim.x + threadIdx.x;
    if (eid >= Et) return;
    int d;
    if (eid < Ee){ d = ei[Ee + eid]; } else { d = eid - Ee; }
    float4 e = ((const float4*)g_e)[eid];
    uint4  m = ((const uint4*)g_m)[d];
    float4 ex;
    ex.x = __expf(e.x - fdec(m.x));
    ex.y = __expf(e.y - fdec(m.y));
    ex.z = __expf(e.z - fdec(m.z));
    ex.w = __expf(e.w - fdec(m.w));
    ((float4*)g_e)[eid] = ex;
    float* dp = &g_den[d*NH];
    atomicAdd(dp+0, ex.x); atomicAdd(dp+1, ex.y);
    atomicAdd(dp+2, ex.z); atomicAdd(dp+3, ex.w);
}

// ---------------- edge pass 3: weighted aggregation ----------------
// warp per edge: out[dst][h][c] += h[src][h][c] * alpha[h]
__global__ __launch_bounds__(256) void k_edge3(const int* __restrict__ ei){
    int gtid = blockIdx.x*blockDim.x + threadIdx.x;
    int eid  = gtid >> 5;
    int lane = gtid & 31;
    if (eid >= Et) return;
    int s, d;
    if (eid < Ee){ s = ei[eid]; d = ei[Ee + eid]; } else { s = d = eid - Ee; }
    float4 ex = ((const float4*)g_e)[eid];
    float4 dn = ((const float4*)g_den)[d];
    float al[4] = { ex.x/dn.x, ex.y/dn.y, ex.z/dn.z, ex.w/dn.w };
    const float* hr = &g_h[(size_t)s*HC];
    float* orow = &g_out[(size_t)d*HC];
    #pragma unroll
    for (int i = 0; i < 8; i++){
        int c = lane + i*32;
        atomicAdd(&orow[c], hr[c] * al[i >> 1]);
    }
}

// ---------------- node post: head-mean + bias + LN + PReLU + residual ----------------
__global__ __launch_bounds__(256) void k_post(const float* __restrict__ bg,
                                              const float* __restrict__ gam,
                                              const float* __restrict__ bet,
                                              const float* __restrict__ pa){
    int n    = (blockIdx.x*blockDim.x + threadIdx.x) >> 5;
    int lane = threadIdx.x & 31;
    if (n >= Nn) return;
    const float* o = &g_out[(size_t)n*HC];
    int c0 = lane, c1 = lane + 32;
    float v0 = 0.25f*(o[c0] + o[c0+64] + o[c0+128] + o[c0+192]) + bg[c0];
    float v1 = 0.25f*(o[c1] + o[c1+64] + o[c1+128] + o[c1+192]) + bg[c1];
    float s = v0 + v1, q = v0*v0 + v1*v1;
    #pragma unroll
    for (int off = 16; off; off >>= 1){
        s += __shfl_xor_sync(0xFFFFFFFFu, s, off);
        q += __shfl_xor_sync(0xFFFFFFFFu, q, off);
    }
    float mu   = s * (1.f/64.f);
    float var  = q * (1.f/64.f) - mu*mu;
    float rstd = rsqrtf(var + 1e-5f);
    float a = pa[0];
    float xn0 = (v0 - mu)*rstd*gam[c0] + bet[c0];
    float xn1 = (v1 - mu)*rstd*gam[c1] + bet[c1];
    xn0 = xn0 > 0.f ? xn0 : a*xn0;
    xn1 = xn1 > 0.f ? xn1 : a*xn1;
    g_x[(size_t)n*HD + c0] += xn0;
    g_x[(size_t)n*HD + c1] += xn1;
}

// ---------------- final: z = x @ Wp + bp, L2-normalize rows ----------------
__global__ __launch_bounds__(256) void k_final(const float* __restrict__ Wp,
                                               const float* __restrict__ bp,
                                               float* __restrict__ out){
    __shared__ float Wps[64*64];
    __shared__ float xs[8][64];
    int t = threadIdx.x;
    for (int i = t; i < 4096; i += 256) Wps[i] = Wp[i];
    int nb = blockIdx.x*8;
    for (int i = t; i < 512; i += 256){
        int r = nb + (i >> 6);
        xs[i>>6][i&63] = (r < Nn) ? g_x[(size_t)r*HD + (i & 63)] : 0.f;
    }
    __syncthreads();
    int w = t >> 5, lane = t & 31;
    int n = nb + w;
    if (n >= Nn) return;
    int c0 = lane, c1 = lane + 32;
    float z0 = bp[c0], z1 = bp[c1];
    #pragma unroll
    for (int k = 0; k < 64; k++){
        float xv = xs[w][k];
        z0 += xv * Wps[k*64 + c0];
        z1 += xv * Wps[k*64 + c1];
    }
    float q = z0*z0 + z1*z1;
    #pragma unroll
    for (int off = 16; off; off >>= 1) q += __shfl_xor_sync(0xFFFFFFFFu, q, off);
    float inv = 1.f / fmaxf(sqrtf(q), 1e-12f);
    out[(size_t)n*HD + c0] = z0*inv;
    out[(size_t)n*HD + c1] = z1*inv;
}

// ---------------- launch ----------------
extern "C" void kernel_launch(void* const* d_in, const int* in_sizes, int n_in,
                              void* d_out, int out_size){
    const float* feat = (const float*)d_in[0];
    const int*   ei   = (const int*)  d_in[1];
    const float* Wt   = (const float*)d_in[2];
    const float* bt   = (const float*)d_in[3];
    const float* Wp   = (const float*)d_in[4];
    const float* bp   = (const float*)d_in[5];

    k_lin1<<<(Nn + 63)/64, 256>>>(feat, Wt, bt);

    for (int l = 0; l < 2; l++){
        const float* Wg  = (const float*)d_in[6 + l*7 + 0];
        const float* as_ = (const float*)d_in[6 + l*7 + 1];
        const float* ad_ = (const float*)d_in[6 + l*7 + 2];
        const float* bg  = (const float*)d_in[6 + l*7 + 3];
        const float* gam = (const float*)d_in[6 + l*7 + 4];
        const float* bet = (const float*)d_in[6 + l*7 + 5];
        const float* pa  = (const float*)d_in[6 + l*7 + 6];

        k_zero  <<<(Nn*HC + 255)/256, 256>>>();
        k_gemm_h<<<1184, 256>>>(Wg);
        k_al    <<<(Nn*32 + 255)/256, 256>>>(as_, ad_);
        k_edge1 <<<(Et + 255)/256, 256>>>(ei);
        k_edge2 <<<(Et + 255)/256, 256>>>(ei);
        k_edge3 <<<(Et*32 + 255)/256, 256>>>(ei);
        k_post  <<<(Nn*32 + 255)/256, 256>>>(bg, gam, bet, pa);
    }

    k_final<<<(Nn + 7)/8, 256>>>(Wp, bp, (float*)d_out);
}

// round 4
// speedup vs baseline: 1.7436x; 1.7436x over previous
#include <cuda_runtime.h>
#include <math_constants.h>

#define Nn 50000
#define Ee 800000
#define Et 850000
#define FD 512
#define HD 64
#define NH 4
#define HC 256   // NH*HD

// ---------------- scratch (device globals; no allocation) ----------------
__device__ float g_x  [Nn*HD];     // current node features
__device__ float g_h  [Nn*HC];     // per-head transformed features
__device__ float g_als[Nn*NH];     // attention logit (src part)
__device__ float g_ald[Nn*NH];     // attention logit (dst part)
__device__ int   g_deg   [Nn];
__device__ int   g_rowptr[Nn+1];
__device__ int   g_cursor[Nn];
__device__ int   g_csrc  [Et];     // CSR (by dst) source node list
__device__ float g_vs[HD*NH];      // Wg-folded a_src: [k][h]
__device__ float g_vd[HD*NH];      // Wg-folded a_dst: [k][h]

// ---------------- CSR build ----------------
__global__ void k_zerodeg(){
    int i = blockIdx.x*blockDim.x + threadIdx.x;
    if (i < Nn) g_deg[i] = 0;
}
__global__ void k_count(const int* __restrict__ ei){
    int eid = blockIdx.x*blockDim.x + threadIdx.x;
    if (eid >= Et) return;
    int d = (eid < Ee) ? ei[Ee + eid] : (eid - Ee);
    atomicAdd(&g_deg[d], 1);
}
__global__ void k_scan(){
    __shared__ int sh[1024];
    const int CH = (Nn + 1023) / 1024;   // 49
    int t = threadIdx.x;
    int base = t * CH;
    int s = 0;
    for (int i = 0; i < CH; i++){
        int idx = base + i;
        if (idx < Nn) s += g_deg[idx];
    }
    sh[t] = s; __syncthreads();
    for (int off = 1; off < 1024; off <<= 1){
        int v = (t >= off) ? sh[t-off] : 0;
        __syncthreads();
        sh[t] += v;
        __syncthreads();
    }
    int run = sh[t] - s;   // exclusive prefix
    for (int i = 0; i < CH; i++){
        int idx = base + i;
        if (idx < Nn){
            g_rowptr[idx] = run;
            g_cursor[idx] = run;
            run += g_deg[idx];
        }
    }
    if (t == 1023) g_rowptr[Nn] = Et;
}
__global__ void k_scatter(const int* __restrict__ ei){
    int eid = blockIdx.x*blockDim.x + threadIdx.x;
    if (eid >= Et) return;
    int s, d;
    if (eid < Ee){ s = ei[eid]; d = ei[Ee + eid]; } else { s = d = eid - Ee; }
    int pos = atomicAdd(&g_cursor[d], 1);
    g_csrc[pos] = s;
}

// ---------------- x = feat @ Wt + bt  (50000x512 @ 512x64) ----------------
__global__ __launch_bounds__(256) void k_lin1(const float* __restrict__ A,
                                              const float* __restrict__ W,
                                              const float* __restrict__ bt){
    __shared__ float Ast[32][68];
    __shared__ float Bs [32][64];
    int t  = threadIdx.x;
    int rb = blockIdx.x*64;
    int ty = t >> 4, tx = t & 15;
    int ar = t >> 2;
    int ac = (t & 3) * 8;
    int br = t >> 3;
    int bc = (t & 7) * 8;
    float c00=0,c01=0,c02=0,c03=0, c10=0,c11=0,c12=0,c13=0;
    float c20=0,c21=0,c22=0,c23=0, c30=0,c31=0,c32=0,c33=0;

    for (int kb = 0; kb < FD; kb += 32){
        float4 a0 = {0,0,0,0}, a1 = {0,0,0,0};
        if (rb + ar < Nn){
            a0 = *(const float4*)&A[(size_t)(rb+ar)*FD + kb + ac];
            a1 = *(const float4*)&A[(size_t)(rb+ar)*FD + kb + ac + 4];
        }
        float4 b0 = *(const float4*)&W[(size_t)(kb+br)*64 + bc];
        float4 b1 = *(const float4*)&W[(size_t)(kb+br)*64 + bc + 4];
        __syncthreads();
        Ast[ac+0][ar]=a0.x; Ast[ac+1][ar]=a0.y; Ast[ac+2][ar]=a0.z; Ast[ac+3][ar]=a0.w;
        Ast[ac+4][ar]=a1.x; Ast[ac+5][ar]=a1.y; Ast[ac+6][ar]=a1.z; Ast[ac+7][ar]=a1.w;
        *(float4*)&Bs[br][bc]   = b0;
        *(float4*)&Bs[br][bc+4] = b1;
        __syncthreads();
        #pragma unroll
        for (int k = 0; k < 32; k++){
            float4 av = *(const float4*)&Ast[k][ty*4];
            float4 bv = *(const float4*)&Bs[k][tx*4];
            c00 += av.x*bv.x; c01 += av.x*bv.y; c02 += av.x*bv.z; c03 += av.x*bv.w;
            c10 += av.y*bv.x; c11 += av.y*bv.y; c12 += av.y*bv.z; c13 += av.y*bv.w;
            c20 += av.z*bv.x; c21 += av.z*bv.y; c22 += av.z*bv.z; c23 += av.z*bv.w;
            c30 += av.w*bv.x; c31 += av.w*bv.y; c32 += av.w*bv.z; c33 += av.w*bv.w;
        }
    }
    float bt0 = bt[tx*4+0], bt1 = bt[tx*4+1], bt2 = bt[tx*4+2], bt3 = bt[tx*4+3];
    int r0 = rb + ty*4;
    float rows[4][4] = {{c00,c01,c02,c03},{c10,c11,c12,c13},
                        {c20,c21,c22,c23},{c30,c31,c32,c33}};
    #pragma unroll
    for (int i = 0; i < 4; i++){
        int r = r0 + i;
        if (r < Nn){
            float* o = &g_x[(size_t)r*HD + tx*4];
            o[0] = rows[i][0] + bt0; o[1] = rows[i][1] + bt1;
            o[2] = rows[i][2] + bt2; o[3] = rows[i][3] + bt3;
        }
    }
}

// ---------------- h = x @ Wg  (50000x64 @ 64x256) ----------------
__global__ __launch_bounds__(256) void k_gemm_h(const float* __restrict__ W){
    int j = threadIdx.x;
    float w[64];
    #pragma unroll
    for (int k = 0; k < 64; k++) w[k] = W[k*256 + j];
    __shared__ float xs[4][64];
    for (int rb = blockIdx.x*4; rb < Nn; rb += gridDim.x*4){
        int r = rb + (j >> 6);
        float xv = (r < Nn) ? g_x[(size_t)r*HD + (j & 63)] : 0.f;
        __syncthreads();
        xs[j>>6][j&63] = xv;
        __syncthreads();
        float a0=0,a1=0,a2=0,a3=0;
        #pragma unroll
        for (int k4 = 0; k4 < 16; k4++){
            float4 x0 = *(const float4*)&xs[0][k4*4];
            float4 x1 = *(const float4*)&xs[1][k4*4];
            float4 x2 = *(const float4*)&xs[2][k4*4];
            float4 x3 = *(const float4*)&xs[3][k4*4];
            float w0 = w[k4*4], w1 = w[k4*4+1], w2 = w[k4*4+2], w3 = w[k4*4+3];
            a0 += x0.x*w0 + x0.y*w1 + x0.z*w2 + x0.w*w3;
            a1 += x1.x*w0 + x1.y*w1 + x1.z*w2 + x1.w*w3;
            a2 += x2.x*w0 + x2.y*w1 + x2.z*w2 + x2.w*w3;
            a3 += x3.x*w0 + x3.y*w1 + x3.z*w2 + x3.w*w3;
        }
        if (rb+0 < Nn) g_h[(size_t)(rb+0)*HC + j] = a0;
        if (rb+1 < Nn) g_h[(size_t)(rb+1)*HC + j] = a1;
        if (rb+2 < Nn) g_h[(size_t)(rb+2)*HC + j] = a2;
        if (rb+3 < Nn) g_h[(size_t)(rb+3)*HC + j] = a3;
    }
}

// ---------------- fold attention vectors through Wg ----------------
// vs[k][h] = sum_c Wg[k, h*64+c] * a_src[h,c]
__global__ void k_vsvd(const float* __restrict__ Wg,
                       const float* __restrict__ as_,
                       const float* __restrict__ ad_){
    int t = threadIdx.x;           // 256 threads
    int k = t >> 2, h = t & 3;
    float ss = 0.f, sd = 0.f;
    const float* wrow = &Wg[k*HC + h*HD];
    const float* av   = &as_[h*HD];
    const float* bv   = &ad_[h*HD];
    #pragma unroll 16
    for (int c = 0; c < HD; c++){
        float w = wrow[c];
        ss += w * av[c];
        sd += w * bv[c];
    }
    g_vs[k*NH + h] = ss;
    g_vd[k*NH + h] = sd;
}

// ---------------- als/ald = x @ Vs / x @ Vd ----------------
__global__ __launch_bounds__(256) void k_als(){
    int n    = (blockIdx.x*blockDim.x + threadIdx.x) >> 5;
    int lane = threadIdx.x & 31;
    if (n >= Nn) return;
    float x0 = g_x[(size_t)n*HD + lane];
    float x1 = g_x[(size_t)n*HD + lane + 32];
    float4 v0 = ((const float4*)g_vs)[lane];
    float4 v1 = ((const float4*)g_vs)[lane+32];
    float4 d0 = ((const float4*)g_vd)[lane];
    float4 d1 = ((const float4*)g_vd)[lane+32];
    float s[4], d[4];
    s[0] = x0*v0.x + x1*v1.x; s[1] = x0*v0.y + x1*v1.y;
    s[2] = x0*v0.z + x1*v1.z; s[3] = x0*v0.w + x1*v1.w;
    d[0] = x0*d0.x + x1*d1.x; d[1] = x0*d0.y + x1*d1.y;
    d[2] = x0*d0.z + x1*d1.z; d[3] = x0*d0.w + x1*d1.w;
    #pragma unroll
    for (int off = 16; off; off >>= 1){
        #pragma unroll
        for (int h = 0; h < 4; h++){
            s[h] += __shfl_xor_sync(0xFFFFFFFFu, s[h], off);
            d[h] += __shfl_xor_sync(0xFFFFFFFFu, d[h], off);
        }
    }
    if (lane == 0){
        ((float4*)g_als)[n] = make_float4(s[0], s[1], s[2], s[3]);
        ((float4*)g_ald)[n] = make_float4(d[0], d[1], d[2], d[3]);
    }
}

__device__ __forceinline__ float lrelu(float v){ return v > 0.f ? v : 0.2f*v; }

// ---------------- fused GAT: softmax + aggregate + mean + LN + PReLU + residual ----------------
// warp per dst node; CSR in-edges; no atomics.
__global__ __launch_bounds__(256) void k_gat(const float* __restrict__ bg,
                                             const float* __restrict__ gam,
                                             const float* __restrict__ bet,
                                             const float* __restrict__ pa){
    int n    = (blockIdx.x*blockDim.x + threadIdx.x) >> 5;
    int lane = threadIdx.x & 31;
    if (n >= Nn) return;
    int beg = g_rowptr[n], end = g_rowptr[n+1];
    float4 ald = ((const float4*)g_ald)[n];

    // pass 1: per-head max over in-edges
    float m0 = -CUDART_INF_F, m1 = m0, m2 = m0, m3 = m0;
    for (int j = beg + lane; j < end; j += 32){
        int s = g_csrc[j];
        float4 a = ((const float4*)g_als)[s];
        m0 = fmaxf(m0, lrelu(a.x + ald.x));
        m1 = fmaxf(m1, lrelu(a.y + ald.y));
        m2 = fmaxf(m2, lrelu(a.z + ald.z));
        m3 = fmaxf(m3, lrelu(a.w + ald.w));
    }
    #pragma unroll
    for (int off = 16; off; off >>= 1){
        m0 = fmaxf(m0, __shfl_xor_sync(0xFFFFFFFFu, m0, off));
        m1 = fmaxf(m1, __shfl_xor_sync(0xFFFFFFFFu, m1, off));
        m2 = fmaxf(m2, __shfl_xor_sync(0xFFFFFFFFu, m2, off));
        m3 = fmaxf(m3, __shfl_xor_sync(0xFFFFFFFFu, m3, off));
    }

    // pass 2: exp + denom + weighted aggregation (lane owns channels lane*8..lane*8+7, head = lane>>3)
    float acc[8] = {0,0,0,0,0,0,0,0};
    float dn0 = 0.f, dn1 = 0.f, dn2 = 0.f, dn3 = 0.f;
    int myh = lane >> 3;
    for (int base = beg; base < end; base += 32){
        int j = base + lane;
        int msrc = 0;
        float4 ex = {0,0,0,0};
        if (j < end){
            msrc = g_csrc[j];
            float4 a = ((const float4*)g_als)[msrc];
            ex.x = __expf(lrelu(a.x + ald.x) - m0);
            ex.y = __expf(lrelu(a.y + ald.y) - m1);
            ex.z = __expf(lrelu(a.z + ald.z) - m2);
            ex.w = __expf(lrelu(a.w + ald.w) - m3);
        }
        dn0 += ex.x; dn1 += ex.y; dn2 += ex.z; dn3 += ex.w;
        int cnt = min(32, end - base);
        for (int t = 0; t < cnt; t++){
            int src = __shfl_sync(0xFFFFFFFFu, msrc, t);
            float e0 = __shfl_sync(0xFFFFFFFFu, ex.x, t);
            float e1 = __shfl_sync(0xFFFFFFFFu, ex.y, t);
            float e2 = __shfl_sync(0xFFFFFFFFu, ex.z, t);
            float e3 = __shfl_sync(0xFFFFFFFFu, ex.w, t);
            float exv = (myh < 2) ? (myh == 0 ? e0 : e1) : (myh == 2 ? e2 : e3);
            const float4* hr = (const float4*)&g_h[(size_t)src*HC + lane*8];
            float4 h0 = hr[0], h1 = hr[1];
            acc[0] += exv*h0.x; acc[1] += exv*h0.y; acc[2] += exv*h0.z; acc[3] += exv*h0.w;
            acc[4] += exv*h1.x; acc[5] += exv*h1.y; acc[6] += exv*h1.z; acc[7] += exv*h1.w;
        }
    }
    // reduce denom across warp
    #pragma unroll
    for (int off = 16; off; off >>= 1){
        dn0 += __shfl_xor_sync(0xFFFFFFFFu, dn0, off);
        dn1 += __shfl_xor_sync(0xFFFFFFFFu, dn1, off);
        dn2 += __shfl_xor_sync(0xFFFFFFFFu, dn2, off);
        dn3 += __shfl_xor_sync(0xFFFFFFFFu, dn3, off);
    }
    float mydn = (myh < 2) ? (myh == 0 ? dn0 : dn1) : (myh == 2 ? dn2 : dn3);
    float inv = 1.f / mydn;
    #pragma unroll
    for (int i = 0; i < 8; i++) acc[i] *= inv;
    // cross-head mean: lanes {l, l^8, l^16, l^24} hold same channel-in-head for heads 0..3
    #pragma unroll
    for (int i = 0; i < 8; i++){
        acc[i] += __shfl_xor_sync(0xFFFFFFFFu, acc[i], 8);
        acc[i] += __shfl_xor_sync(0xFFFFFFFFu, acc[i], 16);
        acc[i] *= 0.25f;
    }
    int cih = (lane & 7) * 8;   // channel-in-head base, replicated x4 across head groups
    float4 b0 = *(const float4*)&bg[cih];
    float4 b1 = *(const float4*)&bg[cih+4];
    float v[8];
    v[0]=acc[0]+b0.x; v[1]=acc[1]+b0.y; v[2]=acc[2]+b0.z; v[3]=acc[3]+b0.w;
    v[4]=acc[4]+b1.x; v[5]=acc[5]+b1.y; v[6]=acc[6]+b1.z; v[7]=acc[7]+b1.w;
    float s = 0.f, q = 0.f;
    #pragma unroll
    for (int i = 0; i < 8; i++){ s += v[i]; q += v[i]*v[i]; }
    #pragma unroll
    for (int off = 4; off; off >>= 1){
        s += __shfl_xor_sync(0xFFFFFFFFu, s, off);
        q += __shfl_xor_sync(0xFFFFFFFFu, q, off);
    }
    float mu   = s * (1.f/64.f);
    float var  = q * (1.f/64.f) - mu*mu;
    float rstd = rsqrtf(var + 1e-5f);
    float aw = pa[0];
    if (lane < 8){
        float4 g0 = *(const float4*)&gam[cih],   g1 = *(const float4*)&gam[cih+4];
        float4 t0 = *(const float4*)&bet[cih],   t1 = *(const float4*)&bet[cih+4];
        float* xp = &g_x[(size_t)n*HD + cih];
        float4 x0 = *(const float4*)xp, x1 = *(const float4*)(xp+4);
        float xn;
        xn = (v[0]-mu)*rstd*g0.x + t0.x; x0.x += (xn>0.f? xn : aw*xn);
        xn = (v[1]-mu)*rstd*g0.y + t0.y; x0.y += (xn>0.f? xn : aw*xn);
        xn = (v[2]-mu)*rstd*g0.z + t0.z; x0.z += (xn>0.f? xn : aw*xn);
        xn = (v[3]-mu)*rstd*g0.w + t0.w; x0.w += (xn>0.f? xn : aw*xn);
        xn = (v[4]-mu)*rstd*g1.x + t1.x; x1.x += (xn>0.f? xn : aw*xn);
        xn = (v[5]-mu)*rstd*g1.y + t1.y; x1.y += (xn>0.f? xn : aw*xn);
        xn = (v[6]-mu)*rstd*g1.z + t1.z; x1.z += (xn>0.f? xn : aw*xn);
        xn = (v[7]-mu)*rstd*g1.w + t1.w; x1.w += (xn>0.f? xn : aw*xn);
        *(float4*)xp     = x0;
        *(float4*)(xp+4) = x1;
    }
}

// ---------------- final: z = x @ Wp + bp, L2-normalize rows ----------------
__global__ __launch_bounds__(256) void k_final(const float* __restrict__ Wp,
                                               const float* __restrict__ bp,
                                               float* __restrict__ out){
    __shared__ float Wps[64*64];
    __shared__ float xs[8][64];
    int t = threadIdx.x;
    for (int i = t; i < 4096; i += 256) Wps[i] = Wp[i];
    int nb = blockIdx.x*8;
    for (int i = t; i < 512; i += 256){
        int r = nb + (i >> 6);
        xs[i>>6][i&63] = (r < Nn) ? g_x[(size_t)r*HD + (i & 63)] : 0.f;
    }
    __syncthreads();
    int w = t >> 5, lane = t & 31;
    int n = nb + w;
    if (n >= Nn) return;
    int c0 = lane, c1 = lane + 32;
    float z0 = bp[c0], z1 = bp[c1];
    #pragma unroll
    for (int k = 0; k < 64; k++){
        float xv = xs[w][k];
        z0 += xv * Wps[k*64 + c0];
        z1 += xv * Wps[k*64 + c1];
    }
    float q = z0*z0 + z1*z1;
    #pragma unroll
    for (int off = 16; off; off >>= 1) q += __shfl_xor_sync(0xFFFFFFFFu, q, off);
    float inv = 1.f / fmaxf(sqrtf(q), 1e-12f);
    out[(size_t)n*HD + c0] = z0*inv;
    out[(size_t)n*HD + c1] = z1*inv;
}

// ---------------- launch ----------------
extern "C" void kernel_launch(void* const* d_in, const int* in_sizes, int n_in,
                              void* d_out, int out_size){
    const float* feat = (const float*)d_in[0];
    const int*   ei   = (const int*)  d_in[1];
    const float* Wt   = (const float*)d_in[2];
    const float* bt   = (const float*)d_in[3];
    const float* Wp   = (const float*)d_in[4];
    const float* bp   = (const float*)d_in[5];

    k_lin1<<<(Nn + 63)/64, 256>>>(feat, Wt, bt);

    // CSR build (shared by both layers)
    k_zerodeg<<<(Nn + 255)/256, 256>>>();
    k_count  <<<(Et + 255)/256, 256>>>(ei);
    k_scan   <<<1, 1024>>>();
    k_scatter<<<(Et + 255)/256, 256>>>(ei);

    for (int l = 0; l < 2; l++){
        const float* Wg  = (const float*)d_in[6 + l*7 + 0];
        const float* as_ = (const float*)d_in[6 + l*7 + 1];
        const float* ad_ = (const float*)d_in[6 + l*7 + 2];
        const float* bg  = (const float*)d_in[6 + l*7 + 3];
        const float* gam = (const float*)d_in[6 + l*7 + 4];
        const float* bet = (const float*)d_in[6 + l*7 + 5];
        const float* pa  = (const float*)d_in[6 + l*7 + 6];

        k_gemm_h<<<1184, 256>>>(Wg);
        k_vsvd  <<<1, 256>>>(Wg, as_, ad_);
        k_als   <<<(Nn*32 + 255)/256, 256>>>();
        k_gat   <<<(Nn*32 + 255)/256, 256>>>(bg, gam, bet, pa);
    }

    k_final<<<(Nn + 7)/8, 256>>>(Wp, bp, (float*)d_out);
}

// round 5
// speedup vs baseline: 1.8980x; 1.0885x over previous
#include <cuda_runtime.h>
#include <math_constants.h>

#define Nn 50000
#define Ee 800000
#define Et 850000
#define FD 512
#define HD 64
#define NH 4
#define HC 256   // NH*HD

typedef unsigned long long ull;

// ---------------- scratch (device globals; no allocation) ----------------
__device__ float g_x  [Nn*HD];     // current node features
__device__ float g_h  [Nn*HC];     // per-head transformed features
__device__ float g_als[Nn*NH];     // attention logit (src part)
__device__ float g_ald[Nn*NH];     // attention logit (dst part)
__device__ int   g_deg   [Nn];
__device__ int   g_rowptr[Nn+1];
__device__ int   g_cursor[Nn];
__device__ int   g_csrc  [Et];     // CSR (by dst) source node list
__device__ float g_vs[HD*NH];      // Wg-folded a_src: [k][h]
__device__ float g_vd[HD*NH];      // Wg-folded a_dst: [k][h]
__device__ int   g_bsum[64];
__device__ int   g_boff[64];

// ---------------- packed f32x2 helpers ----------------
__device__ __forceinline__ void fma2(ull& d, ull a, ull b){
    asm("fma.rn.f32x2 %0, %1, %2, %0;" : "+l"(d) : "l"(a), "l"(b));
}
__device__ __forceinline__ ull pack2(float lo, float hi){
    ull r; asm("mov.b64 %0, {%1, %2};" : "=l"(r) : "f"(lo), "f"(hi)); return r;
}
__device__ __forceinline__ void unpack2(ull v, float& lo, float& hi){
    asm("mov.b64 {%0, %1}, %2;" : "=f"(lo), "=f"(hi) : "l"(v));
}

// ---------------- CSR build ----------------
__global__ void k_zerodeg(){
    int i = blockIdx.x*blockDim.x + threadIdx.x;
    if (i < Nn) g_deg[i] = 0;
}
__global__ void k_count(const int* __restrict__ ei){
    int eid = blockIdx.x*blockDim.x + threadIdx.x;
    if (eid >= Et) return;
    int d = (eid < Ee) ? ei[Ee + eid] : (eid - Ee);
    atomicAdd(&g_deg[d], 1);
}
// phase A: per-block local exclusive scan + block sums
__global__ __launch_bounds__(1024) void k_scanA(){
    __shared__ int sh[1024];
    int t   = threadIdx.x;
    int gid = blockIdx.x*1024 + t;
    int v = (gid < Nn) ? g_deg[gid] : 0;
    sh[t] = v; __syncthreads();
    #pragma unroll
    for (int off = 1; off < 1024; off <<= 1){
        int u = (t >= off) ? sh[t-off] : 0;
        __syncthreads();
        sh[t] += u;
        __syncthreads();
    }
    if (gid < Nn) g_rowptr[gid] = sh[t] - v;   // local exclusive
    if (t == 1023) g_bsum[blockIdx.x] = sh[1023];
}
// phase B: scan 49 block sums (one warp, serial in smem)
__global__ void k_scanB(){
    __shared__ int sh[64];
    int t = threadIdx.x;
    sh[t] = (t < 49) ? g_bsum[t] : 0;
    __syncthreads();
    if (t == 0){
        int run = 0;
        for (int i = 0; i < 49; i++){
            g_boff[i] = run;
            run += sh[i];
        }
    }
}
// phase C: add block offsets
__global__ __launch_bounds__(1024) void k_scanC(){
    int gid = blockIdx.x*1024 + threadIdx.x;
    if (gid < Nn){
        int r = g_rowptr[gid] + g_boff[blockIdx.x];
        g_rowptr[gid] = r;
        g_cursor[gid] = r;
    }
    if (gid == 0) g_rowptr[Nn] = Et;
}
__global__ void k_scatter(const int* __restrict__ ei){
    int eid = blockIdx.x*blockDim.x + threadIdx.x;
    if (eid >= Et) return;
    int s, d;
    if (eid < Ee){ s = ei[eid]; d = ei[Ee + eid]; } else { s = d = eid - Ee; }
    int pos = atomicAdd(&g_cursor[d], 1);
    g_csrc[pos] = s;
}

// ---------------- x = feat @ Wt + bt  (50000x512 @ 512x64), f32x2 ----------------
__global__ __launch_bounds__(256) void k_lin1(const float* __restrict__ A,
                                              const float* __restrict__ W,
                                              const float* __restrict__ bt){
    __shared__ __align__(16) float Ast[32][68];
    __shared__ __align__(16) float Bs [32][64];
    int t  = threadIdx.x;
    int rb = blockIdx.x*64;
    int ty = t >> 4, tx = t & 15;
    int ar = t >> 2;
    int ac = (t & 3) * 8;
    int br = t >> 3;
    int bc = (t & 7) * 8;
    ull c2[4][2] = {{0,0},{0,0},{0,0},{0,0}};   // [row][col-pair]

    for (int kb = 0; kb < FD; kb += 32){
        float4 a0 = {0,0,0,0}, a1 = {0,0,0,0};
        if (rb + ar < Nn){
            a0 = *(const float4*)&A[(size_t)(rb+ar)*FD + kb + ac];
            a1 = *(const float4*)&A[(size_t)(rb+ar)*FD + kb + ac + 4];
        }
        float4 b0 = *(const float4*)&W[(size_t)(kb+br)*64 + bc];
        float4 b1 = *(const float4*)&W[(size_t)(kb+br)*64 + bc + 4];
        __syncthreads();
        Ast[ac+0][ar]=a0.x; Ast[ac+1][ar]=a0.y; Ast[ac+2][ar]=a0.z; Ast[ac+3][ar]=a0.w;
        Ast[ac+4][ar]=a1.x; Ast[ac+5][ar]=a1.y; Ast[ac+6][ar]=a1.z; Ast[ac+7][ar]=a1.w;
        *(float4*)&Bs[br][bc]   = b0;
        *(float4*)&Bs[br][bc+4] = b1;
        __syncthreads();
        #pragma unroll
        for (int k = 0; k < 32; k++){
            float4 av = *(const float4*)&Ast[k][ty*4];
            ulonglong2 bv = *(const ulonglong2*)&Bs[k][tx*4];
            ull ax = pack2(av.x, av.x);
            ull ay = pack2(av.y, av.y);
            ull az = pack2(av.z, av.z);
            ull aw = pack2(av.w, av.w);
            fma2(c2[0][0], ax, bv.x); fma2(c2[0][1], ax, bv.y);
            fma2(c2[1][0], ay, bv.x); fma2(c2[1][1], ay, bv.y);
            fma2(c2[2][0], az, bv.x); fma2(c2[2][1], az, bv.y);
            fma2(c2[3][0], aw, bv.x); fma2(c2[3][1], aw, bv.y);
        }
    }
    float bt0 = bt[tx*4+0], bt1 = bt[tx*4+1], bt2 = bt[tx*4+2], bt3 = bt[tx*4+3];
    int r0 = rb + ty*4;
    #pragma unroll
    for (int i = 0; i < 4; i++){
        int r = r0 + i;
        if (r < Nn){
            float v0,v1,v2,v3;
            unpack2(c2[i][0], v0, v1);
            unpack2(c2[i][1], v2, v3);
            float* o = &g_x[(size_t)r*HD + tx*4];
            o[0] = v0 + bt0; o[1] = v1 + bt1;
            o[2] = v2 + bt2; o[3] = v3 + bt3;
        }
    }
}

// ---------------- h = x @ Wg  (50000x64 @ 64x256), f32x2 pair-over-K ----------------
__global__ __launch_bounds__(256) void k_gemm_h(const float* __restrict__ W){
    int j = threadIdx.x;
    ull w2[32];
    #pragma unroll
    for (int k2 = 0; k2 < 32; k2++)
        w2[k2] = pack2(W[(2*k2)*256 + j], W[(2*k2+1)*256 + j]);
    __shared__ __align__(16) float xs[4][64];
    for (int rb = blockIdx.x*4; rb < Nn; rb += gridDim.x*4){
        int r = rb + (j >> 6);
        float xv = (r < Nn) ? g_x[(size_t)r*HD + (j & 63)] : 0.f;
        __syncthreads();
        xs[j>>6][j&63] = xv;
        __syncthreads();
        ull a2[4] = {0,0,0,0};
        #pragma unroll
        for (int k4 = 0; k4 < 16; k4++){
            ulonglong2 x0 = *(const ulonglong2*)&xs[0][k4*4];
            ulonglong2 x1 = *(const ulonglong2*)&xs[1][k4*4];
            ulonglong2 x2 = *(const ulonglong2*)&xs[2][k4*4];
            ulonglong2 x3 = *(const ulonglong2*)&xs[3][k4*4];
            fma2(a2[0], x0.x, w2[k4*2]); fma2(a2[0], x0.y, w2[k4*2+1]);
            fma2(a2[1], x1.x, w2[k4*2]); fma2(a2[1], x1.y, w2[k4*2+1]);
            fma2(a2[2], x2.x, w2[k4*2]); fma2(a2[2], x2.y, w2[k4*2+1]);
            fma2(a2[3], x3.x, w2[k4*2]); fma2(a2[3], x3.y, w2[k4*2+1]);
        }
        #pragma unroll
        for (int i = 0; i < 4; i++){
            if (rb+i < Nn){
                float lo, hi; unpack2(a2[i], lo, hi);
                g_h[(size_t)(rb+i)*HC + j] = lo + hi;
            }
        }
    }
}

// ---------------- fold attention vectors through Wg ----------------
__global__ void k_vsvd(const float* __restrict__ Wg,
                       const float* __restrict__ as_,
                       const float* __restrict__ ad_){
    int t = threadIdx.x;           // 256 threads
    int k = t >> 2, h = t & 3;
    float ss = 0.f, sd = 0.f;
    const float* wrow = &Wg[k*HC + h*HD];
    const float* av   = &as_[h*HD];
    const float* bv   = &ad_[h*HD];
    #pragma unroll 16
    for (int c = 0; c < HD; c++){
        float w = wrow[c];
        ss += w * av[c];
        sd += w * bv[c];
    }
    g_vs[k*NH + h] = ss;
    g_vd[k*NH + h] = sd;
}

// ---------------- als/ald = x @ Vs / x @ Vd ----------------
__global__ __launch_bounds__(256) void k_als(){
    int n    = (blockIdx.x*blockDim.x + threadIdx.x) >> 5;
    int lane = threadIdx.x & 31;
    if (n >= Nn) return;
    float x0 = g_x[(size_t)n*HD + lane];
    float x1 = g_x[(size_t)n*HD + lane + 32];
    float4 v0 = ((const float4*)g_vs)[lane];
    float4 v1 = ((const float4*)g_vs)[lane+32];
    float4 d0 = ((const float4*)g_vd)[lane];
    float4 d1 = ((const float4*)g_vd)[lane+32];
    float s[4], d[4];
    s[0] = x0*v0.x + x1*v1.x; s[1] = x0*v0.y + x1*v1.y;
    s[2] = x0*v0.z + x1*v1.z; s[3] = x0*v0.w + x1*v1.w;
    d[0] = x0*d0.x + x1*d1.x; d[1] = x0*d0.y + x1*d1.y;
    d[2] = x0*d0.z + x1*d1.z; d[3] = x0*d0.w + x1*d1.w;
    #pragma unroll
    for (int off = 16; off; off >>= 1){
        #pragma unroll
        for (int h = 0; h < 4; h++){
            s[h] += __shfl_xor_sync(0xFFFFFFFFu, s[h], off);
            d[h] += __shfl_xor_sync(0xFFFFFFFFu, d[h], off);
        }
    }
    if (lane == 0){
        ((float4*)g_als)[n] = make_float4(s[0], s[1], s[2], s[3]);
        ((float4*)g_ald)[n] = make_float4(d[0], d[1], d[2], d[3]);
    }
}

__device__ __forceinline__ float lrelu(float v){ return v > 0.f ? v : 0.2f*v; }

// ---------------- fused GAT: softmax + aggregate + mean + LN + PReLU + residual ----------------
__global__ __launch_bounds__(256) void k_gat(const float* __restrict__ bg,
                                             const float* __restrict__ gam,
                                             const float* __restrict__ bet,
                                             const float* __restrict__ pa){
    int n    = (blockIdx.x*blockDim.x + threadIdx.x) >> 5;
    int lane = threadIdx.x & 31;
    if (n >= Nn) return;
    int beg = g_rowptr[n], end = g_rowptr[n+1];
    float4 ald = ((const float4*)g_ald)[n];

    // pass 1: per-head max over in-edges
    float m0 = -CUDART_INF_F, m1 = m0, m2 = m0, m3 = m0;
    for (int j = beg + lane; j < end; j += 32){
        int s = g_csrc[j];
        float4 a = ((const float4*)g_als)[s];
        m0 = fmaxf(m0, lrelu(a.x + ald.x));
        m1 = fmaxf(m1, lrelu(a.y + ald.y));
        m2 = fmaxf(m2, lrelu(a.z + ald.z));
        m3 = fmaxf(m3, lrelu(a.w + ald.w));
    }
    #pragma unroll
    for (int off = 16; off; off >>= 1){
        m0 = fmaxf(m0, __shfl_xor_sync(0xFFFFFFFFu, m0, off));
        m1 = fmaxf(m1, __shfl_xor_sync(0xFFFFFFFFu, m1, off));
        m2 = fmaxf(m2, __shfl_xor_sync(0xFFFFFFFFu, m2, off));
        m3 = fmaxf(m3, __shfl_xor_sync(0xFFFFFFFFu, m3, off));
    }

    // pass 2: exp + denom + weighted aggregation
    float acc[8] = {0,0,0,0,0,0,0,0};
    float dn0 = 0.f, dn1 = 0.f, dn2 = 0.f, dn3 = 0.f;
    int myh = lane >> 3;
    for (int base = beg; base < end; base += 32){
        int j = base + lane;
        int msrc = 0;
        float4 ex = {0,0,0,0};
        if (j < end){
            msrc = g_csrc[j];
            float4 a = ((const float4*)g_als)[msrc];
            ex.x = __expf(lrelu(a.x + ald.x) - m0);
            ex.y = __expf(lrelu(a.y + ald.y) - m1);
            ex.z = __expf(lrelu(a.z + ald.z) - m2);
            ex.w = __expf(lrelu(a.w + ald.w) - m3);
        }
        dn0 += ex.x; dn1 += ex.y; dn2 += ex.z; dn3 += ex.w;
        int cnt = min(32, end - base);
        for (int t = 0; t < cnt; t++){
            int src = __shfl_sync(0xFFFFFFFFu, msrc, t);
            float e0 = __shfl_sync(0xFFFFFFFFu, ex.x, t);
            float e1 = __shfl_sync(0xFFFFFFFFu, ex.y, t);
            float e2 = __shfl_sync(0xFFFFFFFFu, ex.z, t);
            float e3 = __shfl_sync(0xFFFFFFFFu, ex.w, t);
            float exv = (myh < 2) ? (myh == 0 ? e0 : e1) : (myh == 2 ? e2 : e3);
            const float4* hr = (const float4*)&g_h[(size_t)src*HC + lane*8];
            float4 h0 = hr[0], h1 = hr[1];
            acc[0] += exv*h0.x; acc[1] += exv*h0.y; acc[2] += exv*h0.z; acc[3] += exv*h0.w;
            acc[4] += exv*h1.x; acc[5] += exv*h1.y; acc[6] += exv*h1.z; acc[7] += exv*h1.w;
        }
    }
    #pragma unroll
    for (int off = 16; off; off >>= 1){
        dn0 += __shfl_xor_sync(0xFFFFFFFFu, dn0, off);
        dn1 += __shfl_xor_sync(0xFFFFFFFFu, dn1, off);
        dn2 += __shfl_xor_sync(0xFFFFFFFFu, dn2, off);
        dn3 += __shfl_xor_sync(0xFFFFFFFFu, dn3, off);
    }
    float mydn = (myh < 2) ? (myh == 0 ? dn0 : dn1) : (myh == 2 ? dn2 : dn3);
    float inv = 1.f / mydn;
    #pragma unroll
    for (int i = 0; i < 8; i++) acc[i] *= inv;
    #pragma unroll
    for (int i = 0; i < 8; i++){
        acc[i] += __shfl_xor_sync(0xFFFFFFFFu, acc[i], 8);
        acc[i] += __shfl_xor_sync(0xFFFFFFFFu, acc[i], 16);
        acc[i] *= 0.25f;
    }
    int cih = (lane & 7) * 8;
    float4 b0 = *(const float4*)&bg[cih];
    float4 b1 = *(const float4*)&bg[cih+4];
    float v[8];
    v[0]=acc[0]+b0.x; v[1]=acc[1]+b0.y; v[2]=acc[2]+b0.z; v[3]=acc[3]+b0.w;
    v[4]=acc[4]+b1.x; v[5]=acc[5]+b1.y; v[6]=acc[6]+b1.z; v[7]=acc[7]+b1.w;
    float s = 0.f, q = 0.f;
    #pragma unroll
    for (int i = 0; i < 8; i++){ s += v[i]; q += v[i]*v[i]; }
    #pragma unroll
    for (int off = 4; off; off >>= 1){
        s += __shfl_xor_sync(0xFFFFFFFFu, s, off);
        q += __shfl_xor_sync(0xFFFFFFFFu, q, off);
    }
    float mu   = s * (1.f/64.f);
    float var  = q * (1.f/64.f) - mu*mu;
    float rstd = rsqrtf(var + 1e-5f);
    float aw = pa[0];
    if (lane < 8){
        float4 g0 = *(const float4*)&gam[cih],   g1 = *(const float4*)&gam[cih+4];
        float4 t0 = *(const float4*)&bet[cih],   t1 = *(const float4*)&bet[cih+4];
        float* xp = &g_x[(size_t)n*HD + cih];
        float4 x0 = *(const float4*)xp, x1 = *(const float4*)(xp+4);
        float xn;
        xn = (v[0]-mu)*rstd*g0.x + t0.x; x0.x += (xn>0.f? xn : aw*xn);
        xn = (v[1]-mu)*rstd*g0.y + t0.y; x0.y += (xn>0.f? xn : aw*xn);
        xn = (v[2]-mu)*rstd*g0.z + t0.z; x0.z += (xn>0.f? xn : aw*xn);
        xn = (v[3]-mu)*rstd*g0.w + t0.w; x0.w += (xn>0.f? xn : aw*xn);
        xn = (v[4]-mu)*rstd*g1.x + t1.x; x1.x += (xn>0.f? xn : aw*xn);
        xn = (v[5]-mu)*rstd*g1.y + t1.y; x1.y += (xn>0.f? xn : aw*xn);
        xn = (v[6]-mu)*rstd*g1.z + t1.z; x1.z += (xn>0.f? xn : aw*xn);
        xn = (v[7]-mu)*rstd*g1.w + t1.w; x1.w += (xn>0.f? xn : aw*xn);
        *(float4*)xp     = x0;
        *(float4*)(xp+4) = x1;
    }
}

// ---------------- final: z = x @ Wp + bp, L2-normalize rows (f32x2) ----------------
__global__ __launch_bounds__(256) void k_final(const float* __restrict__ Wp,
                                               const float* __restrict__ bp,
                                               float* __restrict__ out){
    __shared__ ull Wp2[32][64];        // pair-over-k: (W[2k][c], W[2k+1][c])
    __shared__ __align__(16) float xs[8][64];
    int t = threadIdx.x;
    for (int i = t; i < 2048; i += 256){
        int k2 = i >> 6, c = i & 63;
        Wp2[k2][c] = pack2(Wp[(2*k2)*64 + c], Wp[(2*k2+1)*64 + c]);
    }
    int nb = blockIdx.x*8;
    for (int i = t; i < 512; i += 256){
        int r = nb + (i >> 6);
        xs[i>>6][i&63] = (r < Nn) ? g_x[(size_t)r*HD + (i & 63)] : 0.f;
    }
    __syncthreads();
    int w = t >> 5, lane = t & 31;
    int n = nb + w;
    if (n >= Nn) return;
    int c0 = lane, c1 = lane + 32;
    ull z2a = 0, z2b = 0;
    #pragma unroll
    for (int k2 = 0; k2 < 32; k2++){
        ull xv = *(const ull*)&xs[w][2*k2];
        fma2(z2a, xv, Wp2[k2][c0]);
        fma2(z2b, xv, Wp2[k2][c1]);
    }
    float l0, h0, l1, h1;
    unpack2(z2a, l0, h0);
    unpack2(z2b, l1, h1);
    float z0 = l0 + h0 + bp[c0];
    float z1 = l1 + h1 + bp[c1];
    float q = z0*z0 + z1*z1;
    #pragma unroll
    for (int off = 16; off; off >>= 1) q += __shfl_xor_sync(0xFFFFFFFFu, q, off);
    float inv = 1.f / fmaxf(sqrtf(q), 1e-12f);
    out[(size_t)n*HD + c0] = z0*inv;
    out[(size_t)n*HD + c1] = z1*inv;
}

// ---------------- launch ----------------
extern "C" void kernel_launch(void* const* d_in, const int* in_sizes, int n_in,
                              void* d_out, int out_size){
    const float* feat = (const float*)d_in[0];
    const int*   ei   = (const int*)  d_in[1];
    const float* Wt   = (const float*)d_in[2];
    const float* bt   = (const float*)d_in[3];
    const float* Wp   = (const float*)d_in[4];
    const float* bp   = (const float*)d_in[5];

    k_lin1<<<(Nn + 63)/64, 256>>>(feat, Wt, bt);

    // CSR build (shared by both layers)
    k_zerodeg<<<(Nn + 255)/256, 256>>>();
    k_count  <<<(Et + 255)/256, 256>>>(ei);
    k_scanA  <<<49, 1024>>>();
    k_scanB  <<<1, 64>>>();
    k_scanC  <<<49, 1024>>>();
    k_scatter<<<(Et + 255)/256, 256>>>(ei);

    for (int l = 0; l < 2; l++){
        const float* Wg  = (const float*)d_in[6 + l*7 + 0];
        const float* as_ = (const float*)d_in[6 + l*7 + 1];
        const float* ad_ = (const float*)d_in[6 + l*7 + 2];
        const float* bg  = (const float*)d_in[6 + l*7 + 3];
        const float* gam = (const float*)d_in[6 + l*7 + 4];
        const float* bet = (const float*)d_in[6 + l*7 + 5];
        const float* pa  = (const float*)d_in[6 + l*7 + 6];

        k_gemm_h<<<1184, 256>>>(Wg);
        k_vsvd  <<<1, 256>>>(Wg, as_, ad_);
        k_als   <<<(Nn*32 + 255)/256, 256>>>();
        k_gat   <<<(Nn*32 + 255)/256, 256>>>(bg, gam, bet, pa);
    }

    k_final<<<(Nn + 7)/8, 256>>>(Wp, bp, (float*)d_out);
}

// round 6
// speedup vs baseline: 2.0943x; 1.1034x over previous
#include <cuda_runtime.h>
#include <math_constants.h>

#define Nn 50000
#define Ee 800000
#define Et 850000
#define FD 512
#define HD 64
#define NH 4
#define HC 256   // NH*HD

typedef unsigned long long ull;

// ---------------- scratch (device globals; no allocation) ----------------
__device__ float g_x  [Nn*HD];     // current node features
__device__ float g_h  [Nn*HC];     // per-head transformed features
__device__ float g_als[Nn*NH];     // attention logit (src part)
__device__ float g_ald[Nn*NH];     // attention logit (dst part)
__device__ int   g_deg   [Nn];
__device__ int   g_rowptr[Nn+1];
__device__ int   g_cursor[Nn];
__device__ int   g_csrc  [Et];     // CSR (by dst) source node list
__device__ float g_vs[HD*NH];      // Wg-folded a_src: [k][h]
__device__ float g_vd[HD*NH];      // Wg-folded a_dst: [k][h]
__device__ int   g_bsum[64];
__device__ int   g_boff[64];

// ---------------- packed f32x2 helpers ----------------
__device__ __forceinline__ void fma2(ull& d, ull a, ull b){
    asm("fma.rn.f32x2 %0, %1, %2, %0;" : "+l"(d) : "l"(a), "l"(b));
}
__device__ __forceinline__ ull pack2(float lo, float hi){
    ull r; asm("mov.b64 %0, {%1, %2};" : "=l"(r) : "f"(lo), "f"(hi)); return r;
}
__device__ __forceinline__ void unpack2(ull v, float& lo, float& hi){
    asm("mov.b64 {%0, %1}, %2;" : "=f"(lo), "=f"(hi) : "l"(v));
}

// ---------------- CSR build ----------------
__global__ void k_zerodeg(){
    int i = blockIdx.x*blockDim.x + threadIdx.x;
    if (i < Nn) g_deg[i] = 0;
}
__global__ void k_count(const int* __restrict__ ei){
    int eid = blockIdx.x*blockDim.x + threadIdx.x;
    if (eid >= Et) return;
    int d = (eid < Ee) ? ei[Ee + eid] : (eid - Ee);
    atomicAdd(&g_deg[d], 1);
}
__global__ __launch_bounds__(1024) void k_scanA(){
    __shared__ int sh[1024];
    int t   = threadIdx.x;
    int gid = blockIdx.x*1024 + t;
    int v = (gid < Nn) ? g_deg[gid] : 0;
    sh[t] = v; __syncthreads();
    #pragma unroll
    for (int off = 1; off < 1024; off <<= 1){
        int u = (t >= off) ? sh[t-off] : 0;
        __syncthreads();
        sh[t] += u;
        __syncthreads();
    }
    if (gid < Nn) g_rowptr[gid] = sh[t] - v;
    if (t == 1023) g_bsum[blockIdx.x] = sh[1023];
}
__global__ void k_scanB(){
    __shared__ int sh[64];
    int t = threadIdx.x;
    sh[t] = (t < 49) ? g_bsum[t] : 0;
    __syncthreads();
    if (t == 0){
        int run = 0;
        for (int i = 0; i < 49; i++){
            g_boff[i] = run;
            run += sh[i];
        }
    }
}
__global__ __launch_bounds__(1024) void k_scanC(){
    int gid = blockIdx.x*1024 + threadIdx.x;
    if (gid < Nn){
        int r = g_rowptr[gid] + g_boff[blockIdx.x];
        g_rowptr[gid] = r;
        g_cursor[gid] = r;
    }
    if (gid == 0) g_rowptr[Nn] = Et;
}
__global__ void k_scatter(const int* __restrict__ ei){
    int eid = blockIdx.x*blockDim.x + threadIdx.x;
    if (eid >= Et) return;
    int s, d;
    if (eid < Ee){ s = ei[eid]; d = ei[Ee + eid]; } else { s = d = eid - Ee; }
    int pos = atomicAdd(&g_cursor[d], 1);
    g_csrc[pos] = s;
}

// ---------------- x = feat @ Wt + bt  (50000x512 @ 512x64), f32x2 ----------------
__global__ __launch_bounds__(256) void k_lin1(const float* __restrict__ A,
                                              const float* __restrict__ W,
                                              const float* __restrict__ bt){
    __shared__ __align__(16) float Ast[32][68];
    __shared__ __align__(16) float Bs [32][64];
    int t  = threadIdx.x;
    int rb = blockIdx.x*64;
    int ty = t >> 4, tx = t & 15;
    int ar = t >> 2;
    int ac = (t & 3) * 8;
    int br = t >> 3;
    int bc = (t & 7) * 8;
    ull c2[4][2] = {{0,0},{0,0},{0,0},{0,0}};

    for (int kb = 0; kb < FD; kb += 32){
        float4 a0 = {0,0,0,0}, a1 = {0,0,0,0};
        if (rb + ar < Nn){
            a0 = *(const float4*)&A[(size_t)(rb+ar)*FD + kb + ac];
            a1 = *(const float4*)&A[(size_t)(rb+ar)*FD + kb + ac + 4];
        }
        float4 b0 = *(const float4*)&W[(size_t)(kb+br)*64 + bc];
        float4 b1 = *(const float4*)&W[(size_t)(kb+br)*64 + bc + 4];
        __syncthreads();
        Ast[ac+0][ar]=a0.x; Ast[ac+1][ar]=a0.y; Ast[ac+2][ar]=a0.z; Ast[ac+3][ar]=a0.w;
        Ast[ac+4][ar]=a1.x; Ast[ac+5][ar]=a1.y; Ast[ac+6][ar]=a1.z; Ast[ac+7][ar]=a1.w;
        *(float4*)&Bs[br][bc]   = b0;
        *(float4*)&Bs[br][bc+4] = b1;
        __syncthreads();
        #pragma unroll
        for (int k = 0; k < 32; k++){
            float4 av = *(const float4*)&Ast[k][ty*4];
            ulonglong2 bv = *(const ulonglong2*)&Bs[k][tx*4];
            ull ax = pack2(av.x, av.x);
            ull ay = pack2(av.y, av.y);
            ull az = pack2(av.z, av.z);
            ull aw = pack2(av.w, av.w);
            fma2(c2[0][0], ax, bv.x); fma2(c2[0][1], ax, bv.y);
            fma2(c2[1][0], ay, bv.x); fma2(c2[1][1], ay, bv.y);
            fma2(c2[2][0], az, bv.x); fma2(c2[2][1], az, bv.y);
            fma2(c2[3][0], aw, bv.x); fma2(c2[3][1], aw, bv.y);
        }
    }
    float bt0 = bt[tx*4+0], bt1 = bt[tx*4+1], bt2 = bt[tx*4+2], bt3 = bt[tx*4+3];
    int r0 = rb + ty*4;
    #pragma unroll
    for (int i = 0; i < 4; i++){
        int r = r0 + i;
        if (r < Nn){
            float v0,v1,v2,v3;
            unpack2(c2[i][0], v0, v1);
            unpack2(c2[i][1], v2, v3);
            float* o = &g_x[(size_t)r*HD + tx*4];
            o[0] = v0 + bt0; o[1] = v1 + bt1;
            o[2] = v2 + bt2; o[3] = v3 + bt3;
        }
    }
}

// ---------------- h = x @ Wg  (50000x64 @ 64x256), f32x2 pair-over-K ----------------
__global__ __launch_bounds__(256) void k_gemm_h(const float* __restrict__ W){
    int j = threadIdx.x;
    ull w2[32];
    #pragma unroll
    for (int k2 = 0; k2 < 32; k2++)
        w2[k2] = pack2(W[(2*k2)*256 + j], W[(2*k2+1)*256 + j]);
    __shared__ __align__(16) float xs[4][64];
    for (int rb = blockIdx.x*4; rb < Nn; rb += gridDim.x*4){
        int r = rb + (j >> 6);
        float xv = (r < Nn) ? g_x[(size_t)r*HD + (j & 63)] : 0.f;
        __syncthreads();
        xs[j>>6][j&63] = xv;
        __syncthreads();
        ull a2[4] = {0,0,0,0};
        #pragma unroll
        for (int k4 = 0; k4 < 16; k4++){
            ulonglong2 x0 = *(const ulonglong2*)&xs[0][k4*4];
            ulonglong2 x1 = *(const ulonglong2*)&xs[1][k4*4];
            ulonglong2 x2 = *(const ulonglong2*)&xs[2][k4*4];
            ulonglong2 x3 = *(const ulonglong2*)&xs[3][k4*4];
            fma2(a2[0], x0.x, w2[k4*2]); fma2(a2[0], x0.y, w2[k4*2+1]);
            fma2(a2[1], x1.x, w2[k4*2]); fma2(a2[1], x1.y, w2[k4*2+1]);
            fma2(a2[2], x2.x, w2[k4*2]); fma2(a2[2], x2.y, w2[k4*2+1]);
            fma2(a2[3], x3.x, w2[k4*2]); fma2(a2[3], x3.y, w2[k4*2+1]);
        }
        #pragma unroll
        for (int i = 0; i < 4; i++){
            if (rb+i < Nn){
                float lo, hi; unpack2(a2[i], lo, hi);
                g_h[(size_t)(rb+i)*HC + j] = lo + hi;
            }
        }
    }
}

// ---------------- fold attention vectors through Wg ----------------
__global__ void k_vsvd(const float* __restrict__ Wg,
                       const float* __restrict__ as_,
                       const float* __restrict__ ad_){
    int t = threadIdx.x;
    int k = t >> 2, h = t & 3;
    float ss = 0.f, sd = 0.f;
    const float* wrow = &Wg[k*HC + h*HD];
    const float* av   = &as_[h*HD];
    const float* bv   = &ad_[h*HD];
    #pragma unroll 16
    for (int c = 0; c < HD; c++){
        float w = wrow[c];
        ss += w * av[c];
        sd += w * bv[c];
    }
    g_vs[k*NH + h] = ss;
    g_vd[k*NH + h] = sd;
}

// ---------------- als/ald = x @ Vs / x @ Vd ----------------
__global__ __launch_bounds__(256) void k_als(){
    int n    = (blockIdx.x*blockDim.x + threadIdx.x) >> 5;
    int lane = threadIdx.x & 31;
    if (n >= Nn) return;
    float x0 = g_x[(size_t)n*HD + lane];
    float x1 = g_x[(size_t)n*HD + lane + 32];
    float4 v0 = ((const float4*)g_vs)[lane];
    float4 v1 = ((const float4*)g_vs)[lane+32];
    float4 d0 = ((const float4*)g_vd)[lane];
    float4 d1 = ((const float4*)g_vd)[lane+32];
    float s[4], d[4];
    s[0] = x0*v0.x + x1*v1.x; s[1] = x0*v0.y + x1*v1.y;
    s[2] = x0*v0.z + x1*v1.z; s[3] = x0*v0.w + x1*v1.w;
    d[0] = x0*d0.x + x1*d1.x; d[1] = x0*d0.y + x1*d1.y;
    d[2] = x0*d0.z + x1*d1.z; d[3] = x0*d0.w + x1*d1.w;
    #pragma unroll
    for (int off = 16; off; off >>= 1){
        #pragma unroll
        for (int h = 0; h < 4; h++){
            s[h] += __shfl_xor_sync(0xFFFFFFFFu, s[h], off);
            d[h] += __shfl_xor_sync(0xFFFFFFFFu, d[h], off);
        }
    }
    if (lane == 0){
        ((float4*)g_als)[n] = make_float4(s[0], s[1], s[2], s[3]);
        ((float4*)g_ald)[n] = make_float4(d[0], d[1], d[2], d[3]);
    }
}

__device__ __forceinline__ float lrelu(float v){ return v > 0.f ? v : 0.2f*v; }

// ---------------- fused GAT ----------------
// warp per dst node. ex/src staged in smem; aggregation 4 edges/group,
// 8 independent LDG.128 in flight; denom accumulated inside the loop.
__global__ __launch_bounds__(256) void k_gat(const float* __restrict__ bg,
                                             const float* __restrict__ gam,
                                             const float* __restrict__ bet,
                                             const float* __restrict__ pa){
    __shared__ __align__(16) float exsh [8][NH][32];
    __shared__ __align__(16) int   srcsh[8][32];
    int w    = threadIdx.x >> 5;
    int lane = threadIdx.x & 31;
    int n    = blockIdx.x*8 + w;
    if (n >= Nn) return;
    int beg = g_rowptr[n], end = g_rowptr[n+1];
    int deg = end - beg;
    float4 ald = ((const float4*)g_ald)[n];
    int myh = lane >> 3;

    ull acc2[4] = {0,0,0,0};
    float dn = 0.f;

    if (deg <= 32){
        // ---- fast path: one chunk, logits computed once ----
        int j = beg + lane;
        bool v = (j < end);
        int src = v ? g_csrc[j] : 0;
        float4 a = v ? ((const float4*)g_als)[src] : make_float4(0,0,0,0);
        float l0 = v ? lrelu(a.x + ald.x) : -CUDART_INF_F;
        float l1 = v ? lrelu(a.y + ald.y) : -CUDART_INF_F;
        float l2 = v ? lrelu(a.z + ald.z) : -CUDART_INF_F;
        float l3 = v ? lrelu(a.w + ald.w) : -CUDART_INF_F;
        float m0=l0, m1=l1, m2=l2, m3=l3;
        #pragma unroll
        for (int off = 16; off; off >>= 1){
            m0 = fmaxf(m0, __shfl_xor_sync(0xFFFFFFFFu, m0, off));
            m1 = fmaxf(m1, __shfl_xor_sync(0xFFFFFFFFu, m1, off));
            m2 = fmaxf(m2, __shfl_xor_sync(0xFFFFFFFFu, m2, off));
            m3 = fmaxf(m3, __shfl_xor_sync(0xFFFFFFFFu, m3, off));
        }
        exsh[w][0][lane] = v ? __expf(l0 - m0) : 0.f;
        exsh[w][1][lane] = v ? __expf(l1 - m1) : 0.f;
        exsh[w][2][lane] = v ? __expf(l2 - m2) : 0.f;
        exsh[w][3][lane] = v ? __expf(l3 - m3) : 0.f;
        srcsh[w][lane] = src;
        __syncwarp();
        const float* eh = exsh[w][myh];
        int t = 0;
        for (; t + 4 <= deg; t += 4){
            float4 e  = *(const float4*)&eh[t];
            int4   s4 = *(const int4*)&srcsh[w][t];
            dn += e.x + e.y + e.z + e.w;
            {
                const ulonglong2* hr = (const ulonglong2*)&g_h[(size_t)s4.x*HC + lane*8];
                ulonglong2 p0 = hr[0], p1 = hr[1];
                ull ee = pack2(e.x, e.x);
                fma2(acc2[0], p0.x, ee); fma2(acc2[1], p0.y, ee);
                fma2(acc2[2], p1.x, ee); fma2(acc2[3], p1.y, ee);
            }
            {
                const ulonglong2* hr = (const ulonglong2*)&g_h[(size_t)s4.y*HC + lane*8];
                ulonglong2 p0 = hr[0], p1 = hr[1];
                ull ee = pack2(e.y, e.y);
                fma2(acc2[0], p0.x, ee); fma2(acc2[1], p0.y, ee);
                fma2(acc2[2], p1.x, ee); fma2(acc2[3], p1.y, ee);
            }
            {
                const ulonglong2* hr = (const ulonglong2*)&g_h[(size_t)s4.z*HC + lane*8];
                ulonglong2 p0 = hr[0], p1 = hr[1];
                ull ee = pack2(e.z, e.z);
                fma2(acc2[0], p0.x, ee); fma2(acc2[1], p0.y, ee);
                fma2(acc2[2], p1.x, ee); fma2(acc2[3], p1.y, ee);
            }
            {
                const ulonglong2* hr = (const ulonglong2*)&g_h[(size_t)s4.w*HC + lane*8];
                ulonglong2 p0 = hr[0], p1 = hr[1];
                ull ee = pack2(e.w, e.w);
                fma2(acc2[0], p0.x, ee); fma2(acc2[1], p0.y, ee);
                fma2(acc2[2], p1.x, ee); fma2(acc2[3], p1.y, ee);
            }
        }
        for (; t < deg; t++){
            float e = eh[t];
            int s = srcsh[w][t];
            dn += e;
            const ulonglong2* hr = (const ulonglong2*)&g_h[(size_t)s*HC + lane*8];
            ulonglong2 p0 = hr[0], p1 = hr[1];
            ull ee = pack2(e, e);
            fma2(acc2[0], p0.x, ee); fma2(acc2[1], p0.y, ee);
            fma2(acc2[2], p1.x, ee); fma2(acc2[3], p1.y, ee);
        }
    } else {
        // ---- generic path (deg > 32, rare) ----
        float m0 = -CUDART_INF_F, m1 = m0, m2 = m0, m3 = m0;
        for (int j = beg + lane; j < end; j += 32){
            int s = g_csrc[j];
            float4 a = ((const float4*)g_als)[s];
            m0 = fmaxf(m0, lrelu(a.x + ald.x));
            m1 = fmaxf(m1, lrelu(a.y + ald.y));
            m2 = fmaxf(m2, lrelu(a.z + ald.z));
            m3 = fmaxf(m3, lrelu(a.w + ald.w));
        }
        #pragma unroll
        for (int off = 16; off; off >>= 1){
            m0 = fmaxf(m0, __shfl_xor_sync(0xFFFFFFFFu, m0, off));
            m1 = fmaxf(m1, __shfl_xor_sync(0xFFFFFFFFu, m1, off));
            m2 = fmaxf(m2, __shfl_xor_sync(0xFFFFFFFFu, m2, off));
            m3 = fmaxf(m3, __shfl_xor_sync(0xFFFFFFFFu, m3, off));
        }
        for (int base = beg; base < end; base += 32){
            int j = base + lane;
            int cnt = min(32, end - base);
            bool v = (j < end);
            int src = v ? g_csrc[j] : 0;
            float4 a = v ? ((const float4*)g_als)[src] : make_float4(0,0,0,0);
            exsh[w][0][lane] = v ? __expf(lrelu(a.x + ald.x) - m0) : 0.f;
            exsh[w][1][lane] = v ? __expf(lrelu(a.y + ald.y) - m1) : 0.f;
            exsh[w][2][lane] = v ? __expf(lrelu(a.z + ald.z) - m2) : 0.f;
            exsh[w][3][lane] = v ? __expf(lrelu(a.w + ald.w) - m3) : 0.f;
            srcsh[w][lane] = src;
            __syncwarp();
            const float* eh = exsh[w][myh];
            int t = 0;
            for (; t + 4 <= cnt; t += 4){
                float4 e  = *(const float4*)&eh[t];
                int4   s4 = *(const int4*)&srcsh[w][t];
                dn += e.x + e.y + e.z + e.w;
                {
                    const ulonglong2* hr = (const ulonglong2*)&g_h[(size_t)s4.x*HC + lane*8];
                    ulonglong2 p0 = hr[0], p1 = hr[1];
                    ull ee = pack2(e.x, e.x);
                    fma2(acc2[0], p0.x, ee); fma2(acc2[1], p0.y, ee);
                    fma2(acc2[2], p1.x, ee); fma2(acc2[3], p1.y, ee);
                }
                {
                    const ulonglong2* hr = (const ulonglong2*)&g_h[(size_t)s4.y*HC + lane*8];
                    ulonglong2 p0 = hr[0], p1 = hr[1];
                    ull ee = pack2(e.y, e.y);
                    fma2(acc2[0], p0.x, ee); fma2(acc2[1], p0.y, ee);
                    fma2(acc2[2], p1.x, ee); fma2(acc2[3], p1.y, ee);
                }
                {
                    const ulonglong2* hr = (const ulonglong2*)&g_h[(size_t)s4.z*HC + lane*8];
                    ulonglong2 p0 = hr[0], p1 = hr[1];
                    ull ee = pack2(e.z, e.z);
                    fma2(acc2[0], p0.x, ee); fma2(acc2[1], p0.y, ee);
                    fma2(acc2[2], p1.x, ee); fma2(acc2[3], p1.y, ee);
                }
                {
                    const ulonglong2* hr = (const ulonglong2*)&g_h[(size_t)s4.w*HC + lane*8];
                    ulonglong2 p0 = hr[0], p1 = hr[1];
                    ull ee = pack2(e.w, e.w);
                    fma2(acc2[0], p0.x, ee); fma2(acc2[1], p0.y, ee);
                    fma2(acc2[2], p1.x, ee); fma2(acc2[3], p1.y, ee);
                }
            }
            for (; t < cnt; t++){
                float e = eh[t];
                int s = srcsh[w][t];
                dn += e;
                const ulonglong2* hr = (const ulonglong2*)&g_h[(size_t)s*HC + lane*8];
                ulonglong2 p0 = hr[0], p1 = hr[1];
                ull ee = pack2(e, e);
                fma2(acc2[0], p0.x, ee); fma2(acc2[1], p0.y, ee);
                fma2(acc2[2], p1.x, ee); fma2(acc2[3], p1.y, ee);
            }
            __syncwarp();
        }
    }

    // unpack accumulators
    float acc[8];
    unpack2(acc2[0], acc[0], acc[1]);
    unpack2(acc2[1], acc[2], acc[3]);
    unpack2(acc2[2], acc[4], acc[5]);
    unpack2(acc2[3], acc[6], acc[7]);
    float inv = 1.f / dn;
    #pragma unroll
    for (int i = 0; i < 8; i++) acc[i] *= inv;
    // cross-head mean
    #pragma unroll
    for (int i = 0; i < 8; i++){
        acc[i] += __shfl_xor_sync(0xFFFFFFFFu, acc[i], 8);
        acc[i] += __shfl_xor_sync(0xFFFFFFFFu, acc[i], 16);
        acc[i] *= 0.25f;
    }
    int cih = (lane & 7) * 8;
    float4 b0 = *(const float4*)&bg[cih];
    float4 b1 = *(const float4*)&bg[cih+4];
    float v[8];
    v[0]=acc[0]+b0.x; v[1]=acc[1]+b0.y; v[2]=acc[2]+b0.z; v[3]=acc[3]+b0.w;
    v[4]=acc[4]+b1.x; v[5]=acc[5]+b1.y; v[6]=acc[6]+b1.z; v[7]=acc[7]+b1.w;
    float s = 0.f, q = 0.f;
    #pragma unroll
    for (int i = 0; i < 8; i++){ s += v[i]; q += v[i]*v[i]; }
    #pragma unroll
    for (int off = 4; off; off >>= 1){
        s += __shfl_xor_sync(0xFFFFFFFFu, s, off);
        q += __shfl_xor_sync(0xFFFFFFFFu, q, off);
    }
    float mu   = s * (1.f/64.f);
    float var  = q * (1.f/64.f) - mu*mu;
    float rstd = rsqrtf(var + 1e-5f);
    float aw = pa[0];
    if (lane < 8){
        float4 g0 = *(const float4*)&gam[cih],   g1 = *(const float4*)&gam[cih+4];
        float4 t0 = *(const float4*)&bet[cih],   t1 = *(const float4*)&bet[cih+4];
        float* xp = &g_x[(size_t)n*HD + cih];
        float4 x0 = *(const float4*)xp, x1 = *(const float4*)(xp+4);
        float xn;
        xn = (v[0]-mu)*rstd*g0.x + t0.x; x0.x += (xn>0.f? xn : aw*xn);
        xn = (v[1]-mu)*rstd*g0.y + t0.y; x0.y += (xn>0.f? xn : aw*xn);
        xn = (v[2]-mu)*rstd*g0.z + t0.z; x0.z += (xn>0.f? xn : aw*xn);
        xn = (v[3]-mu)*rstd*g0.w + t0.w; x0.w += (xn>0.f? xn : aw*xn);
        xn = (v[4]-mu)*rstd*g1.x + t1.x; x1.x += (xn>0.f? xn : aw*xn);
        xn = (v[5]-mu)*rstd*g1.y + t1.y; x1.y += (xn>0.f? xn : aw*xn);
        xn = (v[6]-mu)*rstd*g1.z + t1.z; x1.z += (xn>0.f? xn : aw*xn);
        xn = (v[7]-mu)*rstd*g1.w + t1.w; x1.w += (xn>0.f? xn : aw*xn);
        *(float4*)xp     = x0;
        *(float4*)(xp+4) = x1;
    }
}

// ---------------- final: z = x @ Wp + bp, L2-normalize rows (f32x2) ----------------
__global__ __launch_bounds__(256) void k_final(const float* __restrict__ Wp,
                                               const float* __restrict__ bp,
                                               float* __restrict__ out){
    __shared__ ull Wp2[32][64];
    __shared__ __align__(16) float xs[8][64];
    int t = threadIdx.x;
    for (int i = t; i < 2048; i += 256){
        int k2 = i >> 6, c = i & 63;
        Wp2[k2][c] = pack2(Wp[(2*k2)*64 + c], Wp[(2*k2+1)*64 + c]);
    }
    int nb = blockIdx.x*8;
    for (int i = t; i < 512; i += 256){
        int r = nb + (i >> 6);
        xs[i>>6][i&63] = (r < Nn) ? g_x[(size_t)r*HD + (i & 63)] : 0.f;
    }
    __syncthreads();
    int w = t >> 5, lane = t & 31;
    int n = nb + w;
    if (n >= Nn) return;
    int c0 = lane, c1 = lane + 32;
    ull z2a = 0, z2b = 0;
    #pragma unroll
    for (int k2 = 0; k2 < 32; k2++){
        ull xv = *(const ull*)&xs[w][2*k2];
        fma2(z2a, xv, Wp2[k2][c0]);
        fma2(z2b, xv, Wp2[k2][c1]);
    }
    float l0, h0, l1, h1;
    unpack2(z2a, l0, h0);
    unpack2(z2b, l1, h1);
    float z0 = l0 + h0 + bp[c0];
    float z1 = l1 + h1 + bp[c1];
    float q = z0*z0 + z1*z1;
    #pragma unroll
    for (int off = 16; off; off >>= 1) q += __shfl_xor_sync(0xFFFFFFFFu, q, off);
    float inv = 1.f / fmaxf(sqrtf(q), 1e-12f);
    out[(size_t)n*HD + c0] = z0*inv;
    out[(size_t)n*HD + c1] = z1*inv;
}

// ---------------- launch ----------------
extern "C" void kernel_launch(void* const* d_in, const int* in_sizes, int n_in,
                              void* d_out, int out_size){
    const float* feat = (const float*)d_in[0];
    const int*   ei   = (const int*)  d_in[1];
    const float* Wt   = (const float*)d_in[2];
    const float* bt   = (const float*)d_in[3];
    const float* Wp   = (const float*)d_in[4];
    const float* bp   = (const float*)d_in[5];

    k_lin1<<<(Nn + 63)/64, 256>>>(feat, Wt, bt);

    // CSR build (shared by both layers)
    k_zerodeg<<<(Nn + 255)/256, 256>>>();
    k_count  <<<(Et + 255)/256, 256>>>(ei);
    k_scanA  <<<49, 1024>>>();
    k_scanB  <<<1, 64>>>();
    k_scanC  <<<49, 1024>>>();
    k_scatter<<<(Et + 255)/256, 256>>>(ei);

    for (int l = 0; l < 2; l++){
        const float* Wg  = (const float*)d_in[6 + l*7 + 0];
        const float* as_ = (const float*)d_in[6 + l*7 + 1];
        const float* ad_ = (const float*)d_in[6 + l*7 + 2];
        const float* bg  = (const float*)d_in[6 + l*7 + 3];
        const float* gam = (const float*)d_in[6 + l*7 + 4];
        const float* bet = (const float*)d_in[6 + l*7 + 5];
        const float* pa  = (const float*)d_in[6 + l*7 + 6];

        k_gemm_h<<<1184, 256>>>(Wg);
        k_vsvd  <<<1, 256>>>(Wg, as_, ad_);
        k_als   <<<(Nn*32 + 255)/256, 256>>>();
        k_gat   <<<(Nn + 7)/8, 256>>>(bg, gam, bet, pa);
    }

    k_final<<<(Nn + 7)/8, 256>>>(Wp, bp, (float*)d_out);
}

// round 13
// speedup vs baseline: 2.4366x; 1.1635x over previous
#include <cuda_runtime.h>
#include <cuda_fp16.h>
#include <math_constants.h>

#define Nn 50000
#define Ee 800000
#define Et 850000
#define FD 512
#define HD 64
#define NH 4
#define HC 256   // NH*HD

typedef unsigned long long ull;

// ---------------- scratch (device globals; no allocation) ----------------
__device__ float          g_x  [Nn*HD];   // current node features
__device__ unsigned short g_hh [Nn*HC];   // per-head transformed features (fp16 bits)
__device__ float          g_als[Nn*NH];   // attention logit (src part)
__device__ float          g_ald[Nn*NH];   // attention logit (dst part)
__device__ int   g_deg   [Nn];
__device__ int   g_rowptr[Nn+1];
__device__ int   g_cursor[Nn];
__device__ int   g_csrc  [Et];            // CSR (by dst) source node list
__device__ float g_vs[HD*NH];             // Wg-folded a_src: [k][h]
__device__ float g_vd[HD*NH];             // Wg-folded a_dst: [k][h]
__device__ int   g_bsum[64];
__device__ int   g_boff[64];

// ---------------- packed f32x2 helpers ----------------
__device__ __forceinline__ void fma2(ull& d, ull a, ull b){
    asm("fma.rn.f32x2 %0, %1, %2, %0;" : "+l"(d) : "l"(a), "l"(b));
}
__device__ __forceinline__ ull pack2(float lo, float hi){
    ull r; asm("mov.b64 %0, {%1, %2};" : "=l"(r) : "f"(lo), "f"(hi)); return r;
}
__device__ __forceinline__ void unpack2(ull v, float& lo, float& hi){
    asm("mov.b64 {%0, %1}, %2;" : "=f"(lo), "=f"(hi) : "l"(v));
}
// half2 word -> two fp32
__device__ __forceinline__ float2 h2f(unsigned w){
    __half2 h = *(__half2*)&w;
    return __half22float2(h);
}

// ---------------- CSR build ----------------
__global__ void k_zerodeg(){
    int i = blockIdx.x*blockDim.x + threadIdx.x;
    if (i < Nn) g_deg[i] = 0;
}
__global__ void k_count(const int* __restrict__ ei){
    int eid = blockIdx.x*blockDim.x + threadIdx.x;
    if (eid >= Et) return;
    int d = (eid < Ee) ? ei[Ee + eid] : (eid - Ee);
    atomicAdd(&g_deg[d], 1);
}
__global__ __launch_bounds__(1024) void k_scanA(){
    __shared__ int sh[1024];
    int t   = threadIdx.x;
    int gid = blockIdx.x*1024 + t;
    int v = (gid < Nn) ? g_deg[gid] : 0;
    sh[t] = v; __syncthreads();
    #pragma unroll
    for (int off = 1; off < 1024; off <<= 1){
        int u = (t >= off) ? sh[t-off] : 0;
        __syncthreads();
        sh[t] += u;
        __syncthreads();
    }
    if (gid < Nn) g_rowptr[gid] = sh[t] - v;
    if (t == 1023) g_bsum[blockIdx.x] = sh[1023];
}
__global__ void k_scanB(){
    __shared__ int sh[64];
    int t = threadIdx.x;
    sh[t] = (t < 49) ? g_bsum[t] : 0;
    __syncthreads();
    if (t == 0){
        int run = 0;
        for (int i = 0; i < 49; i++){
            g_boff[i] = run;
            run += sh[i];
        }
    }
}
__global__ __launch_bounds__(1024) void k_scanC(){
    int gid = blockIdx.x*1024 + threadIdx.x;
    if (gid < Nn){
        int r = g_rowptr[gid] + g_boff[blockIdx.x];
        g_rowptr[gid] = r;
        g_cursor[gid] = r;
    }
    if (gid == 0) g_rowptr[Nn] = Et;
}
__global__ void k_scatter(const int* __restrict__ ei){
    int eid = blockIdx.x*blockDim.x + threadIdx.x;
    if (eid >= Et) return;
    int s, d;
    if (eid < Ee){ s = ei[eid]; d = ei[Ee + eid]; } else { s = d = eid - Ee; }
    int pos = atomicAdd(&g_cursor[d], 1);
    g_csrc[pos] = s;
}

// ---------------- x = feat @ Wt + bt  (50000x512 @ 512x64), f32x2 ----------------
__global__ __launch_bounds__(256) void k_lin1(const float* __restrict__ A,
                                              const float* __restrict__ W,
                                              const float* __restrict__ bt){
    __shared__ __align__(16) float Ast[32][68];
    __shared__ __align__(16) float Bs [32][64];
    int t  = threadIdx.x;
    int rb = blockIdx.x*64;
    int ty = t >> 4, tx = t & 15;
    int ar = t >> 2;
    int ac = (t & 3) * 8;
    int br = t >> 3;
    int bc = (t & 7) * 8;
    ull c2[4][2] = {{0,0},{0,0},{0,0},{0,0}};

    for (int kb = 0; kb < FD; kb += 32){
        float4 a0 = {0,0,0,0}, a1 = {0,0,0,0};
        if (rb + ar < Nn){
            a0 = *(const float4*)&A[(size_t)(rb+ar)*FD + kb + ac];
            a1 = *(const float4*)&A[(size_t)(rb+ar)*FD + kb + ac + 4];
        }
        float4 b0 = *(const float4*)&W[(size_t)(kb+br)*64 + bc];
        float4 b1 = *(const float4*)&W[(size_t)(kb+br)*64 + bc + 4];
        __syncthreads();
        Ast[ac+0][ar]=a0.x; Ast[ac+1][ar]=a0.y; Ast[ac+2][ar]=a0.z; Ast[ac+3][ar]=a0.w;
        Ast[ac+4][ar]=a1.x; Ast[ac+5][ar]=a1.y; Ast[ac+6][ar]=a1.z; Ast[ac+7][ar]=a1.w;
        *(float4*)&Bs[br][bc]   = b0;
        *(float4*)&Bs[br][bc+4] = b1;
        __syncthreads();
        #pragma unroll
        for (int k = 0; k < 32; k++){
            float4 av = *(const float4*)&Ast[k][ty*4];
            ulonglong2 bv = *(const ulonglong2*)&Bs[k][tx*4];
            ull ax = pack2(av.x, av.x);
            ull ay = pack2(av.y, av.y);
            ull az = pack2(av.z, av.z);
            ull aw = pack2(av.w, av.w);
            fma2(c2[0][0], ax, bv.x); fma2(c2[0][1], ax, bv.y);
            fma2(c2[1][0], ay, bv.x); fma2(c2[1][1], ay, bv.y);
            fma2(c2[2][0], az, bv.x); fma2(c2[2][1], az, bv.y);
            fma2(c2[3][0], aw, bv.x); fma2(c2[3][1], aw, bv.y);
        }
    }
    float bt0 = bt[tx*4+0], bt1 = bt[tx*4+1], bt2 = bt[tx*4+2], bt3 = bt[tx*4+3];
    int r0 = rb + ty*4;
    #pragma unroll
    for (int i = 0; i < 4; i++){
        int r = r0 + i;
        if (r < Nn){
            float v0,v1,v2,v3;
            unpack2(c2[i][0], v0, v1);
            unpack2(c2[i][1], v2, v3);
            float* o = &g_x[(size_t)r*HD + tx*4];
            o[0] = v0 + bt0; o[1] = v1 + bt1;
            o[2] = v2 + bt2; o[3] = v3 + bt3;
        }
    }
}

// ---------------- h = x @ Wg  (50000x64 @ 64x256), f32x2, fp16 output ----------------
__global__ __launch_bounds__(256) void k_gemm_h(const float* __restrict__ W){
    int j = threadIdx.x;
    ull w2[32];
    #pragma unroll
    for (int k2 = 0; k2 < 32; k2++)
        w2[k2] = pack2(W[(2*k2)*256 + j], W[(2*k2+1)*256 + j]);
    __shared__ __align__(16) float xs[4][64];
    for (int rb = blockIdx.x*4; rb < Nn; rb += gridDim.x*4){
        int r = rb + (j >> 6);
        float xv = (r < Nn) ? g_x[(size_t)r*HD + (j & 63)] : 0.f;
        __syncthreads();
        xs[j>>6][j&63] = xv;
        __syncthreads();
        ull a2[4] = {0,0,0,0};
        #pragma unroll
        for (int k4 = 0; k4 < 16; k4++){
            ulonglong2 x0 = *(const ulonglong2*)&xs[0][k4*4];
            ulonglong2 x1 = *(const ulonglong2*)&xs[1][k4*4];
            ulonglong2 x2 = *(const ulonglong2*)&xs[2][k4*4];
            ulonglong2 x3 = *(const ulonglong2*)&xs[3][k4*4];
            fma2(a2[0], x0.x, w2[k4*2]); fma2(a2[0], x0.y, w2[k4*2+1]);
            fma2(a2[1], x1.x, w2[k4*2]); fma2(a2[1], x1.y, w2[k4*2+1]);
            fma2(a2[2], x2.x, w2[k4*2]); fma2(a2[2], x2.y, w2[k4*2+1]);
            fma2(a2[3], x3.x, w2[k4*2]); fma2(a2[3], x3.y, w2[k4*2+1]);
        }
        #pragma unroll
        for (int i = 0; i < 4; i++){
            if (rb+i < Nn){
                float lo, hi; unpack2(a2[i], lo, hi);
                __half b = __float2half_rn(lo + hi);
                g_hh[(size_t)(rb+i)*HC + j] = *(unsigned short*)&b;
            }
        }
    }
}

// ---------------- fold attention vectors through Wg ----------------
__global__ void k_vsvd(const float* __restrict__ Wg,
                       const float* __restrict__ as_,
                       const float* __restrict__ ad_){
    int t = threadIdx.x;
    int k = t >> 2, h = t & 3;
    float ss = 0.f, sd = 0.f;
    const float* wrow = &Wg[k*HC + h*HD];
    const float* av   = &as_[h*HD];
    const float* bv   = &ad_[h*HD];
    #pragma unroll 16
    for (int c = 0; c < HD; c++){
        float w = wrow[c];
        ss += w * av[c];
        sd += w * bv[c];
    }
    g_vs[k*NH + h] = ss;
    g_vd[k*NH + h] = sd;
}

// ---------------- als/ald = x @ Vs / x @ Vd ----------------
__global__ __launch_bounds__(256) void k_als(){
    int n    = (blockIdx.x*blockDim.x + threadIdx.x) >> 5;
    int lane = threadIdx.x & 31;
    if (n >= Nn) return;
    float x0 = g_x[(size_t)n*HD + lane];
    float x1 = g_x[(size_t)n*HD + lane + 32];
    float4 v0 = ((const float4*)g_vs)[lane];
    float4 v1 = ((const float4*)g_vs)[lane+32];
    float4 d0 = ((const float4*)g_vd)[lane];
    float4 d1 = ((const float4*)g_vd)[lane+32];
    float s[4], d[4];
    s[0] = x0*v0.x + x1*v1.x; s[1] = x0*v0.y + x1*v1.y;
    s[2] = x0*v0.z + x1*v1.z; s[3] = x0*v0.w + x1*v1.w;
    d[0] = x0*d0.x + x1*d1.x; d[1] = x0*d0.y + x1*d1.y;
    d[2] = x0*d0.z + x1*d1.z; d[3] = x0*d0.w + x1*d1.w;
    #pragma unroll
    for (int off = 16; off; off >>= 1){
        #pragma unroll
        for (int h = 0; h < 4; h++){
            s[h] += __shfl_xor_sync(0xFFFFFFFFu, s[h], off);
            d[h] += __shfl_xor_sync(0xFFFFFFFFu, d[h], off);
        }
    }
    if (lane == 0){
        ((float4*)g_als)[n] = make_float4(s[0], s[1], s[2], s[3]);
        ((float4*)g_ald)[n] = make_float4(d[0], d[1], d[2], d[3]);
    }
}

__device__ __forceinline__ float lrelu(float v){ return v > 0.f ? v : 0.2f*v; }

// one-edge aggregation: gather 8 fp16 channels (one LDG.128), fp32 FMA
__device__ __forceinline__ void agg_edge(float* acc, int src, float e, int lane){
    uint4 p = *(const uint4*)&g_hh[(size_t)src*HC + lane*8];
    float2 c0 = h2f(p.x), c1 = h2f(p.y), c2 = h2f(p.z), c3 = h2f(p.w);
    acc[0] += e*c0.x; acc[1] += e*c0.y;
    acc[2] += e*c1.x; acc[3] += e*c1.y;
    acc[4] += e*c2.x; acc[5] += e*c2.y;
    acc[6] += e*c3.x; acc[7] += e*c3.y;
}

// ---------------- fused GAT (no segment-max: softmax is shift-invariant,
// logits bounded so exp is safe) ----------------
__global__ __launch_bounds__(256) void k_gat(const float* __restrict__ bg,
                                             const float* __restrict__ gam,
                                             const float* __restrict__ bet,
                                             const float* __restrict__ pa){
    __shared__ __align__(16) float exsh [8][NH][32];
    __shared__ __align__(16) int   srcsh[8][32];
    int w    = threadIdx.x >> 5;
    int lane = threadIdx.x & 31;
    int n    = blockIdx.x*8 + w;
    if (n >= Nn) return;
    int beg = g_rowptr[n], end = g_rowptr[n+1];
    int deg = end - beg;
    float4 ald = ((const float4*)g_ald)[n];
    int myh = lane >> 3;

    float acc[8] = {0,0,0,0,0,0,0,0};
    float dn = 0.f;

    if (deg <= 32){
        // ---- fast path: one chunk ----
        int j = beg + lane;
        bool v = (j < end);
        int src = v ? g_csrc[j] : 0;
        float4 a = v ? ((const float4*)g_als)[src] : make_float4(0,0,0,0);
        exsh[w][0][lane] = v ? __expf(lrelu(a.x + ald.x)) : 0.f;
        exsh[w][1][lane] = v ? __expf(lrelu(a.y + ald.y)) : 0.f;
        exsh[w][2][lane] = v ? __expf(lrelu(a.z + ald.z)) : 0.f;
        exsh[w][3][lane] = v ? __expf(lrelu(a.w + ald.w)) : 0.f;
        srcsh[w][lane] = src;
        __syncwarp();
        const float* eh = exsh[w][myh];
        int t = 0;
        for (; t + 4 <= deg; t += 4){
            float4 e  = *(const float4*)&eh[t];
            int4   s4 = *(const int4*)&srcsh[w][t];
            dn += e.x + e.y + e.z + e.w;
            agg_edge(acc, s4.x, e.x, lane);
            agg_edge(acc, s4.y, e.y, lane);
            agg_edge(acc, s4.z, e.z, lane);
            agg_edge(acc, s4.w, e.w, lane);
        }
        for (; t < deg; t++){
            float e = eh[t];
            dn += e;
            agg_edge(acc, srcsh[w][t], e, lane);
        }
    } else {
        // ---- generic path (deg > 32, rare) ----
        for (int base = beg; base < end; base += 32){
            int j = base + lane;
            int cnt = min(32, end - base);
            bool v = (j < end);
            int src = v ? g_csrc[j] : 0;
            float4 a = v ? ((const float4*)g_als)[src] : make_float4(0,0,0,0);
            exsh[w][0][lane] = v ? __expf(lrelu(a.x + ald.x)) : 0.f;
            exsh[w][1][lane] = v ? __expf(lrelu(a.y + ald.y)) : 0.f;
            exsh[w][2][lane] = v ? __expf(lrelu(a.z + ald.z)) : 0.f;
            exsh[w][3][lane] = v ? __expf(lrelu(a.w + ald.w)) : 0.f;
            srcsh[w][lane] = src;
            __syncwarp();
            const float* eh = exsh[w][myh];
            int t = 0;
            for (; t + 4 <= cnt; t += 4){
                float4 e  = *(const float4*)&eh[t];
                int4   s4 = *(const int4*)&srcsh[w][t];
                dn += e.x + e.y + e.z + e.w;
                agg_edge(acc, s4.x, e.x, lane);
                agg_edge(acc, s4.y, e.y, lane);
                agg_edge(acc, s4.z, e.z, lane);
                agg_edge(acc, s4.w, e.w, lane);
            }
            for (; t < cnt; t++){
                float e = eh[t];
                dn += e;
                agg_edge(acc, srcsh[w][t], e, lane);
            }
            __syncwarp();
        }
    }

    float inv = 1.f / dn;
    #pragma unroll
    for (int i = 0; i < 8; i++) acc[i] *= inv;
    // cross-head mean: lanes {l, l^8, l^16, l^24} hold same channel-in-head
    #pragma unroll
    for (int i = 0; i < 8; i++){
        acc[i] += __shfl_xor_sync(0xFFFFFFFFu, acc[i], 8);
        acc[i] += __shfl_xor_sync(0xFFFFFFFFu, acc[i], 16);
        acc[i] *= 0.25f;
    }
    int cih = (lane & 7) * 8;
    float4 b0 = *(const float4*)&bg[cih];
    float4 b1 = *(const float4*)&bg[cih+4];
    float v[8];
    v[0]=acc[0]+b0.x; v[1]=acc[1]+b0.y; v[2]=acc[2]+b0.z; v[3]=acc[3]+b0.w;
    v[4]=acc[4]+b1.x; v[5]=acc[5]+b1.y; v[6]=acc[6]+b1.z; v[7]=acc[7]+b1.w;
    float s = 0.f, q = 0.f;
    #pragma unroll
    for (int i = 0; i < 8; i++){ s += v[i]; q += v[i]*v[i]; }
    #pragma unroll
    for (int off = 4; off; off >>= 1){
        s += __shfl_xor_sync(0xFFFFFFFFu, s, off);
        q += __shfl_xor_sync(0xFFFFFFFFu, q, off);
    }
    float mu   = s * (1.f/64.f);
    float var  = q * (1.f/64.f) - mu*mu;
    float rstd = rsqrtf(var + 1e-5f);
    float aw = pa[0];
    if (lane < 8){
        float4 g0 = *(const float4*)&gam[cih],   g1 = *(const float4*)&gam[cih+4];
        float4 t0 = *(const float4*)&bet[cih],   t1 = *(const float4*)&bet[cih+4];
        float* xp = &g_x[(size_t)n*HD + cih];
        float4 x0 = *(const float4*)xp, x1 = *(const float4*)(xp+4);
        float xn;
        xn = (v[0]-mu)*rstd*g0.x + t0.x; x0.x += (xn>0.f? xn : aw*xn);
        xn = (v[1]-mu)*rstd*g0.y + t0.y; x0.y += (xn>0.f? xn : aw*xn);
        xn = (v[2]-mu)*rstd*g0.z + t0.z; x0.z += (xn>0.f? xn : aw*xn);
        xn = (v[3]-mu)*rstd*g0.w + t0.w; x0.w += (xn>0.f? xn : aw*xn);
        xn = (v[4]-mu)*rstd*g1.x + t1.x; x1.x += (xn>0.f? xn : aw*xn);
        xn = (v[5]-mu)*rstd*g1.y + t1.y; x1.y += (xn>0.f? xn : aw*xn);
        xn = (v[6]-mu)*rstd*g1.z + t1.z; x1.z += (xn>0.f? xn : aw*xn);
        xn = (v[7]-mu)*rstd*g1.w + t1.w; x1.w += (xn>0.f? xn : aw*xn);
        *(float4*)xp     = x0;
        *(float4*)(xp+4) = x1;
    }
}

// ---------------- final: z = x @ Wp + bp, L2-normalize rows (f32x2) ----------------
__global__ __launch_bounds__(256) void k_final(const float* __restrict__ Wp,
                                               const float* __restrict__ bp,
                                               float* __restrict__ out){
    __shared__ ull Wp2[32][64];
    __shared__ __align__(16) float xs[8][64];
    int t = threadIdx.x;
    for (int i = t; i < 2048; i += 256){
        int k2 = i >> 6, c = i & 63;
        Wp2[k2][c] = pack2(Wp[(2*k2)*64 + c], Wp[(2*k2+1)*64 + c]);
    }
    int nb = blockIdx.x*8;
    for (int i = t; i < 512; i += 256){
        int r = nb + (i >> 6);
        xs[i>>6][i&63] = (r < Nn) ? g_x[(size_t)r*HD + (i & 63)] : 0.f;
    }
    __syncthreads();
    int w = t >> 5, lane = t & 31;
    int n = nb + w;
    if (n >= Nn) return;
    int c0 = lane, c1 = lane + 32;
    ull z2a = 0, z2b = 0;
    #pragma unroll
    for (int k2 = 0; k2 < 32; k2++){
        ull xv = *(const ull*)&xs[w][2*k2];
        fma2(z2a, xv, Wp2[k2][c0]);
        fma2(z2b, xv, Wp2[k2][c1]);
    }
    float l0, h0, l1, h1;
    unpack2(z2a, l0, h0);
    unpack2(z2b, l1, h1);
    float z0 = l0 + h0 + bp[c0];
    float z1 = l1 + h1 + bp[c1];
    float q = z0*z0 + z1*z1;
    #pragma unroll
    for (int off = 16; off; off >>= 1) q += __shfl_xor_sync(0xFFFFFFFFu, q, off);
    float inv = 1.f / fmaxf(sqrtf(q), 1e-12f);
    out[(size_t)n*HD + c0] = z0*inv;
    out[(size_t)n*HD + c1] = z1*inv;
}

// ---------------- launch ----------------
extern "C" void kernel_launch(void* const* d_in, const int* in_sizes, int n_in,
                              void* d_out, int out_size){
    const float* feat = (const float*)d_in[0];
    const int*   ei   = (const int*)  d_in[1];
    const float* Wt   = (const float*)d_in[2];
    const float* bt   = (const float*)d_in[3];
    const float* Wp   = (const float*)d_in[4];
    const float* bp   = (const float*)d_in[5];

    k_lin1<<<(Nn + 63)/64, 256>>>(feat, Wt, bt);

    // CSR build (shared by both layers)
    k_zerodeg<<<(Nn + 255)/256, 256>>>();
    k_count  <<<(Et + 255)/256, 256>>>(ei);
    k_scanA  <<<49, 1024>>>();
    k_scanB  <<<1, 64>>>();
    k_scanC  <<<49, 1024>>>();
    k_scatter<<<(Et + 255)/256, 256>>>(ei);

    for (int l = 0; l < 2; l++){
        const float* Wg  = (const float*)d_in[6 + l*7 + 0];
        const float* as_ = (const float*)d_in[6 + l*7 + 1];
        const float* ad_ = (const float*)d_in[6 + l*7 + 2];
        const float* bg  = (const float*)d_in[6 + l*7 + 3];
        const float* gam = (const float*)d_in[6 + l*7 + 4];
        const float* bet = (const float*)d_in[6 + l*7 + 5];
        const float* pa  = (const float*)d_in[6 + l*7 + 6];

        k_gemm_h<<<1184, 256>>>(Wg);
        k_vsvd  <<<1, 256>>>(Wg, as_, ad_);
        k_als   <<<(Nn*32 + 255)/256, 256>>>();
        k_gat   <<<(Nn + 7)/8, 256>>>(bg, gam, bet, pa);
    }

    k_final<<<(Nn + 7)/8, 256>>>(Wp, bp, (float*)d_out);
}

// round 14
// speedup vs baseline: 2.4965x; 1.0246x over previous
#include <cuda_runtime.h>
#include <cuda_fp16.h>
#include <math_constants.h>

#define Nn 50000
#define Ee 800000
#define Et 850000
#define FD 512
#define HD 64
#define NH 4
#define HC 256   // NH*HD
#define L1B 782  // lin1 blocks = (Nn+63)/64

typedef unsigned long long ull;

// ---------------- scratch (device globals; no allocation) ----------------
__device__ float          g_x  [Nn*HD];   // current node features
__device__ unsigned short g_hh [Nn*HC];   // per-head transformed features (fp16 bits)
__device__ float          g_als[Nn*NH];   // attention logit (src part)
__device__ float          g_ald[Nn*NH];   // attention logit (dst part)
__device__ int   g_deg   [Nn];
__device__ int   g_rowptr[Nn+1];
__device__ int   g_cursor[Nn];
__device__ int   g_csrc  [Et];            // CSR (by dst) source node list
__device__ float g_vs[HD*NH];             // Wg-folded a_src: [k][h]
__device__ float g_vd[HD*NH];             // Wg-folded a_dst: [k][h]
__device__ int   g_bsum[64];

// ---------------- packed f32x2 helpers ----------------
__device__ __forceinline__ void fma2(ull& d, ull a, ull b){
    asm("fma.rn.f32x2 %0, %1, %2, %0;" : "+l"(d) : "l"(a), "l"(b));
}
__device__ __forceinline__ ull pack2(float lo, float hi){
    ull r; asm("mov.b64 %0, {%1, %2};" : "=l"(r) : "f"(lo), "f"(hi)); return r;
}
__device__ __forceinline__ void unpack2(ull v, float& lo, float& hi){
    asm("mov.b64 {%0, %1}, %2;" : "=f"(lo), "=f"(hi) : "l"(v));
}
__device__ __forceinline__ float2 h2f(unsigned w){
    __half2 h = *(__half2*)&w;
    return __half22float2(h);
}

// ---------------- CSR build ----------------
__global__ void k_zerodeg(){
    int i = blockIdx.x*blockDim.x + threadIdx.x;
    if (i < Nn) g_deg[i] = 0;
}

// ---------------- fused: lin1 GEMM (blocks < L1B) + edge count (rest) ----------------
__global__ __launch_bounds__(256) void k_lin1cnt(const float* __restrict__ A,
                                                 const float* __restrict__ W,
                                                 const float* __restrict__ bt,
                                                 const int*   __restrict__ ei){
    if (blockIdx.x >= L1B){
        int eid = (blockIdx.x - L1B)*256 + threadIdx.x;
        if (eid < Et){
            int d = (eid < Ee) ? ei[Ee + eid] : (eid - Ee);
            atomicAdd(&g_deg[d], 1);
        }
        return;
    }
    __shared__ __align__(16) float Ast[32][68];
    __shared__ __align__(16) float Bs [32][64];
    int t  = threadIdx.x;
    int rb = blockIdx.x*64;
    int ty = t >> 4, tx = t & 15;
    int ar = t >> 2;
    int ac = (t & 3) * 8;
    int br = t >> 3;
    int bc = (t & 7) * 8;
    ull c2[4][2] = {{0,0},{0,0},{0,0},{0,0}};

    for (int kb = 0; kb < FD; kb += 32){
        float4 a0 = {0,0,0,0}, a1 = {0,0,0,0};
        if (rb + ar < Nn){
            a0 = *(const float4*)&A[(size_t)(rb+ar)*FD + kb + ac];
            a1 = *(const float4*)&A[(size_t)(rb+ar)*FD + kb + ac + 4];
        }
        float4 b0 = *(const float4*)&W[(size_t)(kb+br)*64 + bc];
        float4 b1 = *(const float4*)&W[(size_t)(kb+br)*64 + bc + 4];
        __syncthreads();
        Ast[ac+0][ar]=a0.x; Ast[ac+1][ar]=a0.y; Ast[ac+2][ar]=a0.z; Ast[ac+3][ar]=a0.w;
        Ast[ac+4][ar]=a1.x; Ast[ac+5][ar]=a1.y; Ast[ac+6][ar]=a1.z; Ast[ac+7][ar]=a1.w;
        *(float4*)&Bs[br][bc]   = b0;
        *(float4*)&Bs[br][bc+4] = b1;
        __syncthreads();
        #pragma unroll
        for (int k = 0; k < 32; k++){
            float4 av = *(const float4*)&Ast[k][ty*4];
            ulonglong2 bv = *(const ulonglong2*)&Bs[k][tx*4];
            ull ax = pack2(av.x, av.x);
            ull ay = pack2(av.y, av.y);
            ull az = pack2(av.z, av.z);
            ull aw = pack2(av.w, av.w);
            fma2(c2[0][0], ax, bv.x); fma2(c2[0][1], ax, bv.y);
            fma2(c2[1][0], ay, bv.x); fma2(c2[1][1], ay, bv.y);
            fma2(c2[2][0], az, bv.x); fma2(c2[2][1], az, bv.y);
            fma2(c2[3][0], aw, bv.x); fma2(c2[3][1], aw, bv.y);
        }
    }
    float bt0 = bt[tx*4+0], bt1 = bt[tx*4+1], bt2 = bt[tx*4+2], bt3 = bt[tx*4+3];
    int r0 = rb + ty*4;
    #pragma unroll
    for (int i = 0; i < 4; i++){
        int r = r0 + i;
        if (r < Nn){
            float v0,v1,v2,v3;
            unpack2(c2[i][0], v0, v1);
            unpack2(c2[i][1], v2, v3);
            float* o = &g_x[(size_t)r*HD + tx*4];
            o[0] = v0 + bt0; o[1] = v1 + bt1;
            o[2] = v2 + bt2; o[3] = v3 + bt3;
        }
    }
}

__global__ __launch_bounds__(1024) void k_scanA(){
    __shared__ int sh[1024];
    int t   = threadIdx.x;
    int gid = blockIdx.x*1024 + t;
    int v = (gid < Nn) ? g_deg[gid] : 0;
    sh[t] = v; __syncthreads();
    #pragma unroll
    for (int off = 1; off < 1024; off <<= 1){
        int u = (t >= off) ? sh[t-off] : 0;
        __syncthreads();
        sh[t] += u;
        __syncthreads();
    }
    if (gid < Nn) g_rowptr[gid] = sh[t] - v;
    if (t == 1023) g_bsum[blockIdx.x] = sh[1023];
}
// scanC with inlined block-offset computation (one warp reduces 49 bsum entries)
__global__ __launch_bounds__(1024) void k_scanC(){
    __shared__ int s_off;
    int t = threadIdx.x;
    if (t < 32){
        int b = blockIdx.x;
        int v = 0;
        if (t      < b) v  = g_bsum[t];
        if (t + 32 < b) v += g_bsum[t + 32];
        #pragma unroll
        for (int off = 16; off; off >>= 1)
            v += __shfl_xor_sync(0xFFFFFFFFu, v, off);
        if (t == 0) s_off = v;
    }
    __syncthreads();
    int gid = blockIdx.x*1024 + t;
    if (gid < Nn){
        int r = g_rowptr[gid] + s_off;
        g_rowptr[gid] = r;
        g_cursor[gid] = r;
    }
    if (gid == 0) g_rowptr[Nn] = Et;
}
__global__ void k_scatter(const int* __restrict__ ei){
    int eid = blockIdx.x*blockDim.x + threadIdx.x;
    if (eid >= Et) return;
    int s, d;
    if (eid < Ee){ s = ei[eid]; d = ei[Ee + eid]; } else { s = d = eid - Ee; }
    int pos = atomicAdd(&g_cursor[d], 1);
    g_csrc[pos] = s;
}

// ---------------- h = x @ Wg  (50000x64 @ 64x256), f32x2, fp16 output ----------------
__global__ __launch_bounds__(256) void k_gemm_h(const float* __restrict__ W){
    int j = threadIdx.x;
    ull w2[32];
    #pragma unroll
    for (int k2 = 0; k2 < 32; k2++)
        w2[k2] = pack2(W[(2*k2)*256 + j], W[(2*k2+1)*256 + j]);
    __shared__ __align__(16) float xs[4][64];
    for (int rb = blockIdx.x*4; rb < Nn; rb += gridDim.x*4){
        int r = rb + (j >> 6);
        float xv = (r < Nn) ? g_x[(size_t)r*HD + (j & 63)] : 0.f;
        __syncthreads();
        xs[j>>6][j&63] = xv;
        __syncthreads();
        ull a2[4] = {0,0,0,0};
        #pragma unroll
        for (int k4 = 0; k4 < 16; k4++){
            ulonglong2 x0 = *(const ulonglong2*)&xs[0][k4*4];
            ulonglong2 x1 = *(const ulonglong2*)&xs[1][k4*4];
            ulonglong2 x2 = *(const ulonglong2*)&xs[2][k4*4];
            ulonglong2 x3 = *(const ulonglong2*)&xs[3][k4*4];
            fma2(a2[0], x0.x, w2[k4*2]); fma2(a2[0], x0.y, w2[k4*2+1]);
            fma2(a2[1], x1.x, w2[k4*2]); fma2(a2[1], x1.y, w2[k4*2+1]);
            fma2(a2[2], x2.x, w2[k4*2]); fma2(a2[2], x2.y, w2[k4*2+1]);
            fma2(a2[3], x3.x, w2[k4*2]); fma2(a2[3], x3.y, w2[k4*2+1]);
        }
        #pragma unroll
        for (int i = 0; i < 4; i++){
            if (rb+i < Nn){
                float lo, hi; unpack2(a2[i], lo, hi);
                __half b = __float2half_rn(lo + hi);
                g_hh[(size_t)(rb+i)*HC + j] = *(unsigned short*)&b;
            }
        }
    }
}

// ---------------- fold attention vectors through Wg ----------------
__global__ void k_vsvd(const float* __restrict__ Wg,
                       const float* __restrict__ as_,
                       const float* __restrict__ ad_){
    int t = threadIdx.x;
    int k = t >> 2, h = t & 3;
    float ss = 0.f, sd = 0.f;
    const float* wrow = &Wg[k*HC + h*HD];
    const float* av   = &as_[h*HD];
    const float* bv   = &ad_[h*HD];
    #pragma unroll 16
    for (int c = 0; c < HD; c++){
        float w = wrow[c];
        ss += w * av[c];
        sd += w * bv[c];
    }
    g_vs[k*NH + h] = ss;
    g_vd[k*NH + h] = sd;
}

// ---------------- als/ald = x @ Vs / x @ Vd ----------------
__global__ __launch_bounds__(256) void k_als(){
    int n    = (blockIdx.x*blockDim.x + threadIdx.x) >> 5;
    int lane = threadIdx.x & 31;
    if (n >= Nn) return;
    float x0 = g_x[(size_t)n*HD + lane];
    float x1 = g_x[(size_t)n*HD + lane + 32];
    float4 v0 = ((const float4*)g_vs)[lane];
    float4 v1 = ((const float4*)g_vs)[lane+32];
    float4 d0 = ((const float4*)g_vd)[lane];
    float4 d1 = ((const float4*)g_vd)[lane+32];
    float s[4], d[4];
    s[0] = x0*v0.x + x1*v1.x; s[1] = x0*v0.y + x1*v1.y;
    s[2] = x0*v0.z + x1*v1.z; s[3] = x0*v0.w + x1*v1.w;
    d[0] = x0*d0.x + x1*d1.x; d[1] = x0*d0.y + x1*d1.y;
    d[2] = x0*d0.z + x1*d1.z; d[3] = x0*d0.w + x1*d1.w;
    #pragma unroll
    for (int off = 16; off; off >>= 1){
        #pragma unroll
        for (int h = 0; h < 4; h++){
            s[h] += __shfl_xor_sync(0xFFFFFFFFu, s[h], off);
            d[h] += __shfl_xor_sync(0xFFFFFFFFu, d[h], off);
        }
    }
    if (lane == 0){
        ((float4*)g_als)[n] = make_float4(s[0], s[1], s[2], s[3]);
        ((float4*)g_ald)[n] = make_float4(d[0], d[1], d[2], d[3]);
    }
}

__device__ __forceinline__ float lrelu(float v){ return v > 0.f ? v : 0.2f*v; }

__device__ __forceinline__ uint4 ldh(int src, int lane){
    return *(const uint4*)&g_hh[(size_t)src*HC + lane*8];
}
__device__ __forceinline__ void fmah(float* acc, uint4 p, float e){
    float2 c0 = h2f(p.x), c1 = h2f(p.y), c2 = h2f(p.z), c3 = h2f(p.w);
    acc[0] += e*c0.x; acc[1] += e*c0.y;
    acc[2] += e*c1.x; acc[3] += e*c1.y;
    acc[4] += e*c2.x; acc[5] += e*c2.y;
    acc[6] += e*c3.x; acc[7] += e*c3.y;
}

// ---------------- fused GAT (no segment-max; 8-edge batched gathers) ----------------
__global__ __launch_bounds__(256) void k_gat(const float* __restrict__ bg,
                                             const float* __restrict__ gam,
                                             const float* __restrict__ bet,
                                             const float* __restrict__ pa){
    __shared__ __align__(16) float exsh [8][NH][32];
    __shared__ __align__(16) int   srcsh[8][32];
    int w    = threadIdx.x >> 5;
    int lane = threadIdx.x & 31;
    int n    = blockIdx.x*8 + w;
    if (n >= Nn) return;
    int beg = g_rowptr[n], end = g_rowptr[n+1];
    int deg = end - beg;
    float4 ald = ((const float4*)g_ald)[n];
    int myh = lane >> 3;

    float acc[8] = {0,0,0,0,0,0,0,0};
    float dn = 0.f;

    if (deg <= 32){
        // ---- fast path: one chunk ----
        int j = beg + lane;
        bool v = (j < end);
        int src = v ? g_csrc[j] : 0;
        float4 a = v ? ((const float4*)g_als)[src] : make_float4(0,0,0,0);
        exsh[w][0][lane] = v ? __expf(lrelu(a.x + ald.x)) : 0.f;
        exsh[w][1][lane] = v ? __expf(lrelu(a.y + ald.y)) : 0.f;
        exsh[w][2][lane] = v ? __expf(lrelu(a.z + ald.z)) : 0.f;
        exsh[w][3][lane] = v ? __expf(lrelu(a.w + ald.w)) : 0.f;
        srcsh[w][lane] = src;
        __syncwarp();
        const float* eh = exsh[w][myh];
        int t = 0;
        for (; t + 8 <= deg; t += 8){
            float4 ea = *(const float4*)&eh[t];
            float4 eb = *(const float4*)&eh[t+4];
            int4   sa = *(const int4*)&srcsh[w][t];
            int4   sb = *(const int4*)&srcsh[w][t+4];
            uint4 p0 = ldh(sa.x, lane), p1 = ldh(sa.y, lane);
            uint4 p2 = ldh(sa.z, lane), p3 = ldh(sa.w, lane);
            uint4 p4 = ldh(sb.x, lane), p5 = ldh(sb.y, lane);
            uint4 p6 = ldh(sb.z, lane), p7 = ldh(sb.w, lane);
            dn += (ea.x + ea.y + ea.z + ea.w) + (eb.x + eb.y + eb.z + eb.w);
            fmah(acc, p0, ea.x); fmah(acc, p1, ea.y);
            fmah(acc, p2, ea.z); fmah(acc, p3, ea.w);
            fmah(acc, p4, eb.x); fmah(acc, p5, eb.y);
            fmah(acc, p6, eb.z); fmah(acc, p7, eb.w);
        }
        for (; t + 4 <= deg; t += 4){
            float4 ea = *(const float4*)&eh[t];
            int4   sa = *(const int4*)&srcsh[w][t];
            uint4 p0 = ldh(sa.x, lane), p1 = ldh(sa.y, lane);
            uint4 p2 = ldh(sa.z, lane), p3 = ldh(sa.w, lane);
            dn += ea.x + ea.y + ea.z + ea.w;
            fmah(acc, p0, ea.x); fmah(acc, p1, ea.y);
            fmah(acc, p2, ea.z); fmah(acc, p3, ea.w);
        }
        for (; t < deg; t++){
            float e = eh[t];
            dn += e;
            fmah(acc, ldh(srcsh[w][t], lane), e);
        }
    } else {
        // ---- generic path (deg > 32, rare) ----
        for (int base = beg; base < end; base += 32){
            int j = base + lane;
            int cnt = min(32, end - base);
            bool v = (j < end);
            int src = v ? g_csrc[j] : 0;
            float4 a = v ? ((const float4*)g_als)[src] : make_float4(0,0,0,0);
            exsh[w][0][lane] = v ? __expf(lrelu(a.x + ald.x)) : 0.f;
            exsh[w][1][lane] = v ? __expf(lrelu(a.y + ald.y)) : 0.f;
            exsh[w][2][lane] = v ? __expf(lrelu(a.z + ald.z)) : 0.f;
            exsh[w][3][lane] = v ? __expf(lrelu(a.w + ald.w)) : 0.f;
            srcsh[w][lane] = src;
            __syncwarp();
            const float* eh = exsh[w][myh];
            int t = 0;
            for (; t + 8 <= cnt; t += 8){
                float4 ea = *(const float4*)&eh[t];
                float4 eb = *(const float4*)&eh[t+4];
                int4   sa = *(const int4*)&srcsh[w][t];
                int4   sb = *(const int4*)&srcsh[w][t+4];
                uint4 p0 = ldh(sa.x, lane), p1 = ldh(sa.y, lane);
                uint4 p2 = ldh(sa.z, lane), p3 = ldh(sa.w, lane);
                uint4 p4 = ldh(sb.x, lane), p5 = ldh(sb.y, lane);
                uint4 p6 = ldh(sb.z, lane), p7 = ldh(sb.w, lane);
                dn += (ea.x + ea.y + ea.z + ea.w) + (eb.x + eb.y + eb.z + eb.w);
                fmah(acc, p0, ea.x); fmah(acc, p1, ea.y);
                fmah(acc, p2, ea.z); fmah(acc, p3, ea.w);
                fmah(acc, p4, eb.x); fmah(acc, p5, eb.y);
                fmah(acc, p6, eb.z); fmah(acc, p7, eb.w);
            }
            for (; t + 4 <= cnt; t += 4){
                float4 ea = *(const float4*)&eh[t];
                int4   sa = *(const int4*)&srcsh[w][t];
                uint4 p0 = ldh(sa.x, lane), p1 = ldh(sa.y, lane);
                uint4 p2 = ldh(sa.z, lane), p3 = ldh(sa.w, lane);
                dn += ea.x + ea.y + ea.z + ea.w;
                fmah(acc, p0, ea.x); fmah(acc, p1, ea.y);
                fmah(acc, p2, ea.z); fmah(acc, p3, ea.w);
            }
            for (; t < cnt; t++){
                float e = eh[t];
                dn += e;
                fmah(acc, ldh(srcsh[w][t], lane), e);
            }
            __syncwarp();
        }
    }

    float inv = 1.f / dn;
    #pragma unroll
    for (int i = 0; i < 8; i++) acc[i] *= inv;
    // cross-head mean: lanes {l, l^8, l^16, l^24} hold same channel-in-head
    #pragma unroll
    for (int i = 0; i < 8; i++){
        acc[i] += __shfl_xor_sync(0xFFFFFFFFu, acc[i], 8);
        acc[i] += __shfl_xor_sync(0xFFFFFFFFu, acc[i], 16);
        acc[i] *= 0.25f;
    }
    int cih = (lane & 7) * 8;
    float4 b0 = *(const float4*)&bg[cih];
    float4 b1 = *(const float4*)&bg[cih+4];
    float v[8];
    v[0]=acc[0]+b0.x; v[1]=acc[1]+b0.y; v[2]=acc[2]+b0.z; v[3]=acc[3]+b0.w;
    v[4]=acc[4]+b1.x; v[5]=acc[5]+b1.y; v[6]=acc[6]+b1.z; v[7]=acc[7]+b1.w;
    float s = 0.f, q = 0.f;
    #pragma unroll
    for (int i = 0; i < 8; i++){ s += v[i]; q += v[i]*v[i]; }
    #pragma unroll
    for (int off = 4; off; off >>= 1){
        s += __shfl_xor_sync(0xFFFFFFFFu, s, off);
        q += __shfl_xor_sync(0xFFFFFFFFu, q, off);
    }
    float mu   = s * (1.f/64.f);
    float var  = q * (1.f/64.f) - mu*mu;
    float rstd = rsqrtf(var + 1e-5f);
    float aw = pa[0];
    if (lane < 8){
        float4 g0 = *(const float4*)&gam[cih],   g1 = *(const float4*)&gam[cih+4];
        float4 t0 = *(const float4*)&bet[cih],   t1 = *(const float4*)&bet[cih+4];
        float* xp = &g_x[(size_t)n*HD + cih];
        float4 x0 = *(const float4*)xp, x1 = *(const float4*)(xp+4);
        float xn;
        xn = (v[0]-mu)*rstd*g0.x + t0.x; x0.x += (xn>0.f? xn : aw*xn);
        xn = (v[1]-mu)*rstd*g0.y + t0.y; x0.y += (xn>0.f? xn : aw*xn);
        xn = (v[2]-mu)*rstd*g0.z + t0.z; x0.z += (xn>0.f? xn : aw*xn);
        xn = (v[3]-mu)*rstd*g0.w + t0.w; x0.w += (xn>0.f? xn : aw*xn);
        xn = (v[4]-mu)*rstd*g1.x + t1.x; x1.x += (xn>0.f? xn : aw*xn);
        xn = (v[5]-mu)*rstd*g1.y + t1.y; x1.y += (xn>0.f? xn : aw*xn);
        xn = (v[6]-mu)*rstd*g1.z + t1.z; x1.z += (xn>0.f? xn : aw*xn);
        xn = (v[7]-mu)*rstd*g1.w + t1.w; x1.w += (xn>0.f? xn : aw*xn);
        *(float4*)xp     = x0;
        *(float4*)(xp+4) = x1;
    }
}

// ---------------- final: z = x @ Wp + bp, L2-normalize rows (f32x2) ----------------
__global__ __launch_bounds__(256) void k_final(const float* __restrict__ Wp,
                                               const float* __restrict__ bp,
                                               float* __restrict__ out){
    __shared__ ull Wp2[32][64];
    __shared__ __align__(16) float xs[8][64];
    int t = threadIdx.x;
    for (int i = t; i < 2048; i += 256){
        int k2 = i >> 6, c = i & 63;
        Wp2[k2][c] = pack2(Wp[(2*k2)*64 + c], Wp[(2*k2+1)*64 + c]);
    }
    int nb = blockIdx.x*8;
    for (int i = t; i < 512; i += 256){
        int r = nb + (i >> 6);
        xs[i>>6][i&63] = (r < Nn) ? g_x[(size_t)r*HD + (i & 63)] : 0.f;
    }
    __syncthreads();
    int w = t >> 5, lane = t & 31;
    int n = nb + w;
    if (n >= Nn) return;
    int c0 = lane, c1 = lane + 32;
    ull z2a = 0, z2b = 0;
    #pragma unroll
    for (int k2 = 0; k2 < 32; k2++){
        ull xv = *(const ull*)&xs[w][2*k2];
        fma2(z2a, xv, Wp2[k2][c0]);
        fma2(z2b, xv, Wp2[k2][c1]);
    }
    float l0, h0, l1, h1;
    unpack2(z2a, l0, h0);
    unpack2(z2b, l1, h1);
    float z0 = l0 + h0 + bp[c0];
    float z1 = l1 + h1 + bp[c1];
    float q = z0*z0 + z1*z1;
    #pragma unroll
    for (int off = 16; off; off >>= 1) q += __shfl_xor_sync(0xFFFFFFFFu, q, off);
    float inv = 1.f / fmaxf(sqrtf(q), 1e-12f);
    out[(size_t)n*HD + c0] = z0*inv;
    out[(size_t)n*HD + c1] = z1*inv;
}

// ---------------- launch ----------------
extern "C" void kernel_launch(void* const* d_in, const int* in_sizes, int n_in,
                              void* d_out, int out_size){
    const float* feat = (const float*)d_in[0];
    const int*   ei   = (const int*)  d_in[1];
    const float* Wt   = (const float*)d_in[2];
    const float* bt   = (const float*)d_in[3];
    const float* Wp   = (const float*)d_in[4];
    const float* bp   = (const float*)d_in[5];

    k_zerodeg<<<(Nn + 255)/256, 256>>>();
    k_lin1cnt<<<L1B + (Et + 255)/256, 256>>>(feat, Wt, bt, ei);
    k_scanA  <<<49, 1024>>>();
    k_scanC  <<<49, 1024>>>();
    k_scatter<<<(Et + 255)/256, 256>>>(ei);

    for (int l = 0; l < 2; l++){
        const float* Wg  = (const float*)d_in[6 + l*7 + 0];
        const float* as_ = (const float*)d_in[6 + l*7 + 1];
        const float* ad_ = (const float*)d_in[6 + l*7 + 2];
        const float* bg  = (const float*)d_in[6 + l*7 + 3];
        const float* gam = (const float*)d_in[6 + l*7 + 4];
        const float* bet = (const float*)d_in[6 + l*7 + 5];
        const float* pa  = (const float*)d_in[6 + l*7 + 6];

        k_gemm_h<<<1184, 256>>>(Wg);
        k_vsvd  <<<1, 256>>>(Wg, as_, ad_);
        k_als   <<<(Nn*32 + 255)/256, 256>>>();
        k_gat   <<<(Nn + 7)/8, 256>>>(bg, gam, bet, pa);
    }

    k_final<<<(Nn + 7)/8, 256>>>(Wp, bp, (float*)d_out);
}

// round 15
// speedup vs baseline: 2.5195x; 1.0092x over previous
#include <cuda_runtime.h>
#include <cuda_fp16.h>
#include <math_constants.h>

#define Nn 50000
#define Ee 800000
#define Et 850000
#define FD 512
#define HD 64
#define NH 4
#define HC 256   // NH*HD
#define L1B 782  // lin1 blocks = (Nn+63)/64

typedef unsigned long long ull;

// ---------------- scratch (device globals; no allocation) ----------------
__device__ float          g_x  [Nn*HD];   // current node features
__device__ unsigned short g_hh [Nn*HC];   // per-head transformed features (fp16 bits)
__device__ float          g_als[Nn*NH];   // attention logit (src part)
__device__ float          g_ald[Nn*NH];   // attention logit (dst part)
__device__ float          g_e  [Et*NH];   // per-edge exp values (CSR order)
__device__ int   g_deg   [Nn];
__device__ int   g_rowptr[Nn+1];
__device__ int   g_cursor[Nn];
__device__ int   g_csrc  [Et];            // CSR (by dst) source node list
__device__ int   g_cdst  [Et];            // CSR dst (row) per edge
__device__ int   g_bsum[64];

// ---------------- packed f32x2 helpers ----------------
__device__ __forceinline__ void fma2(ull& d, ull a, ull b){
    asm("fma.rn.f32x2 %0, %1, %2, %0;" : "+l"(d) : "l"(a), "l"(b));
}
__device__ __forceinline__ ull pack2(float lo, float hi){
    ull r; asm("mov.b64 %0, {%1, %2};" : "=l"(r) : "f"(lo), "f"(hi)); return r;
}
__device__ __forceinline__ void unpack2(ull v, float& lo, float& hi){
    asm("mov.b64 {%0, %1}, %2;" : "=f"(lo), "=f"(hi) : "l"(v));
}
__device__ __forceinline__ float2 h2f(unsigned w){
    __half2 h = *(__half2*)&w;
    return __half22float2(h);
}

// ---------------- CSR build ----------------
__global__ void k_zerodeg(){
    int i = blockIdx.x*blockDim.x + threadIdx.x;
    if (i < Nn) g_deg[i] = 0;
}

// ---------------- fused: lin1 GEMM (blocks < L1B) + edge count (rest) ----------------
__global__ __launch_bounds__(256) void k_lin1cnt(const float* __restrict__ A,
                                                 const float* __restrict__ W,
                                                 const float* __restrict__ bt,
                                                 const int*   __restrict__ ei){
    if (blockIdx.x >= L1B){
        int eid = (blockIdx.x - L1B)*256 + threadIdx.x;
        if (eid < Et){
            int d = (eid < Ee) ? ei[Ee + eid] : (eid - Ee);
            atomicAdd(&g_deg[d], 1);
        }
        return;
    }
    __shared__ __align__(16) float Ast[32][68];
    __shared__ __align__(16) float Bs [32][64];
    int t  = threadIdx.x;
    int rb = blockIdx.x*64;
    int ty = t >> 4, tx = t & 15;
    int ar = t >> 2;
    int ac = (t & 3) * 8;
    int br = t >> 3;
    int bc = (t & 7) * 8;
    ull c2[4][2] = {{0,0},{0,0},{0,0},{0,0}};

    for (int kb = 0; kb < FD; kb += 32){
        float4 a0 = {0,0,0,0}, a1 = {0,0,0,0};
        if (rb + ar < Nn){
            a0 = *(const float4*)&A[(size_t)(rb+ar)*FD + kb + ac];
            a1 = *(const float4*)&A[(size_t)(rb+ar)*FD + kb + ac + 4];
        }
        float4 b0 = *(const float4*)&W[(size_t)(kb+br)*64 + bc];
        float4 b1 = *(const float4*)&W[(size_t)(kb+br)*64 + bc + 4];
        __syncthreads();
        Ast[ac+0][ar]=a0.x; Ast[ac+1][ar]=a0.y; Ast[ac+2][ar]=a0.z; Ast[ac+3][ar]=a0.w;
        Ast[ac+4][ar]=a1.x; Ast[ac+5][ar]=a1.y; Ast[ac+6][ar]=a1.z; Ast[ac+7][ar]=a1.w;
        *(float4*)&Bs[br][bc]   = b0;
        *(float4*)&Bs[br][bc+4] = b1;
        __syncthreads();
        #pragma unroll
        for (int k = 0; k < 32; k++){
            float4 av = *(const float4*)&Ast[k][ty*4];
            ulonglong2 bv = *(const ulonglong2*)&Bs[k][tx*4];
            ull ax = pack2(av.x, av.x);
            ull ay = pack2(av.y, av.y);
            ull az = pack2(av.z, av.z);
            ull aw = pack2(av.w, av.w);
            fma2(c2[0][0], ax, bv.x); fma2(c2[0][1], ax, bv.y);
            fma2(c2[1][0], ay, bv.x); fma2(c2[1][1], ay, bv.y);
            fma2(c2[2][0], az, bv.x); fma2(c2[2][1], az, bv.y);
            fma2(c2[3][0], aw, bv.x); fma2(c2[3][1], aw, bv.y);
        }
    }
    float bt0 = bt[tx*4+0], bt1 = bt[tx*4+1], bt2 = bt[tx*4+2], bt3 = bt[tx*4+3];
    int r0 = rb + ty*4;
    #pragma unroll
    for (int i = 0; i < 4; i++){
        int r = r0 + i;
        if (r < Nn){
            float v0,v1,v2,v3;
            unpack2(c2[i][0], v0, v1);
            unpack2(c2[i][1], v2, v3);
            float* o = &g_x[(size_t)r*HD + tx*4];
            o[0] = v0 + bt0; o[1] = v1 + bt1;
            o[2] = v2 + bt2; o[3] = v3 + bt3;
        }
    }
}

__global__ __launch_bounds__(1024) void k_scanA(){
    __shared__ int sh[1024];
    int t   = threadIdx.x;
    int gid = blockIdx.x*1024 + t;
    int v = (gid < Nn) ? g_deg[gid] : 0;
    sh[t] = v; __syncthreads();
    #pragma unroll
    for (int off = 1; off < 1024; off <<= 1){
        int u = (t >= off) ? sh[t-off] : 0;
        __syncthreads();
        sh[t] += u;
        __syncthreads();
    }
    if (gid < Nn) g_rowptr[gid] = sh[t] - v;
    if (t == 1023) g_bsum[blockIdx.x] = sh[1023];
}
__global__ __launch_bounds__(1024) void k_scanC(){
    __shared__ int s_off;
    int t = threadIdx.x;
    if (t < 32){
        int b = blockIdx.x;
        int v = 0;
        if (t      < b) v  = g_bsum[t];
        if (t + 32 < b) v += g_bsum[t + 32];
        #pragma unroll
        for (int off = 16; off; off >>= 1)
            v += __shfl_xor_sync(0xFFFFFFFFu, v, off);
        if (t == 0) s_off = v;
    }
    __syncthreads();
    int gid = blockIdx.x*1024 + t;
    if (gid < Nn){
        int r = g_rowptr[gid] + s_off;
        g_rowptr[gid] = r;
        g_cursor[gid] = r;
    }
    if (gid == 0) g_rowptr[Nn] = Et;
}
__global__ void k_scatter(const int* __restrict__ ei){
    int eid = blockIdx.x*blockDim.x + threadIdx.x;
    if (eid >= Et) return;
    int s, d;
    if (eid < Ee){ s = ei[eid]; d = ei[Ee + eid]; } else { s = d = eid - Ee; }
    int pos = atomicAdd(&g_cursor[d], 1);
    g_csrc[pos] = s;
    g_cdst[pos] = d;
}

// ---------------- h = x @ Wg (fp16 out) + fused als/ald epilogue ----------------
__global__ __launch_bounds__(256) void k_gemm_h(const float* __restrict__ W,
                                                const float* __restrict__ as_,
                                                const float* __restrict__ ad_){
    int j = threadIdx.x;
    int wrp = j >> 5, lane = j & 31;
    ull w2[32];
    #pragma unroll
    for (int k2 = 0; k2 < 32; k2++)
        w2[k2] = pack2(W[(2*k2)*256 + j], W[(2*k2+1)*256 + j]);
    float asj = as_[j];   // a_src flattened [h*64+c] == column j
    float adj = ad_[j];
    __shared__ __align__(16) float xs[4][64];
    __shared__ float wps[4][8], wpd[4][8];
    for (int rb = blockIdx.x*4; rb < Nn; rb += gridDim.x*4){
        int r = rb + (j >> 6);
        float xv = (r < Nn) ? g_x[(size_t)r*HD + (j & 63)] : 0.f;
        __syncthreads();
        xs[j>>6][j&63] = xv;
        __syncthreads();
        ull a2[4] = {0,0,0,0};
        #pragma unroll
        for (int k4 = 0; k4 < 16; k4++){
            ulonglong2 x0 = *(const ulonglong2*)&xs[0][k4*4];
            ulonglong2 x1 = *(const ulonglong2*)&xs[1][k4*4];
            ulonglong2 x2 = *(const ulonglong2*)&xs[2][k4*4];
            ulonglong2 x3 = *(const ulonglong2*)&xs[3][k4*4];
            fma2(a2[0], x0.x, w2[k4*2]); fma2(a2[0], x0.y, w2[k4*2+1]);
            fma2(a2[1], x1.x, w2[k4*2]); fma2(a2[1], x1.y, w2[k4*2+1]);
            fma2(a2[2], x2.x, w2[k4*2]); fma2(a2[2], x2.y, w2[k4*2+1]);
            fma2(a2[3], x3.x, w2[k4*2]); fma2(a2[3], x3.y, w2[k4*2+1]);
        }
        float hv[4];
        #pragma unroll
        for (int i = 0; i < 4; i++){
            float lo, hi; unpack2(a2[i], lo, hi);
            hv[i] = lo + hi;
            if (rb+i < Nn){
                __half b = __float2half_rn(hv[i]);
                g_hh[(size_t)(rb+i)*HC + j] = *(unsigned short*)&b;
            }
        }
        // fused attention-logit reduction: als[r][h] = sum_c h[r][h*64+c]*a_src[h][c]
        float ps[4], pd[4];
        #pragma unroll
        for (int i = 0; i < 4; i++){ ps[i] = hv[i]*asj; pd[i] = hv[i]*adj; }
        #pragma unroll
        for (int off = 16; off; off >>= 1){
            #pragma unroll
            for (int i = 0; i < 4; i++){
                ps[i] += __shfl_xor_sync(0xFFFFFFFFu, ps[i], off);
                pd[i] += __shfl_xor_sync(0xFFFFFFFFu, pd[i], off);
            }
        }
        if (lane == 0){
            #pragma unroll
            for (int i = 0; i < 4; i++){ wps[i][wrp] = ps[i]; wpd[i][wrp] = pd[i]; }
        }
        __syncthreads();
        if (j < 16){
            int i = j >> 2, h = j & 3;
            int r2 = rb + i;
            if (r2 < Nn){
                g_als[r2*4 + h] = wps[i][2*h] + wps[i][2*h+1];
                g_ald[r2*4 + h] = wpd[i][2*h] + wpd[i][2*h+1];
            }
        }
    }
}

__device__ __forceinline__ float lrelu(float v){ return v > 0.f ? v : 0.2f*v; }

// ---------------- per-edge exp in CSR order (fully parallel) ----------------
__global__ __launch_bounds__(256) void k_edge(){
    int j = blockIdx.x*blockDim.x + threadIdx.x;
    if (j >= Et) return;
    int s = g_csrc[j], d = g_cdst[j];
    float4 a = ((const float4*)g_als)[s];
    float4 b = ((const float4*)g_ald)[d];
    float4 e;
    e.x = __expf(lrelu(a.x + b.x));
    e.y = __expf(lrelu(a.y + b.y));
    e.z = __expf(lrelu(a.z + b.z));
    e.w = __expf(lrelu(a.w + b.w));
    ((float4*)g_e)[j] = e;
}

__device__ __forceinline__ uint4 ldh(int src, int lane){
    return *(const uint4*)&g_hh[(size_t)src*HC + lane*8];
}
__device__ __forceinline__ void fmah(float* acc, uint4 p, float e){
    float2 c0 = h2f(p.x), c1 = h2f(p.y), c2 = h2f(p.z), c3 = h2f(p.w);
    acc[0] += e*c0.x; acc[1] += e*c0.y;
    acc[2] += e*c1.x; acc[3] += e*c1.y;
    acc[4] += e*c2.x; acc[5] += e*c2.y;
    acc[6] += e*c3.x; acc[7] += e*c3.y;
}

// ---------------- fused GAT: pure gather + FMA (ex precomputed) ----------------
__global__ __launch_bounds__(256) void k_gat(const float* __restrict__ bg,
                                             const float* __restrict__ gam,
                                             const float* __restrict__ bet,
                                             const float* __restrict__ pa){
    __shared__ __align__(16) float exsh [8][NH][32];
    __shared__ __align__(16) int   srcsh[8][32];
    int w    = threadIdx.x >> 5;
    int lane = threadIdx.x & 31;
    int n    = blockIdx.x*8 + w;
    if (n >= Nn) return;
    int beg = g_rowptr[n], end = g_rowptr[n+1];
    int deg = end - beg;
    int myh = lane >> 3;

    float acc[8] = {0,0,0,0,0,0,0,0};
    float dn = 0.f;

    if (deg <= 32){
        // ---- fast path: one chunk; csrc and e loads issue in parallel ----
        int j = beg + lane;
        bool v = (j < end);
        int src   = v ? g_csrc[j] : 0;
        float4 e4 = v ? ((const float4*)g_e)[j] : make_float4(0,0,0,0);
        srcsh[w][lane] = src;
        exsh[w][0][lane] = e4.x;
        exsh[w][1][lane] = e4.y;
        exsh[w][2][lane] = e4.z;
        exsh[w][3][lane] = e4.w;
        __syncwarp();
        const float* eh = exsh[w][myh];
        int t = 0;
        for (; t + 8 <= deg; t += 8){
            float4 ea = *(const float4*)&eh[t];
            float4 eb = *(const float4*)&eh[t+4];
            int4   sa = *(const int4*)&srcsh[w][t];
            int4   sb = *(const int4*)&srcsh[w][t+4];
            uint4 p0 = ldh(sa.x, lane), p1 = ldh(sa.y, lane);
            uint4 p2 = ldh(sa.z, lane), p3 = ldh(sa.w, lane);
            uint4 p4 = ldh(sb.x, lane), p5 = ldh(sb.y, lane);
            uint4 p6 = ldh(sb.z, lane), p7 = ldh(sb.w, lane);
            dn += (ea.x + ea.y + ea.z + ea.w) + (eb.x + eb.y + eb.z + eb.w);
            fmah(acc, p0, ea.x); fmah(acc, p1, ea.y);
            fmah(acc, p2, ea.z); fmah(acc, p3, ea.w);
            fmah(acc, p4, eb.x); fmah(acc, p5, eb.y);
            fmah(acc, p6, eb.z); fmah(acc, p7, eb.w);
        }
        for (; t + 4 <= deg; t += 4){
            float4 ea = *(const float4*)&eh[t];
            int4   sa = *(const int4*)&srcsh[w][t];
            uint4 p0 = ldh(sa.x, lane), p1 = ldh(sa.y, lane);
            uint4 p2 = ldh(sa.z, lane), p3 = ldh(sa.w, lane);
            dn += ea.x + ea.y + ea.z + ea.w;
            fmah(acc, p0, ea.x); fmah(acc, p1, ea.y);
            fmah(acc, p2, ea.z); fmah(acc, p3, ea.w);
        }
        for (; t < deg; t++){
            float e = eh[t];
            dn += e;
            fmah(acc, ldh(srcsh[w][t], lane), e);
        }
    } else {
        // ---- generic path (deg > 32, rare) ----
        for (int base = beg; base < end; base += 32){
            int j = base + lane;
            int cnt = min(32, end - base);
            bool v = (j < end);
            int src   = v ? g_csrc[j] : 0;
            float4 e4 = v ? ((const float4*)g_e)[j] : make_float4(0,0,0,0);
            srcsh[w][lane] = src;
            exsh[w][0][lane] = e4.x;
            exsh[w][1][lane] = e4.y;
            exsh[w][2][lane] = e4.z;
            exsh[w][3][lane] = e4.w;
            __syncwarp();
            const float* eh = exsh[w][myh];
            int t = 0;
            for (; t + 8 <= cnt; t += 8){
                float4 ea = *(const float4*)&eh[t];
                float4 eb = *(const float4*)&eh[t+4];
                int4   sa = *(const int4*)&srcsh[w][t];
                int4   sb = *(const int4*)&srcsh[w][t+4];
                uint4 p0 = ldh(sa.x, lane), p1 = ldh(sa.y, lane);
                uint4 p2 = ldh(sa.z, lane), p3 = ldh(sa.w, lane);
                uint4 p4 = ldh(sb.x, lane), p5 = ldh(sb.y, lane);
                uint4 p6 = ldh(sb.z, lane), p7 = ldh(sb.w, lane);
                dn += (ea.x + ea.y + ea.z + ea.w) + (eb.x + eb.y + eb.z + eb.w);
                fmah(acc, p0, ea.x); fmah(acc, p1, ea.y);
                fmah(acc, p2, ea.z); fmah(acc, p3, ea.w);
                fmah(acc, p4, eb.x); fmah(acc, p5, eb.y);
                fmah(acc, p6, eb.z); fmah(acc, p7, eb.w);
            }
            for (; t + 4 <= cnt; t += 4){
                float4 ea = *(const float4*)&eh[t];
                int4   sa = *(const int4*)&srcsh[w][t];
                uint4 p0 = ldh(sa.x, lane), p1 = ldh(sa.y, lane);
                uint4 p2 = ldh(sa.z, lane), p3 = ldh(sa.w, lane);
                dn += ea.x + ea.y + ea.z + ea.w;
                fmah(acc, p0, ea.x); fmah(acc, p1, ea.y);
                fmah(acc, p2, ea.z); fmah(acc, p3, ea.w);
            }
            for (; t < cnt; t++){
                float e = eh[t];
                dn += e;
                fmah(acc, ldh(srcsh[w][t], lane), e);
            }
            __syncwarp();
        }
    }

    float inv = 1.f / dn;
    #pragma unroll
    for (int i = 0; i < 8; i++) acc[i] *= inv;
    #pragma unroll
    for (int i = 0; i < 8; i++){
        acc[i] += __shfl_xor_sync(0xFFFFFFFFu, acc[i], 8);
        acc[i] += __shfl_xor_sync(0xFFFFFFFFu, acc[i], 16);
        acc[i] *= 0.25f;
    }
    int cih = (lane & 7) * 8;
    float4 b0 = *(const float4*)&bg[cih];
    float4 b1 = *(const float4*)&bg[cih+4];
    float v[8];
    v[0]=acc[0]+b0.x; v[1]=acc[1]+b0.y; v[2]=acc[2]+b0.z; v[3]=acc[3]+b0.w;
    v[4]=acc[4]+b1.x; v[5]=acc[5]+b1.y; v[6]=acc[6]+b1.z; v[7]=acc[7]+b1.w;
    float s = 0.f, q = 0.f;
    #pragma unroll
    for (int i = 0; i < 8; i++){ s += v[i]; q += v[i]*v[i]; }
    #pragma unroll
    for (int off = 4; off; off >>= 1){
        s += __shfl_xor_sync(0xFFFFFFFFu, s, off);
        q += __shfl_xor_sync(0xFFFFFFFFu, q, off);
    }
    float mu   = s * (1.f/64.f);
    float var  = q * (1.f/64.f) - mu*mu;
    float rstd = rsqrtf(var + 1e-5f);
    float aw = pa[0];
    if (lane < 8){
        float4 g0 = *(const float4*)&gam[cih],   g1 = *(const float4*)&gam[cih+4];
        float4 t0 = *(const float4*)&bet[cih],   t1 = *(const float4*)&bet[cih+4];
        float* xp = &g_x[(size_t)n*HD + cih];
        float4 x0 = *(const float4*)xp, x1 = *(const float4*)(xp+4);
        float xn;
        xn = (v[0]-mu)*rstd*g0.x + t0.x; x0.x += (xn>0.f? xn : aw*xn);
        xn = (v[1]-mu)*rstd*g0.y + t0.y; x0.y += (xn>0.f? xn : aw*xn);
        xn = (v[2]-mu)*rstd*g0.z + t0.z; x0.z += (xn>0.f? xn : aw*xn);
        xn = (v[3]-mu)*rstd*g0.w + t0.w; x0.w += (xn>0.f? xn : aw*xn);
        xn = (v[4]-mu)*rstd*g1.x + t1.x; x1.x += (xn>0.f? xn : aw*xn);
        xn = (v[5]-mu)*rstd*g1.y + t1.y; x1.y += (xn>0.f? xn : aw*xn);
        xn = (v[6]-mu)*rstd*g1.z + t1.z; x1.z += (xn>0.f? xn : aw*xn);
        xn = (v[7]-mu)*rstd*g1.w + t1.w; x1.w += (xn>0.f? xn : aw*xn);
        *(float4*)xp     = x0;
        *(float4*)(xp+4) = x1;
    }
}

// ---------------- final: z = x @ Wp + bp, L2-normalize rows (f32x2) ----------------
__global__ __launch_bounds__(256) void k_final(const float* __restrict__ Wp,
                                               const float* __restrict__ bp,
                                               float* __restrict__ out){
    __shared__ ull Wp2[32][64];
    __shared__ __align__(16) float xs[8][64];
    int t = threadIdx.x;
    for (int i = t; i < 2048; i += 256){
        int k2 = i >> 6, c = i & 63;
        Wp2[k2][c] = pack2(Wp[(2*k2)*64 + c], Wp[(2*k2+1)*64 + c]);
    }
    int nb = blockIdx.x*8;
    for (int i = t; i < 512; i += 256){
        int r = nb + (i >> 6);
        xs[i>>6][i&63] = (r < Nn) ? g_x[(size_t)r*HD + (i & 63)] : 0.f;
    }
    __syncthreads();
    int w = t >> 5, lane = t & 31;
    int n = nb + w;
    if (n >= Nn) return;
    int c0 = lane, c1 = lane + 32;
    ull z2a = 0, z2b = 0;
    #pragma unroll
    for (int k2 = 0; k2 < 32; k2++){
        ull xv = *(const ull*)&xs[w][2*k2];
        fma2(z2a, xv, Wp2[k2][c0]);
        fma2(z2b, xv, Wp2[k2][c1]);
    }
    float l0, h0, l1, h1;
    unpack2(z2a, l0, h0);
    unpack2(z2b, l1, h1);
    float z0 = l0 + h0 + bp[c0];
    float z1 = l1 + h1 + bp[c1];
    float q = z0*z0 + z1*z1;
    #pragma unroll
    for (int off = 16; off; off >>= 1) q += __shfl_xor_sync(0xFFFFFFFFu, q, off);
    float inv = 1.f / fmaxf(sqrtf(q), 1e-12f);
    out[(size_t)n*HD + c0] = z0*inv;
    out[(size_t)n*HD + c1] = z1*inv;
}

// ---------------- launch ----------------
extern "C" void kernel_launch(void* const* d_in, const int* in_sizes, int n_in,
                              void* d_out, int out_size){
    const float* feat = (const float*)d_in[0];
    const int*   ei   = (const int*)  d_in[1];
    const float* Wt   = (const float*)d_in[2];
    const float* bt   = (const float*)d_in[3];
    const float* Wp   = (const float*)d_in[4];
    const float* bp   = (const float*)d_in[5];

    k_zerodeg<<<(Nn + 255)/256, 256>>>();
    k_lin1cnt<<<L1B + (Et + 255)/256, 256>>>(feat, Wt, bt, ei);
    k_scanA  <<<49, 1024>>>();
    k_scanC  <<<49, 1024>>>();
    k_scatter<<<(Et + 255)/256, 256>>>(ei);

    for (int l = 0; l < 2; l++){
        const float* Wg  = (const float*)d_in[6 + l*7 + 0];
        const float* as_ = (const float*)d_in[6 + l*7 + 1];
        const float* ad_ = (const float*)d_in[6 + l*7 + 2];
        const float* bg  = (const float*)d_in[6 + l*7 + 3];
        const float* gam = (const float*)d_in[6 + l*7 + 4];
        const float* bet = (const float*)d_in[6 + l*7 + 5];
        const float* pa  = (const float*)d_in[6 + l*7 + 6];

        k_gemm_h<<<1184, 256>>>(Wg, as_, ad_);
        k_edge  <<<(Et + 255)/256, 256>>>();
        k_gat   <<<(Nn + 7)/8, 256>>>(bg, gam, bet, pa);
    }

    k_final<<<(Nn + 7)/8, 256>>>(Wp, bp, (float*)d_out);
}

// round 16
// speedup vs baseline: 2.7418x; 1.0882x over previous
#include <cuda_runtime.h>
#include <cuda_fp16.h>
#include <math_constants.h>

#define Nn 50000
#define Ee 800000
#define Et 850000
#define FD 512
#define HD 64
#define NH 4
#define HC 256   // NH*HD
#define L1B 391  // lin1 mma blocks = (Nn+127)/128

typedef unsigned long long ull;

// ---------------- scratch (device globals; no allocation) ----------------
__device__ float          g_x  [Nn*HD];   // current node features
__device__ unsigned short g_hh [Nn*HC];   // per-head transformed features (fp16 bits)
__device__ float          g_als[Nn*NH];   // attention logit (src part)
__device__ float          g_ald[Nn*NH];   // attention logit (dst part)
__device__ float          g_e  [Et*NH];   // per-edge exp values (CSR order)
__device__ int   g_deg   [Nn];
__device__ int   g_rowptr[Nn+1];
__device__ int   g_cursor[Nn];
__device__ int   g_csrc  [Et];            // CSR (by dst) source node list
__device__ int   g_cdst  [Et];            // CSR dst (row) per edge
__device__ int   g_bsum[64];

// ---------------- packed f32x2 helpers ----------------
__device__ __forceinline__ void fma2(ull& d, ull a, ull b){
    asm("fma.rn.f32x2 %0, %1, %2, %0;" : "+l"(d) : "l"(a), "l"(b));
}
__device__ __forceinline__ ull pack2(float lo, float hi){
    ull r; asm("mov.b64 %0, {%1, %2};" : "=l"(r) : "f"(lo), "f"(hi)); return r;
}
__device__ __forceinline__ void unpack2(ull v, float& lo, float& hi){
    asm("mov.b64 {%0, %1}, %2;" : "=f"(lo), "=f"(hi) : "l"(v));
}
__device__ __forceinline__ float2 h2f(unsigned w){
    __half2 h = *(__half2*)&w;
    return __half22float2(h);
}
// ---------------- tf32 mma helpers ----------------
__device__ __forceinline__ unsigned f2tf(float f){
    unsigned r; asm("cvt.rna.tf32.f32 %0, %1;" : "=r"(r) : "f"(f)); return r;
}
__device__ __forceinline__ void mma_tf32(float& c0, float& c1, float& c2, float& c3,
                                         unsigned a0, unsigned a1, unsigned a2, unsigned a3,
                                         unsigned b0, unsigned b1){
    asm("mma.sync.aligned.m16n8k8.row.col.f32.tf32.tf32.f32 "
        "{%0,%1,%2,%3}, {%4,%5,%6,%7}, {%8,%9}, {%0,%1,%2,%3};"
        : "+f"(c0), "+f"(c1), "+f"(c2), "+f"(c3)
        : "r"(a0), "r"(a1), "r"(a2), "r"(a3), "r"(b0), "r"(b1));
}

// ---------------- CSR build ----------------
__global__ void k_zerodeg(){
    int i = blockIdx.x*blockDim.x + threadIdx.x;
    if (i < Nn) g_deg[i] = 0;
}

// ---------------- fused: lin1 tf32-MMA GEMM (blocks < L1B) + edge count ----------------
__global__ __launch_bounds__(256) void k_lin1cnt(const float* __restrict__ A,
                                                 const float* __restrict__ W,
                                                 const float* __restrict__ bt,
                                                 const int*   __restrict__ ei){
    if (blockIdx.x >= L1B){
        int eid = (blockIdx.x - L1B)*256 + threadIdx.x;
        if (eid < Et){
            int d = (eid < Ee) ? ei[Ee + eid] : (eid - Ee);
            atomicAdd(&g_deg[d], 1);
        }
        return;
    }
    __shared__ unsigned As[128][36];   // [row][k], stride 36 -> conflict-free frags
    __shared__ unsigned Ws[32][68];    // [k][n],   stride 68 -> conflict-free frags
    int t    = threadIdx.x;
    int warp = t >> 5, lane = t & 31;
    int g    = lane >> 2, tig = lane & 3;
    int rbase = blockIdx.x*128;
    int rw    = warp*16;

    float c[8][4];
    #pragma unroll
    for (int nt = 0; nt < 8; nt++){ c[nt][0]=0; c[nt][1]=0; c[nt][2]=0; c[nt][3]=0; }

    int ra = t >> 1;             // 0..127 (A row within tile)
    int ca = (t & 1) * 16;       // 0 or 16 (A col base within chunk)
    int wr = t >> 3;             // 0..31   (W row)
    int wc = (t & 7) * 8;        // W col base

    for (int kb = 0; kb < FD; kb += 32){
        bool av = (rbase + ra < Nn);
        #pragma unroll
        for (int i = 0; i < 4; i++){
            float4 a4 = av ? *(const float4*)&A[(size_t)(rbase+ra)*FD + kb + ca + 4*i]
                           : make_float4(0,0,0,0);
            As[ra][ca+4*i+0] = f2tf(a4.x);
            As[ra][ca+4*i+1] = f2tf(a4.y);
            As[ra][ca+4*i+2] = f2tf(a4.z);
            As[ra][ca+4*i+3] = f2tf(a4.w);
        }
        #pragma unroll
        for (int i = 0; i < 2; i++){
            float4 w4 = *(const float4*)&W[(size_t)(kb+wr)*64 + wc + 4*i];
            Ws[wr][wc+4*i+0] = f2tf(w4.x);
            Ws[wr][wc+4*i+1] = f2tf(w4.y);
            Ws[wr][wc+4*i+2] = f2tf(w4.z);
            Ws[wr][wc+4*i+3] = f2tf(w4.w);
        }
        __syncthreads();
        #pragma unroll
        for (int ks = 0; ks < 32; ks += 8){
            unsigned a0 = As[rw+g  ][ks+tig  ];
            unsigned a1 = As[rw+g+8][ks+tig  ];
            unsigned a2 = As[rw+g  ][ks+tig+4];
            unsigned a3 = As[rw+g+8][ks+tig+4];
            #pragma unroll
            for (int nt = 0; nt < 8; nt++){
                unsigned b0 = Ws[ks+tig  ][nt*8+g];
                unsigned b1 = Ws[ks+tig+4][nt*8+g];
                mma_tf32(c[nt][0], c[nt][1], c[nt][2], c[nt][3], a0, a1, a2, a3, b0, b1);
            }
        }
        __syncthreads();
    }
    // epilogue: thread owns (rows r0,r0+8) x (cols nt*8+2tig, +1)
    int r0 = rbase + rw + g;
    int r1 = r0 + 8;
    #pragma unroll
    for (int nt = 0; nt < 8; nt++){
        int col = nt*8 + tig*2;
        float2 b2 = *(const float2*)&bt[col];
        if (r0 < Nn){
            float2 o; o.x = c[nt][0] + b2.x; o.y = c[nt][1] + b2.y;
            *(float2*)&g_x[(size_t)r0*HD + col] = o;
        }
        if (r1 < Nn){
            float2 o; o.x = c[nt][2] + b2.x; o.y = c[nt][3] + b2.y;
            *(float2*)&g_x[(size_t)r1*HD + col] = o;
        }
    }
}

__global__ __launch_bounds__(1024) void k_scanA(){
    __shared__ int sh[1024];
    int t   = threadIdx.x;
    int gid = blockIdx.x*1024 + t;
    int v = (gid < Nn) ? g_deg[gid] : 0;
    sh[t] = v; __syncthreads();
    #pragma unroll
    for (int off = 1; off < 1024; off <<= 1){
        int u = (t >= off) ? sh[t-off] : 0;
        __syncthreads();
        sh[t] += u;
        __syncthreads();
    }
    if (gid < Nn) g_rowptr[gid] = sh[t] - v;
    if (t == 1023) g_bsum[blockIdx.x] = sh[1023];
}
__global__ __launch_bounds__(1024) void k_scanC(){
    __shared__ int s_off;
    int t = threadIdx.x;
    if (t < 32){
        int b = blockIdx.x;
        int v = 0;
        if (t      < b) v  = g_bsum[t];
        if (t + 32 < b) v += g_bsum[t + 32];
        #pragma unroll
        for (int off = 16; off; off >>= 1)
            v += __shfl_xor_sync(0xFFFFFFFFu, v, off);
        if (t == 0) s_off = v;
    }
    __syncthreads();
    int gid = blockIdx.x*1024 + t;
    if (gid < Nn){
        int r = g_rowptr[gid] + s_off;
        g_rowptr[gid] = r;
        g_cursor[gid] = r;
    }
    if (gid == 0) g_rowptr[Nn] = Et;
}
__global__ void k_scatter(const int* __restrict__ ei){
    int eid = blockIdx.x*blockDim.x + threadIdx.x;
    if (eid >= Et) return;
    int s, d;
    if (eid < Ee){ s = ei[eid]; d = ei[Ee + eid]; } else { s = d = eid - Ee; }
    int pos = atomicAdd(&g_cursor[d], 1);
    g_csrc[pos] = s;
    g_cdst[pos] = d;
}

// ---------------- h = x @ Wg (fp16 out) + fused als/ald epilogue ----------------
__global__ __launch_bounds__(256) void k_gemm_h(const float* __restrict__ W,
                                                const float* __restrict__ as_,
                                                const float* __restrict__ ad_){
    int j = threadIdx.x;
    int wrp = j >> 5, lane = j & 31;
    ull w2[32];
    #pragma unroll
    for (int k2 = 0; k2 < 32; k2++)
        w2[k2] = pack2(W[(2*k2)*256 + j], W[(2*k2+1)*256 + j]);
    float asj = as_[j];
    float adj = ad_[j];
    __shared__ __align__(16) float xs[4][64];
    __shared__ float wps[4][8], wpd[4][8];
    for (int rb = blockIdx.x*4; rb < Nn; rb += gridDim.x*4){
        int r = rb + (j >> 6);
        float xv = (r < Nn) ? g_x[(size_t)r*HD + (j & 63)] : 0.f;
        __syncthreads();
        xs[j>>6][j&63] = xv;
        __syncthreads();
        ull a2[4] = {0,0,0,0};
        #pragma unroll
        for (int k4 = 0; k4 < 16; k4++){
            ulonglong2 x0 = *(const ulonglong2*)&xs[0][k4*4];
            ulonglong2 x1 = *(const ulonglong2*)&xs[1][k4*4];
            ulonglong2 x2 = *(const ulonglong2*)&xs[2][k4*4];
            ulonglong2 x3 = *(const ulonglong2*)&xs[3][k4*4];
            fma2(a2[0], x0.x, w2[k4*2]); fma2(a2[0], x0.y, w2[k4*2+1]);
            fma2(a2[1], x1.x, w2[k4*2]); fma2(a2[1], x1.y, w2[k4*2+1]);
            fma2(a2[2], x2.x, w2[k4*2]); fma2(a2[2], x2.y, w2[k4*2+1]);
            fma2(a2[3], x3.x, w2[k4*2]); fma2(a2[3], x3.y, w2[k4*2+1]);
        }
        float hv[4];
        #pragma unroll
        for (int i = 0; i < 4; i++){
            float lo, hi; unpack2(a2[i], lo, hi);
            hv[i] = lo + hi;
            if (rb+i < Nn){
                __half b = __float2half_rn(hv[i]);
                g_hh[(size_t)(rb+i)*HC + j] = *(unsigned short*)&b;
            }
        }
        float ps[4], pd[4];
        #pragma unroll
        for (int i = 0; i < 4; i++){ ps[i] = hv[i]*asj; pd[i] = hv[i]*adj; }
        #pragma unroll
        for (int off = 16; off; off >>= 1){
            #pragma unroll
            for (int i = 0; i < 4; i++){
                ps[i] += __shfl_xor_sync(0xFFFFFFFFu, ps[i], off);
                pd[i] += __shfl_xor_sync(0xFFFFFFFFu, pd[i], off);
            }
        }
        if (lane == 0){
            #pragma unroll
            for (int i = 0; i < 4; i++){ wps[i][wrp] = ps[i]; wpd[i][wrp] = pd[i]; }
        }
        __syncthreads();
        if (j < 16){
            int i = j >> 2, h = j & 3;
            int r2 = rb + i;
            if (r2 < Nn){
                g_als[r2*4 + h] = wps[i][2*h] + wps[i][2*h+1];
                g_ald[r2*4 + h] = wpd[i][2*h] + wpd[i][2*h+1];
            }
        }
    }
}

__device__ __forceinline__ float lrelu(float v){ return v > 0.f ? v : 0.2f*v; }

// ---------------- per-edge exp in CSR order (fully parallel) ----------------
__global__ __launch_bounds__(256) void k_edge(){
    int j = blockIdx.x*blockDim.x + threadIdx.x;
    if (j >= Et) return;
    int s = g_csrc[j], d = g_cdst[j];
    float4 a = ((const float4*)g_als)[s];
    float4 b = ((const float4*)g_ald)[d];
    float4 e;
    e.x = __expf(lrelu(a.x + b.x));
    e.y = __expf(lrelu(a.y + b.y));
    e.z = __expf(lrelu(a.z + b.z));
    e.w = __expf(lrelu(a.w + b.w));
    ((float4*)g_e)[j] = e;
}

__device__ __forceinline__ uint4 ldh(int src, int lane){
    return *(const uint4*)&g_hh[(size_t)src*HC + lane*8];
}
__device__ __forceinline__ void fmah(float* acc, uint4 p, float e){
    float2 c0 = h2f(p.x), c1 = h2f(p.y), c2 = h2f(p.z), c3 = h2f(p.w);
    acc[0] += e*c0.x; acc[1] += e*c0.y;
    acc[2] += e*c1.x; acc[3] += e*c1.y;
    acc[4] += e*c2.x; acc[5] += e*c2.y;
    acc[6] += e*c3.x; acc[7] += e*c3.y;
}

// ---------------- fused GAT: pure gather + FMA (ex precomputed) ----------------
__global__ __launch_bounds__(256) void k_gat(const float* __restrict__ bg,
                                             const float* __restrict__ gam,
                                             const float* __restrict__ bet,
                                             const float* __restrict__ pa){
    __shared__ __align__(16) float exsh [8][NH][32];
    __shared__ __align__(16) int   srcsh[8][32];
    int w    = threadIdx.x >> 5;
    int lane = threadIdx.x & 31;
    int n    = blockIdx.x*8 + w;
    if (n >= Nn) return;
    int beg = g_rowptr[n], end = g_rowptr[n+1];
    int deg = end - beg;
    int myh = lane >> 3;

    float acc[8] = {0,0,0,0,0,0,0,0};
    float dn = 0.f;

    if (deg <= 32){
        int j = beg + lane;
        bool v = (j < end);
        int src   = v ? g_csrc[j] : 0;
        float4 e4 = v ? ((const float4*)g_e)[j] : make_float4(0,0,0,0);
        srcsh[w][lane] = src;
        exsh[w][0][lane] = e4.x;
        exsh[w][1][lane] = e4.y;
        exsh[w][2][lane] = e4.z;
        exsh[w][3][lane] = e4.w;
        __syncwarp();
        const float* eh = exsh[w][myh];
        int t = 0;
        for (; t + 8 <= deg; t += 8){
            float4 ea = *(const float4*)&eh[t];
            float4 eb = *(const float4*)&eh[t+4];
            int4   sa = *(const int4*)&srcsh[w][t];
            int4   sb = *(const int4*)&srcsh[w][t+4];
            uint4 p0 = ldh(sa.x, lane), p1 = ldh(sa.y, lane);
            uint4 p2 = ldh(sa.z, lane), p3 = ldh(sa.w, lane);
            uint4 p4 = ldh(sb.x, lane), p5 = ldh(sb.y, lane);
            uint4 p6 = ldh(sb.z, lane), p7 = ldh(sb.w, lane);
            dn += (ea.x + ea.y + ea.z + ea.w) + (eb.x + eb.y + eb.z + eb.w);
            fmah(acc, p0, ea.x); fmah(acc, p1, ea.y);
            fmah(acc, p2, ea.z); fmah(acc, p3, ea.w);
            fmah(acc, p4, eb.x); fmah(acc, p5, eb.y);
            fmah(acc, p6, eb.z); fmah(acc, p7, eb.w);
        }
        for (; t + 4 <= deg; t += 4){
            float4 ea = *(const float4*)&eh[t];
            int4   sa = *(const int4*)&srcsh[w][t];
            uint4 p0 = ldh(sa.x, lane), p1 = ldh(sa.y, lane);
            uint4 p2 = ldh(sa.z, lane), p3 = ldh(sa.w, lane);
            dn += ea.x + ea.y + ea.z + ea.w;
            fmah(acc, p0, ea.x); fmah(acc, p1, ea.y);
            fmah(acc, p2, ea.z); fmah(acc, p3, ea.w);
        }
        for (; t < deg; t++){
            float e = eh[t];
            dn += e;
            fmah(acc, ldh(srcsh[w][t], lane), e);
        }
    } else {
        for (int base = beg; base < end; base += 32){
            int j = base + lane;
            int cnt = min(32, end - base);
            bool v = (j < end);
            int src   = v ? g_csrc[j] : 0;
            float4 e4 = v ? ((const float4*)g_e)[j] : make_float4(0,0,0,0);
            srcsh[w][lane] = src;
            exsh[w][0][lane] = e4.x;
            exsh[w][1][lane] = e4.y;
            exsh[w][2][lane] = e4.z;
            exsh[w][3][lane] = e4.w;
            __syncwarp();
            const float* eh = exsh[w][myh];
            int t = 0;
            for (; t + 8 <= cnt; t += 8){
                float4 ea = *(const float4*)&eh[t];
                float4 eb = *(const float4*)&eh[t+4];
                int4   sa = *(const int4*)&srcsh[w][t];
                int4   sb = *(const int4*)&srcsh[w][t+4];
                uint4 p0 = ldh(sa.x, lane), p1 = ldh(sa.y, lane);
                uint4 p2 = ldh(sa.z, lane), p3 = ldh(sa.w, lane);
                uint4 p4 = ldh(sb.x, lane), p5 = ldh(sb.y, lane);
                uint4 p6 = ldh(sb.z, lane), p7 = ldh(sb.w, lane);
                dn += (ea.x + ea.y + ea.z + ea.w) + (eb.x + eb.y + eb.z + eb.w);
                fmah(acc, p0, ea.x); fmah(acc, p1, ea.y);
                fmah(acc, p2, ea.z); fmah(acc, p3, ea.w);
                fmah(acc, p4, eb.x); fmah(acc, p5, eb.y);
                fmah(acc, p6, eb.z); fmah(acc, p7, eb.w);
            }
            for (; t + 4 <= cnt; t += 4){
                float4 ea = *(const float4*)&eh[t];
                int4   sa = *(const int4*)&srcsh[w][t];
                uint4 p0 = ldh(sa.x, lane), p1 = ldh(sa.y, lane);
                uint4 p2 = ldh(sa.z, lane), p3 = ldh(sa.w, lane);
                dn += ea.x + ea.y + ea.z + ea.w;
                fmah(acc, p0, ea.x); fmah(acc, p1, ea.y);
                fmah(acc, p2, ea.z); fmah(acc, p3, ea.w);
            }
            for (; t < cnt; t++){
                float e = eh[t];
                dn += e;
                fmah(acc, ldh(srcsh[w][t], lane), e);
            }
            __syncwarp();
        }
    }

    float inv = 1.f / dn;
    #pragma unroll
    for (int i = 0; i < 8; i++) acc[i] *= inv;
    #pragma unroll
    for (int i = 0; i < 8; i++){
        acc[i] += __shfl_xor_sync(0xFFFFFFFFu, acc[i], 8);
        acc[i] += __shfl_xor_sync(0xFFFFFFFFu, acc[i], 16);
        acc[i] *= 0.25f;
    }
    int cih = (lane & 7) * 8;
    float4 b0 = *(const float4*)&bg[cih];
    float4 b1 = *(const float4*)&bg[cih+4];
    float v[8];
    v[0]=acc[0]+b0.x; v[1]=acc[1]+b0.y; v[2]=acc[2]+b0.z; v[3]=acc[3]+b0.w;
    v[4]=acc[4]+b1.x; v[5]=acc[5]+b1.y; v[6]=acc[6]+b1.z; v[7]=acc[7]+b1.w;
    float s = 0.f, q = 0.f;
    #pragma unroll
    for (int i = 0; i < 8; i++){ s += v[i]; q += v[i]*v[i]; }
    #pragma unroll
    for (int off = 4; off; off >>= 1){
        s += __shfl_xor_sync(0xFFFFFFFFu, s, off);
        q += __shfl_xor_sync(0xFFFFFFFFu, q, off);
    }
    float mu   = s * (1.f/64.f);
    float var  = q * (1.f/64.f) - mu*mu;
    float rstd = rsqrtf(var + 1e-5f);
    float aw = pa[0];
    if (lane < 8){
        float4 g0 = *(const float4*)&gam[cih],   g1 = *(const float4*)&gam[cih+4];
        float4 t0 = *(const float4*)&bet[cih],   t1 = *(const float4*)&bet[cih+4];
        float* xp = &g_x[(size_t)n*HD + cih];
        float4 x0 = *(const float4*)xp, x1 = *(const float4*)(xp+4);
        float xn;
        xn = (v[0]-mu)*rstd*g0.x + t0.x; x0.x += (xn>0.f? xn : aw*xn);
        xn = (v[1]-mu)*rstd*g0.y + t0.y; x0.y += (xn>0.f? xn : aw*xn);
        xn = (v[2]-mu)*rstd*g0.z + t0.z; x0.z += (xn>0.f? xn : aw*xn);
        xn = (v[3]-mu)*rstd*g0.w + t0.w; x0.w += (xn>0.f? xn : aw*xn);
        xn = (v[4]-mu)*rstd*g1.x + t1.x; x1.x += (xn>0.f? xn : aw*xn);
        xn = (v[5]-mu)*rstd*g1.y + t1.y; x1.y += (xn>0.f? xn : aw*xn);
        xn = (v[6]-mu)*rstd*g1.z + t1.z; x1.z += (xn>0.f? xn : aw*xn);
        xn = (v[7]-mu)*rstd*g1.w + t1.w; x1.w += (xn>0.f? xn : aw*xn);
        *(float4*)xp     = x0;
        *(float4*)(xp+4) = x1;
    }
}

// ---------------- final: z = x @ Wp + bp, L2-normalize rows (f32x2) ----------------
__global__ __launch_bounds__(256) void k_final(const float* __restrict__ Wp,
                                               const float* __restrict__ bp,
                                               float* __restrict__ out){
    __shared__ ull Wp2[32][64];
    __shared__ __align__(16) float xs[8][64];
    int t = threadIdx.x;
    for (int i = t; i < 2048; i += 256){
        int k2 = i >> 6, c = i & 63;
        Wp2[k2][c] = pack2(Wp[(2*k2)*64 + c], Wp[(2*k2+1)*64 + c]);
    }
    int nb = blockIdx.x*8;
    for (int i = t; i < 512; i += 256){
        int r = nb + (i >> 6);
        xs[i>>6][i&63] = (r < Nn) ? g_x[(size_t)r*HD + (i & 63)] : 0.f;
    }
    __syncthreads();
    int w = t >> 5, lane = t & 31;
    int n = nb + w;
    if (n >= Nn) return;
    int c0 = lane, c1 = lane + 32;
    ull z2a = 0, z2b = 0;
    #pragma unroll
    for (int k2 = 0; k2 < 32; k2++){
        ull xv = *(const ull*)&xs[w][2*k2];
        fma2(z2a, xv, Wp2[k2][c0]);
        fma2(z2b, xv, Wp2[k2][c1]);
    }
    float l0, h0, l1, h1;
    unpack2(z2a, l0, h0);
    unpack2(z2b, l1, h1);
    float z0 = l0 + h0 + bp[c0];
    float z1 = l1 + h1 + bp[c1];
    float q = z0*z0 + z1*z1;
    #pragma unroll
    for (int off = 16; off; off >>= 1) q += __shfl_xor_sync(0xFFFFFFFFu, q, off);
    float inv = 1.f / fmaxf(sqrtf(q), 1e-12f);
    out[(size_t)n*HD + c0] = z0*inv;
    out[(size_t)n*HD + c1] = z1*inv;
}

// ---------------- launch ----------------
extern "C" void kernel_launch(void* const* d_in, const int* in_sizes, int n_in,
                              void* d_out, int out_size){
    const float* feat = (const float*)d_in[0];
    const int*   ei   = (const int*)  d_in[1];
    const float* Wt   = (const float*)d_in[2];
    const float* bt   = (const float*)d_in[3];
    const float* Wp   = (const float*)d_in[4];
    const float* bp   = (const float*)d_in[5];

    k_zerodeg<<<(Nn + 255)/256, 256>>>();
    k_lin1cnt<<<L1B + (Et + 255)/256, 256>>>(feat, Wt, bt, ei);
    k_scanA  <<<49, 1024>>>();
    k_scanC  <<<49, 1024>>>();
    k_scatter<<<(Et + 255)/256, 256>>>(ei);

    for (int l = 0; l < 2; l++){
        const float* Wg  = (const float*)d_in[6 + l*7 + 0];
        const float* as_ = (const float*)d_in[6 + l*7 + 1];
        const float* ad_ = (const float*)d_in[6 + l*7 + 2];
        const float* bg  = (const float*)d_in[6 + l*7 + 3];
        const float* gam = (const float*)d_in[6 + l*7 + 4];
        const float* bet = (const float*)d_in[6 + l*7 + 5];
        const float* pa  = (const float*)d_in[6 + l*7 + 6];

        k_gemm_h<<<1184, 256>>>(Wg, as_, ad_);
        k_edge  <<<(Et + 255)/256, 256>>>();
        k_gat   <<<(Nn + 7)/8, 256>>>(bg, gam, bet, pa);
    }

    k_final<<<(Nn + 7)/8, 256>>>(Wp, bp, (float*)d_out);
}

// round 17
// speedup vs baseline: 3.3386x; 1.2177x over previous
#include <cuda_runtime.h>
#include <cuda_fp16.h>
#include <math_constants.h>

#define Nn 50000
#define Ee 800000
#define Et 850000
#define FD 512
#define HD 64
#define NH 4
#define HC 256   // NH*HD
#define L1B 391  // lin1 mma blocks = (Nn+127)/128

typedef unsigned long long ull;

// ---------------- scratch (device globals; no allocation) ----------------
__device__ float          g_x  [Nn*HD];   // current node features
__device__ unsigned short g_hh [Nn*HC];   // per-head transformed features (fp16 bits)
__device__ float          g_als[Nn*NH];   // attention logit (src part)
__device__ float          g_ald[Nn*NH];   // attention logit (dst part)
__device__ float          g_e  [Et*NH];   // per-edge exp values (CSR order)
__device__ int   g_deg   [Nn];
__device__ int   g_rowptr[Nn+1];
__device__ int   g_cursor[Nn];
__device__ int   g_csrc  [Et];            // CSR (by dst) source node list
__device__ int   g_cdst  [Et];            // CSR dst (row) per edge
__device__ int   g_bsum[64];

// ---------------- packed f32x2 helpers ----------------
__device__ __forceinline__ void fma2(ull& d, ull a, ull b){
    asm("fma.rn.f32x2 %0, %1, %2, %0;" : "+l"(d) : "l"(a), "l"(b));
}
__device__ __forceinline__ ull pack2(float lo, float hi){
    ull r; asm("mov.b64 %0, {%1, %2};" : "=l"(r) : "f"(lo), "f"(hi)); return r;
}
__device__ __forceinline__ void unpack2(ull v, float& lo, float& hi){
    asm("mov.b64 {%0, %1}, %2;" : "=f"(lo), "=f"(hi) : "l"(v));
}
__device__ __forceinline__ float2 h2f(unsigned w){
    __half2 h = *(__half2*)&w;
    return __half22float2(h);
}
// ---------------- tf32 mma helpers ----------------
__device__ __forceinline__ unsigned f2tf(float f){
    unsigned r; asm("cvt.rna.tf32.f32 %0, %1;" : "=r"(r) : "f"(f)); return r;
}
__device__ __forceinline__ void mma_tf32(float& c0, float& c1, float& c2, float& c3,
                                         unsigned a0, unsigned a1, unsigned a2, unsigned a3,
                                         unsigned b0, unsigned b1){
    asm("mma.sync.aligned.m16n8k8.row.col.f32.tf32.tf32.f32 "
        "{%0,%1,%2,%3}, {%4,%5,%6,%7}, {%8,%9}, {%0,%1,%2,%3};"
        : "+f"(c0), "+f"(c1), "+f"(c2), "+f"(c3)
        : "r"(a0), "r"(a1), "r"(a2), "r"(a3), "r"(b0), "r"(b1));
}

// ---------------- CSR build ----------------
__global__ void k_zerodeg(){
    int i = blockIdx.x*blockDim.x + threadIdx.x;
    if (i < Nn) g_deg[i] = 0;
}

// ---------------- fused: lin1 tf32-MMA GEMM (blocks < L1B) + edge count ----------------
__global__ __launch_bounds__(256) void k_lin1cnt(const float* __restrict__ A,
                                                 const float* __restrict__ W,
                                                 const float* __restrict__ bt,
                                                 const int*   __restrict__ ei){
    if (blockIdx.x >= L1B){
        int eid = (blockIdx.x - L1B)*256 + threadIdx.x;
        if (eid < Et){
            int d = (eid < Ee) ? ei[Ee + eid] : (eid - Ee);
            atomicAdd(&g_deg[d], 1);
        }
        return;
    }
    __shared__ unsigned As[128][36];
    __shared__ unsigned Ws[32][68];
    int t    = threadIdx.x;
    int warp = t >> 5, lane = t & 31;
    int g    = lane >> 2, tig = lane & 3;
    int rbase = blockIdx.x*128;
    int rw    = warp*16;

    float c[8][4];
    #pragma unroll
    for (int nt = 0; nt < 8; nt++){ c[nt][0]=0; c[nt][1]=0; c[nt][2]=0; c[nt][3]=0; }

    int ra = t >> 1;
    int ca = (t & 1) * 16;
    int wr = t >> 3;
    int wc = (t & 7) * 8;

    for (int kb = 0; kb < FD; kb += 32){
        bool av = (rbase + ra < Nn);
        #pragma unroll
        for (int i = 0; i < 4; i++){
            float4 a4 = av ? *(const float4*)&A[(size_t)(rbase+ra)*FD + kb + ca + 4*i]
                           : make_float4(0,0,0,0);
            As[ra][ca+4*i+0] = f2tf(a4.x);
            As[ra][ca+4*i+1] = f2tf(a4.y);
            As[ra][ca+4*i+2] = f2tf(a4.z);
            As[ra][ca+4*i+3] = f2tf(a4.w);
        }
        #pragma unroll
        for (int i = 0; i < 2; i++){
            float4 w4 = *(const float4*)&W[(size_t)(kb+wr)*64 + wc + 4*i];
            Ws[wr][wc+4*i+0] = f2tf(w4.x);
            Ws[wr][wc+4*i+1] = f2tf(w4.y);
            Ws[wr][wc+4*i+2] = f2tf(w4.z);
            Ws[wr][wc+4*i+3] = f2tf(w4.w);
        }
        __syncthreads();
        #pragma unroll
        for (int ks = 0; ks < 32; ks += 8){
            unsigned a0 = As[rw+g  ][ks+tig  ];
            unsigned a1 = As[rw+g+8][ks+tig  ];
            unsigned a2 = As[rw+g  ][ks+tig+4];
            unsigned a3 = As[rw+g+8][ks+tig+4];
            #pragma unroll
            for (int nt = 0; nt < 8; nt++){
                unsigned b0 = Ws[ks+tig  ][nt*8+g];
                unsigned b1 = Ws[ks+tig+4][nt*8+g];
                mma_tf32(c[nt][0], c[nt][1], c[nt][2], c[nt][3], a0, a1, a2, a3, b0, b1);
            }
        }
        __syncthreads();
    }
    int r0 = rbase + rw + g;
    int r1 = r0 + 8;
    #pragma unroll
    for (int nt = 0; nt < 8; nt++){
        int col = nt*8 + tig*2;
        float2 b2 = *(const float2*)&bt[col];
        if (r0 < Nn){
            float2 o; o.x = c[nt][0] + b2.x; o.y = c[nt][1] + b2.y;
            *(float2*)&g_x[(size_t)r0*HD + col] = o;
        }
        if (r1 < Nn){
            float2 o; o.x = c[nt][2] + b2.x; o.y = c[nt][3] + b2.y;
            *(float2*)&g_x[(size_t)r1*HD + col] = o;
        }
    }
}

__global__ __launch_bounds__(1024) void k_scanA(){
    __shared__ int sh[1024];
    int t   = threadIdx.x;
    int gid = blockIdx.x*1024 + t;
    int v = (gid < Nn) ? g_deg[gid] : 0;
    sh[t] = v; __syncthreads();
    #pragma unroll
    for (int off = 1; off < 1024; off <<= 1){
        int u = (t >= off) ? sh[t-off] : 0;
        __syncthreads();
        sh[t] += u;
        __syncthreads();
    }
    if (gid < Nn) g_rowptr[gid] = sh[t] - v;
    if (t == 1023) g_bsum[blockIdx.x] = sh[1023];
}
__global__ __launch_bounds__(1024) void k_scanC(){
    __shared__ int s_off;
    int t = threadIdx.x;
    if (t < 32){
        int b = blockIdx.x;
        int v = 0;
        if (t      < b) v  = g_bsum[t];
        if (t + 32 < b) v += g_bsum[t + 32];
        #pragma unroll
        for (int off = 16; off; off >>= 1)
            v += __shfl_xor_sync(0xFFFFFFFFu, v, off);
        if (t == 0) s_off = v;
    }
    __syncthreads();
    int gid = blockIdx.x*1024 + t;
    if (gid < Nn){
        int r = g_rowptr[gid] + s_off;
        g_rowptr[gid] = r;
        g_cursor[gid] = r;
    }
    if (gid == 0) g_rowptr[Nn] = Et;
}
__global__ void k_scatter(const int* __restrict__ ei){
    int eid = blockIdx.x*blockDim.x + threadIdx.x;
    if (eid >= Et) return;
    int s, d;
    if (eid < Ee){ s = ei[eid]; d = ei[Ee + eid]; } else { s = d = eid - Ee; }
    int pos = atomicAdd(&g_cursor[d], 1);
    g_csrc[pos] = s;
    g_cdst[pos] = d;
}

// ---------------- h = x @ Wg via tf32 MMA (fp16 out) + fused als/ald ----------------
// block: 64 rows x 256 cols, 8 warps. warp w: rows (w&3)*16, cols (w>>2)*128.
__global__ __launch_bounds__(256) void k_gemm_h(const float* __restrict__ W,
                                                const float* __restrict__ as_,
                                                const float* __restrict__ ad_){
    __shared__ unsigned xs[64][68];    // [row][k] tf32, conflict-free
    __shared__ unsigned Ws[16][260];   // [k][n] tf32 chunk, conflict-free
    __shared__ float ass[256], ads[256];
    int t    = threadIdx.x;
    int warp = t >> 5, lane = t & 31;
    int g    = lane >> 2, tig = lane & 3;
    int rbase = blockIdx.x*64;
    int rw    = (warp & 3)*16;
    int cb    = (warp >> 2)*128;

    ass[t] = as_[t];
    ads[t] = ad_[t];
    {   // load x tile (64 x 64) as tf32
        int ra = t >> 2;
        int ca = (t & 3)*16;
        bool v = (rbase + ra < Nn);
        #pragma unroll
        for (int i = 0; i < 4; i++){
            float4 x4 = v ? *(const float4*)&g_x[(size_t)(rbase+ra)*HD + ca + 4*i]
                          : make_float4(0,0,0,0);
            xs[ra][ca+4*i+0] = f2tf(x4.x);
            xs[ra][ca+4*i+1] = f2tf(x4.y);
            xs[ra][ca+4*i+2] = f2tf(x4.z);
            xs[ra][ca+4*i+3] = f2tf(x4.w);
        }
    }

    float c[16][4];
    #pragma unroll
    for (int nt = 0; nt < 16; nt++){ c[nt][0]=0; c[nt][1]=0; c[nt][2]=0; c[nt][3]=0; }

    int wr = t >> 4;          // 0..15 (k row in chunk)
    int wc = (t & 15)*16;     // col base
    for (int kb = 0; kb < 64; kb += 16){
        #pragma unroll
        for (int i = 0; i < 4; i++){
            float4 w4 = *(const float4*)&W[(size_t)(kb+wr)*HC + wc + 4*i];
            Ws[wr][wc+4*i+0] = f2tf(w4.x);
            Ws[wr][wc+4*i+1] = f2tf(w4.y);
            Ws[wr][wc+4*i+2] = f2tf(w4.z);
            Ws[wr][wc+4*i+3] = f2tf(w4.w);
        }
        __syncthreads();
        #pragma unroll
        for (int ks = 0; ks < 16; ks += 8){
            unsigned a0 = xs[rw+g  ][kb+ks+tig  ];
            unsigned a1 = xs[rw+g+8][kb+ks+tig  ];
            unsigned a2 = xs[rw+g  ][kb+ks+tig+4];
            unsigned a3 = xs[rw+g+8][kb+ks+tig+4];
            #pragma unroll
            for (int nt = 0; nt < 16; nt++){
                unsigned b0 = Ws[ks+tig  ][cb+nt*8+g];
                unsigned b1 = Ws[ks+tig+4][cb+nt*8+g];
                mma_tf32(c[nt][0], c[nt][1], c[nt][2], c[nt][3], a0, a1, a2, a3, b0, b1);
            }
        }
        __syncthreads();
    }

    // epilogue: fp16 h store + fused als/ald from fp32 fragments
    int r0 = rbase + rw + g;
    int r1 = r0 + 8;
    bool v0 = (r0 < Nn), v1 = (r1 < Nn);
    float psA0=0, psA1=0, psB0=0, psB1=0;
    float pdA0=0, pdA1=0, pdB0=0, pdB1=0;
    #pragma unroll
    for (int nt = 0; nt < 16; nt++){
        int col = cb + nt*8 + tig*2;
        __half2 ha = __floats2half2_rn(c[nt][0], c[nt][1]);
        __half2 hb = __floats2half2_rn(c[nt][2], c[nt][3]);
        if (v0) *(__half2*)&g_hh[(size_t)r0*HC + col] = ha;
        if (v1) *(__half2*)&g_hh[(size_t)r1*HC + col] = hb;
        float a0 = ass[col], a1 = ass[col+1];
        float d0 = ads[col], d1 = ads[col+1];
        if (nt < 8){
            psA0 += c[nt][0]*a0 + c[nt][1]*a1;
            psA1 += c[nt][2]*a0 + c[nt][3]*a1;
            pdA0 += c[nt][0]*d0 + c[nt][1]*d1;
            pdA1 += c[nt][2]*d0 + c[nt][3]*d1;
        } else {
            psB0 += c[nt][0]*a0 + c[nt][1]*a1;
            psB1 += c[nt][2]*a0 + c[nt][3]*a1;
            pdB0 += c[nt][0]*d0 + c[nt][1]*d1;
            pdB1 += c[nt][2]*d0 + c[nt][3]*d1;
        }
    }
    #pragma unroll
    for (int off = 1; off <= 2; off <<= 1){
        psA0 += __shfl_xor_sync(0xFFFFFFFFu, psA0, off);
        psA1 += __shfl_xor_sync(0xFFFFFFFFu, psA1, off);
        psB0 += __shfl_xor_sync(0xFFFFFFFFu, psB0, off);
        psB1 += __shfl_xor_sync(0xFFFFFFFFu, psB1, off);
        pdA0 += __shfl_xor_sync(0xFFFFFFFFu, pdA0, off);
        pdA1 += __shfl_xor_sync(0xFFFFFFFFu, pdA1, off);
        pdB0 += __shfl_xor_sync(0xFFFFFFFFu, pdB0, off);
        pdB1 += __shfl_xor_sync(0xFFFFFFFFu, pdB1, off);
    }
    if (tig == 0){
        int hA = (warp >> 2)*2, hB = hA + 1;
        if (v0){
            g_als[r0*4 + hA] = psA0; g_als[r0*4 + hB] = psB0;
            g_ald[r0*4 + hA] = pdA0; g_ald[r0*4 + hB] = pdB0;
        }
        if (v1){
            g_als[r1*4 + hA] = psA1; g_als[r1*4 + hB] = psB1;
            g_ald[r1*4 + hA] = pdA1; g_ald[r1*4 + hB] = pdB1;
        }
    }
}

__device__ __forceinline__ float lrelu(float v){ return v > 0.f ? v : 0.2f*v; }

// ---------------- per-edge exp in CSR order (fully parallel) ----------------
__global__ __launch_bounds__(256) void k_edge(){
    int j = blockIdx.x*blockDim.x + threadIdx.x;
    if (j >= Et) return;
    int s = g_csrc[j], d = g_cdst[j];
    float4 a = ((const float4*)g_als)[s];
    float4 b = ((const float4*)g_ald)[d];
    float4 e;
    e.x = __expf(lrelu(a.x + b.x));
    e.y = __expf(lrelu(a.y + b.y));
    e.z = __expf(lrelu(a.z + b.z));
    e.w = __expf(lrelu(a.w + b.w));
    ((float4*)g_e)[j] = e;
}

__device__ __forceinline__ uint4 ldh(int src, int lane){
    return *(const uint4*)&g_hh[(size_t)src*HC + lane*8];
}
__device__ __forceinline__ void fmah(float* acc, uint4 p, float e){
    float2 c0 = h2f(p.x), c1 = h2f(p.y), c2 = h2f(p.z), c3 = h2f(p.w);
    acc[0] += e*c0.x; acc[1] += e*c0.y;
    acc[2] += e*c1.x; acc[3] += e*c1.y;
    acc[4] += e*c2.x; acc[5] += e*c2.y;
    acc[6] += e*c3.x; acc[7] += e*c3.y;
}

// ---------------- fused GAT: pure gather + FMA (ex precomputed) ----------------
__global__ __launch_bounds__(256) void k_gat(const float* __restrict__ bg,
                                             const float* __restrict__ gam,
                                             const float* __restrict__ bet,
                                             const float* __restrict__ pa){
    __shared__ __align__(16) float exsh [8][NH][32];
    __shared__ __align__(16) int   srcsh[8][32];
    int w    = threadIdx.x >> 5;
    int lane = threadIdx.x & 31;
    int n    = blockIdx.x*8 + w;
    if (n >= Nn) return;
    int beg = g_rowptr[n], end = g_rowptr[n+1];
    int deg = end - beg;
    int myh = lane >> 3;

    float acc[8] = {0,0,0,0,0,0,0,0};
    float dn = 0.f;

    if (deg <= 32){
        int j = beg + lane;
        bool v = (j < end);
        int src   = v ? g_csrc[j] : 0;
        float4 e4 = v ? ((const float4*)g_e)[j] : make_float4(0,0,0,0);
        srcsh[w][lane] = src;
        exsh[w][0][lane] = e4.x;
        exsh[w][1][lane] = e4.y;
        exsh[w][2][lane] = e4.z;
        exsh[w][3][lane] = e4.w;
        __syncwarp();
        const float* eh = exsh[w][myh];
        int t = 0;
        for (; t + 8 <= deg; t += 8){
            float4 ea = *(const float4*)&eh[t];
            float4 eb = *(const float4*)&eh[t+4];
            int4   sa = *(const int4*)&srcsh[w][t];
            int4   sb = *(const int4*)&srcsh[w][t+4];
            uint4 p0 = ldh(sa.x, lane), p1 = ldh(sa.y, lane);
            uint4 p2 = ldh(sa.z, lane), p3 = ldh(sa.w, lane);
            uint4 p4 = ldh(sb.x, lane), p5 = ldh(sb.y, lane);
            uint4 p6 = ldh(sb.z, lane), p7 = ldh(sb.w, lane);
            dn += (ea.x + ea.y + ea.z + ea.w) + (eb.x + eb.y + eb.z + eb.w);
            fmah(acc, p0, ea.x); fmah(acc, p1, ea.y);
            fmah(acc, p2, ea.z); fmah(acc, p3, ea.w);
            fmah(acc, p4, eb.x); fmah(acc, p5, eb.y);
            fmah(acc, p6, eb.z); fmah(acc, p7, eb.w);
        }
        for (; t + 4 <= deg; t += 4){
            float4 ea = *(const float4*)&eh[t];
            int4   sa = *(const int4*)&srcsh[w][t];
            uint4 p0 = ldh(sa.x, lane), p1 = ldh(sa.y, lane);
            uint4 p2 = ldh(sa.z, lane), p3 = ldh(sa.w, lane);
            dn += ea.x + ea.y + ea.z + ea.w;
            fmah(acc, p0, ea.x); fmah(acc, p1, ea.y);
            fmah(acc, p2, ea.z); fmah(acc, p3, ea.w);
        }
        for (; t < deg; t++){
            float e = eh[t];
            dn += e;
            fmah(acc, ldh(srcsh[w][t], lane), e);
        }
    } else {
        for (int base = beg; base < end; base += 32){
            int j = base + lane;
            int cnt = min(32, end - base);
            bool v = (j < end);
            int src   = v ? g_csrc[j] : 0;
            float4 e4 = v ? ((const float4*)g_e)[j] : make_float4(0,0,0,0);
            srcsh[w][lane] = src;
            exsh[w][0][lane] = e4.x;
            exsh[w][1][lane] = e4.y;
            exsh[w][2][lane] = e4.z;
            exsh[w][3][lane] = e4.w;
            __syncwarp();
            const float* eh = exsh[w][myh];
            int t = 0;
            for (; t + 8 <= cnt; t += 8){
                float4 ea = *(const float4*)&eh[t];
                float4 eb = *(const float4*)&eh[t+4];
                int4   sa = *(const int4*)&srcsh[w][t];
                int4   sb = *(const int4*)&srcsh[w][t+4];
                uint4 p0 = ldh(sa.x, lane), p1 = ldh(sa.y, lane);
                uint4 p2 = ldh(sa.z, lane), p3 = ldh(sa.w, lane);
                uint4 p4 = ldh(sb.x, lane), p5 = ldh(sb.y, lane);
                uint4 p6 = ldh(sb.z, lane), p7 = ldh(sb.w, lane);
                dn += (ea.x + ea.y + ea.z + ea.w) + (eb.x + eb.y + eb.z + eb.w);
                fmah(acc, p0, ea.x); fmah(acc, p1, ea.y);
                fmah(acc, p2, ea.z); fmah(acc, p3, ea.w);
                fmah(acc, p4, eb.x); fmah(acc, p5, eb.y);
                fmah(acc, p6, eb.z); fmah(acc, p7, eb.w);
            }
            for (; t + 4 <= cnt; t += 4){
                float4 ea = *(const float4*)&eh[t];
                int4   sa = *(const int4*)&srcsh[w][t];
                uint4 p0 = ldh(sa.x, lane), p1 = ldh(sa.y, lane);
                uint4 p2 = ldh(sa.z, lane), p3 = ldh(sa.w, lane);
                dn += ea.x + ea.y + ea.z + ea.w;
                fmah(acc, p0, ea.x); fmah(acc, p1, ea.y);
                fmah(acc, p2, ea.z); fmah(acc, p3, ea.w);
            }
            for (; t < cnt; t++){
                float e = eh[t];
                dn += e;
                fmah(acc, ldh(srcsh[w][t], lane), e);
            }
            __syncwarp();
        }
    }

    float inv = 1.f / dn;
    #pragma unroll
    for (int i = 0; i < 8; i++) acc[i] *= inv;
    #pragma unroll
    for (int i = 0; i < 8; i++){
        acc[i] += __shfl_xor_sync(0xFFFFFFFFu, acc[i], 8);
        acc[i] += __shfl_xor_sync(0xFFFFFFFFu, acc[i], 16);
        acc[i] *= 0.25f;
    }
    int cih = (lane & 7) * 8;
    float4 b0 = *(const float4*)&bg[cih];
    float4 b1 = *(const float4*)&bg[cih+4];
    float v[8];
    v[0]=acc[0]+b0.x; v[1]=acc[1]+b0.y; v[2]=acc[2]+b0.z; v[3]=acc[3]+b0.w;
    v[4]=acc[4]+b1.x; v[5]=acc[5]+b1.y; v[6]=acc[6]+b1.z; v[7]=acc[7]+b1.w;
    float s = 0.f, q = 0.f;
    #pragma unroll
    for (int i = 0; i < 8; i++){ s += v[i]; q += v[i]*v[i]; }
    #pragma unroll
    for (int off = 4; off; off >>= 1){
        s += __shfl_xor_sync(0xFFFFFFFFu, s, off);
        q += __shfl_xor_sync(0xFFFFFFFFu, q, off);
    }
    float mu   = s * (1.f/64.f);
    float var  = q * (1.f/64.f) - mu*mu;
    float rstd = rsqrtf(var + 1e-5f);
    float aw = pa[0];
    if (lane < 8){
        float4 g0 = *(const float4*)&gam[cih],   g1 = *(const float4*)&gam[cih+4];
        float4 t0 = *(const float4*)&bet[cih],   t1 = *(const float4*)&bet[cih+4];
        float* xp = &g_x[(size_t)n*HD + cih];
        float4 x0 = *(const float4*)xp, x1 = *(const float4*)(xp+4);
        float xn;
        xn = (v[0]-mu)*rstd*g0.x + t0.x; x0.x += (xn>0.f? xn : aw*xn);
        xn = (v[1]-mu)*rstd*g0.y + t0.y; x0.y += (xn>0.f? xn : aw*xn);
        xn = (v[2]-mu)*rstd*g0.z + t0.z; x0.z += (xn>0.f? xn : aw*xn);
        xn = (v[3]-mu)*rstd*g0.w + t0.w; x0.w += (xn>0.f? xn : aw*xn);
        xn = (v[4]-mu)*rstd*g1.x + t1.x; x1.x += (xn>0.f? xn : aw*xn);
        xn = (v[5]-mu)*rstd*g1.y + t1.y; x1.y += (xn>0.f? xn : aw*xn);
        xn = (v[6]-mu)*rstd*g1.z + t1.z; x1.z += (xn>0.f? xn : aw*xn);
        xn = (v[7]-mu)*rstd*g1.w + t1.w; x1.w += (xn>0.f? xn : aw*xn);
        *(float4*)xp     = x0;
        *(float4*)(xp+4) = x1;
    }
}

// ---------------- final: z = x @ Wp + bp, L2-normalize rows (f32x2) ----------------
__global__ __launch_bounds__(256) void k_final(const float* __restrict__ Wp,
                                               const float* __restrict__ bp,
                                               float* __restrict__ out){
    __shared__ ull Wp2[32][64];
    __shared__ __align__(16) float xs[8][64];
    int t = threadIdx.x;
    for (int i = t; i < 2048; i += 256){
        int k2 = i >> 6, c = i & 63;
        Wp2[k2][c] = pack2(Wp[(2*k2)*64 + c], Wp[(2*k2+1)*64 + c]);
    }
    int nb = blockIdx.x*8;
    for (int i = t; i < 512; i += 256){
        int r = nb + (i >> 6);
        xs[i>>6][i&63] = (r < Nn) ? g_x[(size_t)r*HD + (i & 63)] : 0.f;
    }
    __syncthreads();
    int w = t >> 5, lane = t & 31;
    int n = nb + w;
    if (n >= Nn) return;
    int c0 = lane, c1 = lane + 32;
    ull z2a = 0, z2b = 0;
    #pragma unroll
    for (int k2 = 0; k2 < 32; k2++){
        ull xv = *(const ull*)&xs[w][2*k2];
        fma2(z2a, xv, Wp2[k2][c0]);
        fma2(z2b, xv, Wp2[k2][c1]);
    }
    float l0, h0, l1, h1;
    unpack2(z2a, l0, h0);
    unpack2(z2b, l1, h1);
    float z0 = l0 + h0 + bp[c0];
    float z1 = l1 + h1 + bp[c1];
    float q = z0*z0 + z1*z1;
    #pragma unroll
    for (int off = 16; off; off >>= 1) q += __shfl_xor_sync(0xFFFFFFFFu, q, off);
    float inv = 1.f / fmaxf(sqrtf(q), 1e-12f);
    out[(size_t)n*HD + c0] = z0*inv;
    out[(size_t)n*HD + c1] = z1*inv;
}

// ---------------- launch ----------------
extern "C" void kernel_launch(void* const* d_in, const int* in_sizes, int n_in,
                              void* d_out, int out_size){
    const float* feat = (const float*)d_in[0];
    const int*   ei   = (const int*)  d_in[1];
    const float* Wt   = (const float*)d_in[2];
    const float* bt   = (const float*)d_in[3];
    const float* Wp   = (const float*)d_in[4];
    const float* bp   = (const float*)d_in[5];

    k_zerodeg<<<(Nn + 255)/256, 256>>>();
    k_lin1cnt<<<L1B + (Et + 255)/256, 256>>>(feat, Wt, bt, ei);
    k_scanA  <<<49, 1024>>>();
    k_scanC  <<<49, 1024>>>();
    k_scatter<<<(Et + 255)/256, 256>>>(ei);

    for (int l = 0; l < 2; l++){
        const float* Wg  = (const float*)d_in[6 + l*7 + 0];
        const float* as_ = (const float*)d_in[6 + l*7 + 1];
        const float* ad_ = (const float*)d_in[6 + l*7 + 2];
        const float* bg  = (const float*)d_in[6 + l*7 + 3];
        const float* gam = (const float*)d_in[6 + l*7 + 4];
        const float* bet = (const float*)d_in[6 + l*7 + 5];
        const float* pa  = (const float*)d_in[6 + l*7 + 6];

        k_gemm_h<<<(Nn + 63)/64, 256>>>(Wg, as_, ad_);
        k_edge  <<<(Et + 255)/256, 256>>>();
        k_gat   <<<(Nn + 7)/8, 256>>>(bg, gam, bet, pa);
    }

    k_final<<<(Nn + 7)/8, 256>>>(Wp, bp, (float*)d_out);
}